// round 9
// baseline (speedup 1.0000x reference)
#include <cuda_runtime.h>
#include <cuda_bf16.h>
#include <math.h>
#include <stdint.h>

#define BB 4
#define SS 2048
#define DD 512
#define HH 8
#define DHH 64
#define FF 2048
#define LL 6
#define NROWS (BB*SS)   // 8192
#define TD (3*DD)       // 1536 packed qkv width

typedef __nv_bfloat16 bf16;

// ---------------------------------------------------------------------------
// Scratch
// ---------------------------------------------------------------------------
__device__ float g_tmp[NROWS * DD];
__device__ bf16 g_xhi[NROWS * DD];
__device__ bf16 g_xlo[NROWS * DD];
__device__ bf16 g_qkvhi[NROWS * TD];
__device__ bf16 g_qkvlo[NROWS * TD];
__device__ bf16 g_thi[NROWS * DD];
__device__ bf16 g_tlo[NROWS * DD];
__device__ bf16 g_hhi[NROWS * FF];
__device__ bf16 g_hlo[NROWS * FF];
__device__ bf16 g_wqkvhi[LL * TD * DD];
__device__ bf16 g_wqkvlo[LL * TD * DD];
__device__ bf16 g_wohi[LL * DD * DD];
__device__ bf16 g_wolo[LL * DD * DD];
__device__ bf16 g_w1hi[LL * FF * DD];
__device__ bf16 g_w1lo[LL * FF * DD];
__device__ bf16 g_w2hi[LL * DD * FF];
__device__ bf16 g_w2lo[LL * DD * FF];
__device__ float g_bqkv[LL * TD];

// ---------------------------------------------------------------------------
// helpers
// ---------------------------------------------------------------------------
__device__ __forceinline__ uint32_t smem_u32(const void* p) {
    uint32_t a;
    asm("{ .reg .u64 t; cvta.to.shared.u64 t, %1; cvt.u32.u64 %0, t; }"
        : "=r"(a) : "l"(p));
    return a;
}

__device__ __forceinline__ void mma16816(float* c, const uint32_t* a, const uint32_t* b) {
    asm volatile(
        "mma.sync.aligned.m16n8k16.row.col.f32.bf16.bf16.f32 "
        "{%0,%1,%2,%3}, {%4,%5,%6,%7}, {%8,%9}, {%0,%1,%2,%3};"
        : "+f"(c[0]), "+f"(c[1]), "+f"(c[2]), "+f"(c[3])
        : "r"(a[0]), "r"(a[1]), "r"(a[2]), "r"(a[3]), "r"(b[0]), "r"(b[1]));
}

__device__ __forceinline__ void ldm_x4t(uint32_t* r, uint32_t addr) {
    asm volatile("ldmatrix.sync.aligned.m8n8.x4.trans.shared.b16 {%0,%1,%2,%3}, [%4];"
                 : "=r"(r[0]), "=r"(r[1]), "=r"(r[2]), "=r"(r[3]) : "r"(addr));
}

__device__ __forceinline__ void cpa16(uint32_t dst, const void* src) {
    asm volatile("cp.async.cg.shared.global [%0], [%1], 16;" :: "r"(dst), "l"(src));
}

__device__ __forceinline__ uint32_t pk2(float x0, float x1) {
    __nv_bfloat162 t = __floats2bfloat162_rn(x0, x1);
    return *(uint32_t*)&t;
}

// ---------------------------------------------------------------------------
// Embedding gather + split
// ---------------------------------------------------------------------------
__global__ __launch_bounds__(128) void embed_kernel(const int* __restrict__ src,
                                                    const float* __restrict__ emb,
                                                    float* __restrict__ x,
                                                    bf16* __restrict__ xhi,
                                                    bf16* __restrict__ xlo) {
    int row = blockIdx.x;
    int tok = src[row];
    float4 v = ((const float4*)(emb + (size_t)tok * DD))[threadIdx.x];
    ((float4*)(x + (size_t)row * DD))[threadIdx.x] = v;
    float h0 = __bfloat162float(__float2bfloat16_rn(v.x));
    float h1 = __bfloat162float(__float2bfloat16_rn(v.y));
    float h2 = __bfloat162float(__float2bfloat16_rn(v.z));
    float h3 = __bfloat162float(__float2bfloat16_rn(v.w));
    uint32_t* H = (uint32_t*)(xhi + (size_t)row * DD);
    uint32_t* L = (uint32_t*)(xlo + (size_t)row * DD);
    H[2 * threadIdx.x]     = pk2(h0, h1);
    H[2 * threadIdx.x + 1] = pk2(h2, h3);
    L[2 * threadIdx.x]     = pk2(v.x - h0, v.y - h1);
    L[2 * threadIdx.x + 1] = pk2(v.z - h2, v.w - h3);
}

// ---------------------------------------------------------------------------
// Batched transpose + split over layers
// ---------------------------------------------------------------------------
__global__ __launch_bounds__(256) void transpose_cvt_kernel(
    const float* __restrict__ W, bf16* __restrict__ WThi, bf16* __restrict__ WTlo,
    int K, int N, size_t src_ls, size_t dst_ls) {
    __shared__ float t[32][33];
    const float* Wl = W + (size_t)blockIdx.z * src_ls;
    bf16* Hl = WThi + (size_t)blockIdx.z * dst_ls;
    bf16* Ll = WTlo + (size_t)blockIdx.z * dst_ls;
    int n0 = blockIdx.x * 32, k0 = blockIdx.y * 32;
    int c = threadIdx.x & 31, r = threadIdx.x >> 5;
#pragma unroll
    for (int i = 0; i < 4; i++)
        t[r + i * 8][c] = Wl[(size_t)(k0 + r + i * 8) * N + n0 + c];
    __syncthreads();
#pragma unroll
    for (int i = 0; i < 4; i++) {
        float x = t[c][r + i * 8];
        bf16 h = __float2bfloat16_rn(x);
        bf16 l = __float2bfloat16_rn(x - __bfloat162float(h));
        size_t o = (size_t)(n0 + r + i * 8) * K + k0 + c;
        Hl[o] = h;
        Ll[o] = l;
    }
}

__global__ __launch_bounds__(256) void pack_bias_kernel(const float* __restrict__ bq,
                                                        const float* __restrict__ bk,
                                                        const float* __restrict__ bv,
                                                        float* __restrict__ dst) {
    int i = blockIdx.x * 256 + threadIdx.x;
    if (i >= LL * TD) return;
    int l = i / TD, r = i % TD;
    int sel = r / DD, c = r % DD;
    const float* s = sel == 0 ? bq : (sel == 1 ? bk : bv);
    dst[i] = s[l * DD + c];
}

// ---------------------------------------------------------------------------
// Warp-MMA bf16x3 GEMM — single-sync double-buffered pipeline.
// Loop: wait_group 0 -> __syncthreads -> issue prefetch(it+1) -> compute(it).
// The sync proves all warps finished compute(it-1) (reads of buf^1), so the
// prefetch may safely overwrite buf^1. Exactly one cp.async group is
// outstanding at each wait.
// ---------------------------------------------------------------------------
#define GP_B   80
#define GTILE_B (128 * GP_B)
#define GSTAGE_B (4 * GTILE_B)
#define GSMEM   (2 * GSTAGE_B)    // 81920

__global__ __launch_bounds__(256, 2) void gemm_wm_kernel(
    const bf16* __restrict__ Ahi, const bf16* __restrict__ Alo,
    const bf16* __restrict__ Bhi, const bf16* __restrict__ Blo,
    const float* __restrict__ bias, float* __restrict__ C,
    bf16* __restrict__ Chi, bf16* __restrict__ Clo,
    int M, int N, int K, int relu, int mode) {
    extern __shared__ char sm[];
    const uint32_t sbase = smem_u32(sm);

    const int tid = threadIdx.x;
    const int lane = tid & 31;
    const int wid = tid >> 5;
    const int warp_m = wid >> 2;
    const int warp_n = wid & 3;
    const int g = lane >> 2;
    const int tig = lane & 3;

    const int bm = blockIdx.y * 128;
    const int bn = blockIdx.x * 128;

    const bf16* srcs[4] = {
        Ahi + (size_t)bm * K, Alo + (size_t)bm * K,
        Bhi + (size_t)bn * K, Blo + (size_t)bn * K };

    float acc[4][4][4];
#pragma unroll
    for (int mt = 0; mt < 4; mt++)
#pragma unroll
        for (int nt = 0; nt < 4; nt++)
#pragma unroll
            for (int e = 0; e < 4; e++) acc[mt][nt][e] = 0.f;

    const int NIT = K >> 5;

    auto load_stage = [&](int s, int it) {
        const uint32_t stage = sbase + (uint32_t)s * GSTAGE_B;
#pragma unroll
        for (int t = 0; t < 4; t++) {
#pragma unroll
            for (int i = 0; i < 2; i++) {
                int idx = i * 256 + tid;
                int r = idx >> 2;
                int c8 = idx & 3;
                const void* src = (const char*)(srcs[t] + (size_t)r * K + it * 32) + c8 * 16;
                uint32_t dst = stage + (uint32_t)t * GTILE_B + (uint32_t)r * GP_B + c8 * 16;
                cpa16(dst, src);
            }
        }
        asm volatile("cp.async.commit_group;" ::: "memory");
    };

    load_stage(0, 0);

    for (int it = 0; it < NIT; it++) {
        const int buf = it & 1;
        asm volatile("cp.async.wait_group 0;" ::: "memory");
        __syncthreads();                         // single barrier per iteration
        if (it + 1 < NIT) load_stage(buf ^ 1, it + 1);

        const char* A0 = sm + buf * GSTAGE_B;
        const char* A1 = A0 + GTILE_B;
        const char* B0 = A0 + 2 * GTILE_B;
        const char* B1 = A0 + 3 * GTILE_B;

#pragma unroll
        for (int ks = 0; ks < 2; ks++) {
            const int kb = ks * 32 + tig * 4;
            uint32_t bh[4][2], bl[4][2];
#pragma unroll
            for (int nt = 0; nt < 4; nt++) {
                int off = (warp_n * 32 + nt * 8 + g) * GP_B + kb;
                bh[nt][0] = *(const uint32_t*)(B0 + off);
                bh[nt][1] = *(const uint32_t*)(B0 + off + 16);
                bl[nt][0] = *(const uint32_t*)(B1 + off);
                bl[nt][1] = *(const uint32_t*)(B1 + off + 16);
            }
#pragma unroll
            for (int mt = 0; mt < 4; mt++) {
                uint32_t ah[4], al[4];
                int off = (warp_m * 64 + mt * 16 + g) * GP_B + kb;
                ah[0] = *(const uint32_t*)(A0 + off);
                ah[1] = *(const uint32_t*)(A0 + off + 8 * GP_B);
                ah[2] = *(const uint32_t*)(A0 + off + 16);
                ah[3] = *(const uint32_t*)(A0 + off + 8 * GP_B + 16);
                al[0] = *(const uint32_t*)(A1 + off);
                al[1] = *(const uint32_t*)(A1 + off + 8 * GP_B);
                al[2] = *(const uint32_t*)(A1 + off + 16);
                al[3] = *(const uint32_t*)(A1 + off + 8 * GP_B + 16);
#pragma unroll
                for (int nt = 0; nt < 4; nt++) {
                    mma16816(acc[mt][nt], ah, bh[nt]);
                    mma16816(acc[mt][nt], ah, bl[nt]);
                    mma16816(acc[mt][nt], al, bh[nt]);
                }
            }
        }
    }

#pragma unroll
    for (int mt = 0; mt < 4; mt++) {
        int row0 = bm + warp_m * 64 + mt * 16 + g;
#pragma unroll
        for (int nt = 0; nt < 4; nt++) {
            int col = bn + warp_n * 32 + nt * 8 + 2 * tig;
            float bx = bias[col], by = bias[col + 1];
            float v00 = acc[mt][nt][0] + bx, v01 = acc[mt][nt][1] + by;
            float v10 = acc[mt][nt][2] + bx, v11 = acc[mt][nt][3] + by;
            if (relu) {
                v00 = fmaxf(v00, 0.f); v01 = fmaxf(v01, 0.f);
                v10 = fmaxf(v10, 0.f); v11 = fmaxf(v11, 0.f);
            }
            if (mode == 0) {
                *(float2*)&C[(size_t)row0 * N + col] = make_float2(v00, v01);
                *(float2*)&C[(size_t)(row0 + 8) * N + col] = make_float2(v10, v11);
            } else {
                float h00 = __bfloat162float(__float2bfloat16_rn(v00));
                float h01 = __bfloat162float(__float2bfloat16_rn(v01));
                float h10 = __bfloat162float(__float2bfloat16_rn(v10));
                float h11 = __bfloat162float(__float2bfloat16_rn(v11));
                *(uint32_t*)&Chi[(size_t)row0 * N + col] = pk2(h00, h01);
                *(uint32_t*)&Chi[(size_t)(row0 + 8) * N + col] = pk2(h10, h11);
                *(uint32_t*)&Clo[(size_t)row0 * N + col] = pk2(v00 - h00, v01 - h01);
                *(uint32_t*)&Clo[(size_t)(row0 + 8) * N + col] = pk2(v10 - h10, v11 - h11);
            }
        }
    }
}

// ---------------------------------------------------------------------------
// Tensor-core flash attention (R8-proven: row-major V + ldmatrix.trans,
// 73,728B smem, 2 CTA/SM, longest-tiles-first). Unchanged.
// ---------------------------------------------------------------------------
#define AP 72
#define ATT_SMEM ((2*128 + 4*64) * AP * 2)   // 73728 bytes

__global__ __launch_bounds__(256, 2) void attn_tc_kernel(
    const bf16* __restrict__ qkvhi, const bf16* __restrict__ qkvlo,
    bf16* __restrict__ thi, bf16* __restrict__ tlo) {
    extern __shared__ bf16 asmem[];
    const uint32_t sb = smem_u32(asmem);
    bf16* Qh = asmem;
    bf16* Ql = Qh + 128 * AP;
    bf16* Kh = Ql + 128 * AP;
    bf16* Kl = Kh + 64 * AP;
    bf16* Vh = Kl + 64 * AP;
    bf16* Vl = Vh + 64 * AP;
    const uint32_t vhb = sb + (uint32_t)(384 * AP) * 2;
    const uint32_t vlb = sb + (uint32_t)(448 * AP) * 2;

    const int tid = threadIdx.x;
    const int lane = tid & 31;
    const int wid = tid >> 5;
    const int g = lane >> 2;
    const int tig = lane & 3;

    const int qb = gridDim.x - 1 - blockIdx.x;
    const int bh = blockIdx.y;
    const int b = bh / HH;
    const int h = bh % HH;
    const int q0 = qb * 128;
    const size_t hoff = (size_t)h * DHH;

#pragma unroll
    for (int i = 0; i < 4; i++) {
        int idx = i * 256 + tid;
        int row = idx >> 3;
        int cb = (idx & 7) * 8;
        size_t go = (size_t)(b * SS + q0 + row) * TD + hoff + cb;
        *(uint4*)&Qh[row * AP + cb] = *(const uint4*)&qkvhi[go];
        *(uint4*)&Ql[row * AP + cb] = *(const uint4*)&qkvlo[go];
    }

    float oacc[8][4];
#pragma unroll
    for (int vn = 0; vn < 8; vn++)
#pragma unroll
        for (int e = 0; e < 4; e++) oacc[vn][e] = 0.f;
    float mrow[2] = {-1e30f, -1e30f};
    float lrow[2] = {0.f, 0.f};

    const int nkt = 2 * qb + 2;
    const int wr0 = q0 + wid * 16;
    const float scale = 0.125f;

    const int l7 = lane & 7;
    const int grp = lane >> 3;
    const uint32_t vrow_off = (uint32_t)((l7 + (grp & 1) * 8) * AP) * 2;
    const uint32_t vcol_off = (uint32_t)((grp >> 1) * 8) * 2;

    for (int kt = 0; kt < nkt; kt++) {
        const int k0 = kt * 64;
        __syncthreads();
#pragma unroll
        for (int i = 0; i < 2; i++) {
            int idx = i * 256 + tid;
            int row = idx >> 3;
            int cb = (idx & 7) * 8;
            size_t go = (size_t)(b * SS + k0 + row) * TD + hoff + cb;
            *(uint4*)&Kh[row * AP + cb] = *(const uint4*)&qkvhi[go + DD];
            *(uint4*)&Kl[row * AP + cb] = *(const uint4*)&qkvlo[go + DD];
            *(uint4*)&Vh[row * AP + cb] = *(const uint4*)&qkvhi[go + 2 * DD];
            *(uint4*)&Vl[row * AP + cb] = *(const uint4*)&qkvlo[go + 2 * DD];
        }
        __syncthreads();

        if (k0 <= wr0 + 15) {
            float sacc[8][4];
#pragma unroll
            for (int nt = 0; nt < 8; nt++)
#pragma unroll
                for (int e = 0; e < 4; e++) sacc[nt][e] = 0.f;

#pragma unroll
            for (int kc = 0; kc < 4; kc++) {
                uint32_t ah[4], al[4];
                int aoff = (wid * 16 + g) * AP + kc * 16 + 2 * tig;
                ah[0] = *(const uint32_t*)&Qh[aoff];
                ah[1] = *(const uint32_t*)&Qh[aoff + 8 * AP];
                ah[2] = *(const uint32_t*)&Qh[aoff + 8];
                ah[3] = *(const uint32_t*)&Qh[aoff + 8 * AP + 8];
                al[0] = *(const uint32_t*)&Ql[aoff];
                al[1] = *(const uint32_t*)&Ql[aoff + 8 * AP];
                al[2] = *(const uint32_t*)&Ql[aoff + 8];
                al[3] = *(const uint32_t*)&Ql[aoff + 8 * AP + 8];
#pragma unroll
                for (int nt = 0; nt < 8; nt++) {
                    int boff = (nt * 8 + g) * AP + kc * 16 + 2 * tig;
                    uint32_t bh2[2], bl2[2];
                    bh2[0] = *(const uint32_t*)&Kh[boff];
                    bh2[1] = *(const uint32_t*)&Kh[boff + 8];
                    bl2[0] = *(const uint32_t*)&Kl[boff];
                    bl2[1] = *(const uint32_t*)&Kl[boff + 8];
                    mma16816(sacc[nt], ah, bh2);
                    mma16816(sacc[nt], ah, bl2);
                    mma16816(sacc[nt], al, bh2);
                }
            }

            const bool needmask = (k0 + 63) > wr0;
#pragma unroll
            for (int nt = 0; nt < 8; nt++)
#pragma unroll
                for (int e = 0; e < 4; e++) {
                    float sv = sacc[nt][e] * scale;
                    if (needmask) {
                        int row = wr0 + g + ((e >> 1) << 3);
                        int col = k0 + nt * 8 + 2 * tig + (e & 1);
                        if (col > row) sv = -1e30f;
                    }
                    sacc[nt][e] = sv;
                }

#pragma unroll
            for (int rr = 0; rr < 2; rr++) {
                float mx = -1e30f;
#pragma unroll
                for (int nt = 0; nt < 8; nt++)
                    mx = fmaxf(mx, fmaxf(sacc[nt][2 * rr], sacc[nt][2 * rr + 1]));
                mx = fmaxf(mx, __shfl_xor_sync(0xffffffffu, mx, 1));
                mx = fmaxf(mx, __shfl_xor_sync(0xffffffffu, mx, 2));
                float mnew = fmaxf(mrow[rr], mx);
                float alpha = __expf(mrow[rr] - mnew);
                float rs = 0.f;
#pragma unroll
                for (int nt = 0; nt < 8; nt++) {
                    float p0 = __expf(sacc[nt][2 * rr] - mnew);
                    float p1 = __expf(sacc[nt][2 * rr + 1] - mnew);
                    sacc[nt][2 * rr] = p0;
                    sacc[nt][2 * rr + 1] = p1;
                    rs += p0 + p1;
                }
                rs += __shfl_xor_sync(0xffffffffu, rs, 1);
                rs += __shfl_xor_sync(0xffffffffu, rs, 2);
                lrow[rr] = lrow[rr] * alpha + rs;
                mrow[rr] = mnew;
#pragma unroll
                for (int vn = 0; vn < 8; vn++) {
                    oacc[vn][2 * rr] *= alpha;
                    oacc[vn][2 * rr + 1] *= alpha;
                }
            }

#pragma unroll
            for (int kc2 = 0; kc2 < 4; kc2++) {
                float* t0 = sacc[2 * kc2];
                float* t1 = sacc[2 * kc2 + 1];
                float h00 = __bfloat162float(__float2bfloat16_rn(t0[0]));
                float h01 = __bfloat162float(__float2bfloat16_rn(t0[1]));
                float h02 = __bfloat162float(__float2bfloat16_rn(t0[2]));
                float h03 = __bfloat162float(__float2bfloat16_rn(t0[3]));
                float h10 = __bfloat162float(__float2bfloat16_rn(t1[0]));
                float h11 = __bfloat162float(__float2bfloat16_rn(t1[1]));
                float h12 = __bfloat162float(__float2bfloat16_rn(t1[2]));
                float h13 = __bfloat162float(__float2bfloat16_rn(t1[3]));
                uint32_t ph[4], pl[4];
                ph[0] = pk2(h00, h01); ph[1] = pk2(h02, h03);
                ph[2] = pk2(h10, h11); ph[3] = pk2(h12, h13);
                pl[0] = pk2(t0[0] - h00, t0[1] - h01);
                pl[1] = pk2(t0[2] - h02, t0[3] - h03);
                pl[2] = pk2(t1[0] - h10, t1[1] - h11);
                pl[3] = pk2(t1[2] - h12, t1[3] - h13);

                const uint32_t kbase = (uint32_t)(kc2 * 16 * AP) * 2 + vrow_off + vcol_off;
#pragma unroll
                for (int vnp = 0; vnp < 4; vnp++) {
                    uint32_t vaddr = kbase + (uint32_t)(vnp * 16) * 2;
                    uint32_t vh4[4], vl4[4];
                    ldm_x4t(vh4, vhb + vaddr);
                    ldm_x4t(vl4, vlb + vaddr);
                    uint32_t bh0[2] = {vh4[0], vh4[1]}, bh1[2] = {vh4[2], vh4[3]};
                    uint32_t bl0[2] = {vl4[0], vl4[1]}, bl1[2] = {vl4[2], vl4[3]};
                    mma16816(oacc[2 * vnp], ph, bh0);
                    mma16816(oacc[2 * vnp], pl, bh0);
                    mma16816(oacc[2 * vnp], ph, bl0);
                    mma16816(oacc[2 * vnp + 1], ph, bh1);
                    mma16816(oacc[2 * vnp + 1], pl, bh1);
                    mma16816(oacc[2 * vnp + 1], ph, bl1);
                }
            }
        }
    }

#pragma unroll
    for (int rr = 0; rr < 2; rr++) {
        float inv = 1.f / lrow[rr];
        int r = wr0 + g + rr * 8;
        size_t rb = (size_t)(b * SS + r) * DD + hoff;
#pragma unroll
        for (int vn = 0; vn < 8; vn++) {
            float o0 = oacc[vn][2 * rr] * inv;
            float o1 = oacc[vn][2 * rr + 1] * inv;
            float h0 = __bfloat162float(__float2bfloat16_rn(o0));
            float h1 = __bfloat162float(__float2bfloat16_rn(o1));
            int col = vn * 8 + 2 * tig;
            *(uint32_t*)&thi[rb + col] = pk2(h0, h1);
            *(uint32_t*)&tlo[rb + col] = pk2(o0 - h0, o1 - h1);
        }
    }
}

// ---------------------------------------------------------------------------
// Residual add + LayerNorm + split
// ---------------------------------------------------------------------------
__global__ __launch_bounds__(256) void add_ln_kernel(float* __restrict__ x,
                                                     const float* __restrict__ y,
                                                     const float* __restrict__ g,
                                                     const float* __restrict__ bb,
                                                     bf16* __restrict__ xhi,
                                                     bf16* __restrict__ xlo) {
    const int row = blockIdx.x;
    const int tid = threadIdx.x;
    float2 xv = *(const float2*)&x[(size_t)row * DD + tid * 2];
    float2 yv = *(const float2*)&y[(size_t)row * DD + tid * 2];
    float a0 = xv.x + yv.x;
    float a1 = xv.y + yv.y;

    float s = a0 + a1;
    float ss = a0 * a0 + a1 * a1;
#pragma unroll
    for (int off = 16; off >= 1; off >>= 1) {
        s += __shfl_xor_sync(0xffffffffu, s, off);
        ss += __shfl_xor_sync(0xffffffffu, ss, off);
    }
    __shared__ float sbuf[8], ssbuf[8];
    if ((tid & 31) == 0) { sbuf[tid >> 5] = s; ssbuf[tid >> 5] = ss; }
    __syncthreads();
    float ts = 0.f, tss = 0.f;
#pragma unroll
    for (int i = 0; i < 8; i++) { ts += sbuf[i]; tss += ssbuf[i]; }
    float mean = ts * (1.f / DD);
    float var = tss * (1.f / DD) - mean * mean;
    float rstd = rsqrtf(var + 1e-5f);

    int col = tid * 2;
    float2 go = *(const float2*)&g[col];
    float2 bo = *(const float2*)&bb[col];
    float o0 = (a0 - mean) * rstd * go.x + bo.x;
    float o1 = (a1 - mean) * rstd * go.y + bo.y;
    *(float2*)&x[(size_t)row * DD + col] = make_float2(o0, o1);
    float h0 = __bfloat162float(__float2bfloat16_rn(o0));
    float h1 = __bfloat162float(__float2bfloat16_rn(o1));
    *(uint32_t*)&xhi[(size_t)row * DD + col] = pk2(h0, h1);
    *(uint32_t*)&xlo[(size_t)row * DD + col] = pk2(o0 - h0, o1 - h1);
}

// ---------------------------------------------------------------------------
// Host driver
// ---------------------------------------------------------------------------
extern "C" void kernel_launch(void* const* d_in, const int* in_sizes, int n_in,
                              void* d_out, int out_size) {
    const int* source = (const int*)d_in[0];
    const float* emb = (const float*)d_in[1];
    const float* ln_g = (const float*)d_in[2];
    const float* ln_b = (const float*)d_in[3];
    const float* wq = (const float*)d_in[4];
    const float* bq = (const float*)d_in[5];
    const float* wk = (const float*)d_in[6];
    const float* bk = (const float*)d_in[7];
    const float* wv = (const float*)d_in[8];
    const float* bv = (const float*)d_in[9];
    const float* wo = (const float*)d_in[10];
    const float* bo = (const float*)d_in[11];
    const float* w1 = (const float*)d_in[12];
    const float* b1 = (const float*)d_in[13];
    const float* w2 = (const float*)d_in[14];
    const float* b2 = (const float*)d_in[15];

    float* x = (float*)d_out;

    float *tmp, *bqkv;
    bf16 *xhi, *xlo, *qkvhi, *qkvlo, *thi, *tlo, *hhi, *hlo;
    bf16 *wqkvhi, *wqkvlo, *wohi, *wolo, *w1hi, *w1lo, *w2hi, *w2lo;
    cudaGetSymbolAddress((void**)&tmp, g_tmp);
    cudaGetSymbolAddress((void**)&bqkv, g_bqkv);
    cudaGetSymbolAddress((void**)&xhi, g_xhi);
    cudaGetSymbolAddress((void**)&xlo, g_xlo);
    cudaGetSymbolAddress((void**)&qkvhi, g_qkvhi);
    cudaGetSymbolAddress((void**)&qkvlo, g_qkvlo);
    cudaGetSymbolAddress((void**)&thi, g_thi);
    cudaGetSymbolAddress((void**)&tlo, g_tlo);
    cudaGetSymbolAddress((void**)&hhi, g_hhi);
    cudaGetSymbolAddress((void**)&hlo, g_hlo);
    cudaGetSymbolAddress((void**)&wqkvhi, g_wqkvhi);
    cudaGetSymbolAddress((void**)&wqkvlo, g_wqkvlo);
    cudaGetSymbolAddress((void**)&wohi, g_wohi);
    cudaGetSymbolAddress((void**)&wolo, g_wolo);
    cudaGetSymbolAddress((void**)&w1hi, g_w1hi);
    cudaGetSymbolAddress((void**)&w1lo, g_w1lo);
    cudaGetSymbolAddress((void**)&w2hi, g_w2hi);
    cudaGetSymbolAddress((void**)&w2lo, g_w2lo);

    cudaFuncSetAttribute(attn_tc_kernel, cudaFuncAttributeMaxDynamicSharedMemorySize,
                         ATT_SMEM);
    cudaFuncSetAttribute(gemm_wm_kernel, cudaFuncAttributeMaxDynamicSharedMemorySize,
                         GSMEM);

    embed_kernel<<<NROWS, 128>>>(source, emb, x, xhi, xlo);
    {
        dim3 gD(DD / 32, DD / 32, LL);
        transpose_cvt_kernel<<<gD, 256>>>(wq, wqkvhi, wqkvlo, DD, DD,
                                          (size_t)DD * DD, (size_t)TD * DD);
        transpose_cvt_kernel<<<gD, 256>>>(wk, wqkvhi + (size_t)DD * DD,
                                          wqkvlo + (size_t)DD * DD, DD, DD,
                                          (size_t)DD * DD, (size_t)TD * DD);
        transpose_cvt_kernel<<<gD, 256>>>(wv, wqkvhi + (size_t)2 * DD * DD,
                                          wqkvlo + (size_t)2 * DD * DD, DD, DD,
                                          (size_t)DD * DD, (size_t)TD * DD);
        transpose_cvt_kernel<<<gD, 256>>>(wo, wohi, wolo, DD, DD,
                                          (size_t)DD * DD, (size_t)DD * DD);
        dim3 g1(FF / 32, DD / 32, LL);
        transpose_cvt_kernel<<<g1, 256>>>(w1, w1hi, w1lo, DD, FF,
                                          (size_t)DD * FF, (size_t)FF * DD);
        dim3 g2(DD / 32, FF / 32, LL);
        transpose_cvt_kernel<<<g2, 256>>>(w2, w2hi, w2lo, FF, DD,
                                          (size_t)FF * DD, (size_t)DD * FF);
        pack_bias_kernel<<<(LL * TD + 255) / 256, 256>>>(bq, bk, bv, bqkv);
    }

    dim3 gA(SS / 128, BB * HH);

    auto gemm = [&](const bf16* ah, const bf16* al, const bf16* bh, const bf16* bl,
                    const float* bias, float* C, bf16* Ch, bf16* Cl,
                    int M, int N, int K, int relu, int mode) {
        dim3 g(N / 128, M / 128);
        gemm_wm_kernel<<<g, 256, GSMEM>>>(ah, al, bh, bl, bias, C, Ch, Cl,
                                          M, N, K, relu, mode);
    };

    for (int l = 0; l < LL; l++) {
        const bf16* Wqkvh = wqkvhi + (size_t)l * TD * DD;
        const bf16* Wqkvl = wqkvlo + (size_t)l * TD * DD;
        const bf16* Woh = wohi + (size_t)l * DD * DD;
        const bf16* Wol = wolo + (size_t)l * DD * DD;
        const bf16* W1h = w1hi + (size_t)l * FF * DD;
        const bf16* W1l = w1lo + (size_t)l * FF * DD;
        const bf16* W2h = w2hi + (size_t)l * DD * FF;
        const bf16* W2l = w2lo + (size_t)l * DD * FF;
        const float* Bqkv = bqkv + (size_t)l * TD;
        const float* Bo = bo + (size_t)l * DD;
        const float* B1 = b1 + (size_t)l * FF;
        const float* B2 = b2 + (size_t)l * DD;

        gemm(xhi, xlo, Wqkvh, Wqkvl, Bqkv, nullptr, qkvhi, qkvlo,
             NROWS, TD, DD, 0, 1);

        attn_tc_kernel<<<gA, 256, ATT_SMEM>>>(qkvhi, qkvlo, thi, tlo);

        gemm(thi, tlo, Woh, Wol, Bo, tmp, nullptr, nullptr, NROWS, DD, DD, 0, 0);
        add_ln_kernel<<<NROWS, 256>>>(x, tmp, ln_g, ln_b, xhi, xlo);

        gemm(xhi, xlo, W1h, W1l, B1, nullptr, hhi, hlo, NROWS, FF, DD, 1, 1);
        gemm(hhi, hlo, W2h, W2l, B2, tmp, nullptr, nullptr, NROWS, DD, FF, 1, 0);
        add_ln_kernel<<<NROWS, 256>>>(x, tmp, ln_g, ln_b, xhi, xlo);
    }
}

// round 10
// speedup vs baseline: 1.0003x; 1.0003x over previous
#include <cuda_runtime.h>
#include <cuda_bf16.h>
#include <math.h>
#include <stdint.h>

#define BB 4
#define SS 2048
#define DD 512
#define HH 8
#define DHH 64
#define FF 2048
#define LL 6
#define NROWS (BB*SS)   // 8192
#define TD (3*DD)       // 1536 packed qkv width

typedef __nv_bfloat16 bf16;

// ---------------------------------------------------------------------------
// Scratch
// ---------------------------------------------------------------------------
__device__ float g_tmp[NROWS * DD];
__device__ bf16 g_xhi[NROWS * DD];
__device__ bf16 g_xlo[NROWS * DD];
__device__ bf16 g_qkvhi[NROWS * TD];
__device__ bf16 g_qkvlo[NROWS * TD];
__device__ bf16 g_thi[NROWS * DD];
__device__ bf16 g_tlo[NROWS * DD];
__device__ bf16 g_hhi[NROWS * FF];
__device__ bf16 g_hlo[NROWS * FF];
__device__ bf16 g_wqkvhi[LL * TD * DD];
__device__ bf16 g_wqkvlo[LL * TD * DD];
__device__ bf16 g_wohi[LL * DD * DD];
__device__ bf16 g_wolo[LL * DD * DD];
__device__ bf16 g_w1hi[LL * FF * DD];
__device__ bf16 g_w1lo[LL * FF * DD];
__device__ bf16 g_w2hi[LL * DD * FF];
__device__ bf16 g_w2lo[LL * DD * FF];
__device__ float g_bqkv[LL * TD];

// ---------------------------------------------------------------------------
// helpers
// ---------------------------------------------------------------------------
__device__ __forceinline__ uint32_t smem_u32(const void* p) {
    uint32_t a;
    asm("{ .reg .u64 t; cvta.to.shared.u64 t, %1; cvt.u32.u64 %0, t; }"
        : "=r"(a) : "l"(p));
    return a;
}

__device__ __forceinline__ void mma16816(float* c, const uint32_t* a, const uint32_t* b) {
    asm volatile(
        "mma.sync.aligned.m16n8k16.row.col.f32.bf16.bf16.f32 "
        "{%0,%1,%2,%3}, {%4,%5,%6,%7}, {%8,%9}, {%0,%1,%2,%3};"
        : "+f"(c[0]), "+f"(c[1]), "+f"(c[2]), "+f"(c[3])
        : "r"(a[0]), "r"(a[1]), "r"(a[2]), "r"(a[3]), "r"(b[0]), "r"(b[1]));
}

__device__ __forceinline__ void ldm_x4t(uint32_t* r, uint32_t addr) {
    asm volatile("ldmatrix.sync.aligned.m8n8.x4.trans.shared.b16 {%0,%1,%2,%3}, [%4];"
                 : "=r"(r[0]), "=r"(r[1]), "=r"(r[2]), "=r"(r[3]) : "r"(addr));
}

__device__ __forceinline__ void cpa16(uint32_t dst, const void* src) {
    asm volatile("cp.async.cg.shared.global [%0], [%1], 16;" :: "r"(dst), "l"(src));
}

__device__ __forceinline__ uint32_t pk2(float x0, float x1) {
    __nv_bfloat162 t = __floats2bfloat162_rn(x0, x1);
    return *(uint32_t*)&t;
}

// ---------------------------------------------------------------------------
// Embedding gather + split
// ---------------------------------------------------------------------------
__global__ __launch_bounds__(128) void embed_kernel(const int* __restrict__ src,
                                                    const float* __restrict__ emb,
                                                    float* __restrict__ x,
                                                    bf16* __restrict__ xhi,
                                                    bf16* __restrict__ xlo) {
    int row = blockIdx.x;
    int tok = src[row];
    float4 v = ((const float4*)(emb + (size_t)tok * DD))[threadIdx.x];
    ((float4*)(x + (size_t)row * DD))[threadIdx.x] = v;
    float h0 = __bfloat162float(__float2bfloat16_rn(v.x));
    float h1 = __bfloat162float(__float2bfloat16_rn(v.y));
    float h2 = __bfloat162float(__float2bfloat16_rn(v.z));
    float h3 = __bfloat162float(__float2bfloat16_rn(v.w));
    uint32_t* H = (uint32_t*)(xhi + (size_t)row * DD);
    uint32_t* L = (uint32_t*)(xlo + (size_t)row * DD);
    H[2 * threadIdx.x]     = pk2(h0, h1);
    H[2 * threadIdx.x + 1] = pk2(h2, h3);
    L[2 * threadIdx.x]     = pk2(v.x - h0, v.y - h1);
    L[2 * threadIdx.x + 1] = pk2(v.z - h2, v.w - h3);
}

// ---------------------------------------------------------------------------
// Batched transpose + split over layers
// ---------------------------------------------------------------------------
__global__ __launch_bounds__(256) void transpose_cvt_kernel(
    const float* __restrict__ W, bf16* __restrict__ WThi, bf16* __restrict__ WTlo,
    int K, int N, size_t src_ls, size_t dst_ls) {
    __shared__ float t[32][33];
    const float* Wl = W + (size_t)blockIdx.z * src_ls;
    bf16* Hl = WThi + (size_t)blockIdx.z * dst_ls;
    bf16* Ll = WTlo + (size_t)blockIdx.z * dst_ls;
    int n0 = blockIdx.x * 32, k0 = blockIdx.y * 32;
    int c = threadIdx.x & 31, r = threadIdx.x >> 5;
#pragma unroll
    for (int i = 0; i < 4; i++)
        t[r + i * 8][c] = Wl[(size_t)(k0 + r + i * 8) * N + n0 + c];
    __syncthreads();
#pragma unroll
    for (int i = 0; i < 4; i++) {
        float x = t[c][r + i * 8];
        bf16 h = __float2bfloat16_rn(x);
        bf16 l = __float2bfloat16_rn(x - __bfloat162float(h));
        size_t o = (size_t)(n0 + r + i * 8) * K + k0 + c;
        Hl[o] = h;
        Ll[o] = l;
    }
}

__global__ __launch_bounds__(256) void pack_bias_kernel(const float* __restrict__ bq,
                                                        const float* __restrict__ bk,
                                                        const float* __restrict__ bv,
                                                        float* __restrict__ dst) {
    int i = blockIdx.x * 256 + threadIdx.x;
    if (i >= LL * TD) return;
    int l = i / TD, r = i % TD;
    int sel = r / DD, c = r % DD;
    const float* s = sel == 0 ? bq : (sel == 1 ? bk : bv);
    dst[i] = s[l * DD + c];
}

// ---------------------------------------------------------------------------
// Warp-MMA bf16x3 GEMM — R8-proven two-sync double-buffered pipeline.
// ---------------------------------------------------------------------------
#define GP_B   80
#define GTILE_B (128 * GP_B)
#define GSTAGE_B (4 * GTILE_B)
#define GSMEM   (2 * GSTAGE_B)    // 81920

__global__ __launch_bounds__(256, 2) void gemm_wm_kernel(
    const bf16* __restrict__ Ahi, const bf16* __restrict__ Alo,
    const bf16* __restrict__ Bhi, const bf16* __restrict__ Blo,
    const float* __restrict__ bias, float* __restrict__ C,
    bf16* __restrict__ Chi, bf16* __restrict__ Clo,
    int M, int N, int K, int relu, int mode) {
    extern __shared__ char sm[];
    const uint32_t sbase = smem_u32(sm);

    const int tid = threadIdx.x;
    const int lane = tid & 31;
    const int wid = tid >> 5;
    const int warp_m = wid >> 2;
    const int warp_n = wid & 3;
    const int g = lane >> 2;
    const int tig = lane & 3;

    const int bm = blockIdx.y * 128;
    const int bn = blockIdx.x * 128;

    const bf16* srcs[4] = {
        Ahi + (size_t)bm * K, Alo + (size_t)bm * K,
        Bhi + (size_t)bn * K, Blo + (size_t)bn * K };

    float acc[4][4][4];
#pragma unroll
    for (int mt = 0; mt < 4; mt++)
#pragma unroll
        for (int nt = 0; nt < 4; nt++)
#pragma unroll
            for (int e = 0; e < 4; e++) acc[mt][nt][e] = 0.f;

    const int NIT = K >> 5;

    auto load_stage = [&](int s, int it) {
        const uint32_t stage = sbase + (uint32_t)s * GSTAGE_B;
#pragma unroll
        for (int t = 0; t < 4; t++) {
#pragma unroll
            for (int i = 0; i < 2; i++) {
                int idx = i * 256 + tid;
                int r = idx >> 2;
                int c8 = idx & 3;
                const void* src = (const char*)(srcs[t] + (size_t)r * K + it * 32) + c8 * 16;
                uint32_t dst = stage + (uint32_t)t * GTILE_B + (uint32_t)r * GP_B + c8 * 16;
                cpa16(dst, src);
            }
        }
        asm volatile("cp.async.commit_group;" ::: "memory");
    };

    load_stage(0, 0);

    for (int it = 0; it < NIT; it++) {
        const int buf = it & 1;
        if (it + 1 < NIT) {
            load_stage(buf ^ 1, it + 1);
            asm volatile("cp.async.wait_group 1;" ::: "memory");
        } else {
            asm volatile("cp.async.wait_group 0;" ::: "memory");
        }
        __syncthreads();

        const char* A0 = sm + buf * GSTAGE_B;
        const char* A1 = A0 + GTILE_B;
        const char* B0 = A0 + 2 * GTILE_B;
        const char* B1 = A0 + 3 * GTILE_B;

#pragma unroll
        for (int ks = 0; ks < 2; ks++) {
            const int kb = ks * 32 + tig * 4;
            uint32_t bh[4][2], bl[4][2];
#pragma unroll
            for (int nt = 0; nt < 4; nt++) {
                int off = (warp_n * 32 + nt * 8 + g) * GP_B + kb;
                bh[nt][0] = *(const uint32_t*)(B0 + off);
                bh[nt][1] = *(const uint32_t*)(B0 + off + 16);
                bl[nt][0] = *(const uint32_t*)(B1 + off);
                bl[nt][1] = *(const uint32_t*)(B1 + off + 16);
            }
#pragma unroll
            for (int mt = 0; mt < 4; mt++) {
                uint32_t ah[4], al[4];
                int off = (warp_m * 64 + mt * 16 + g) * GP_B + kb;
                ah[0] = *(const uint32_t*)(A0 + off);
                ah[1] = *(const uint32_t*)(A0 + off + 8 * GP_B);
                ah[2] = *(const uint32_t*)(A0 + off + 16);
                ah[3] = *(const uint32_t*)(A0 + off + 8 * GP_B + 16);
                al[0] = *(const uint32_t*)(A1 + off);
                al[1] = *(const uint32_t*)(A1 + off + 8 * GP_B);
                al[2] = *(const uint32_t*)(A1 + off + 16);
                al[3] = *(const uint32_t*)(A1 + off + 8 * GP_B + 16);
#pragma unroll
                for (int nt = 0; nt < 4; nt++) {
                    mma16816(acc[mt][nt], ah, bh[nt]);
                    mma16816(acc[mt][nt], ah, bl[nt]);
                    mma16816(acc[mt][nt], al, bh[nt]);
                }
            }
        }
        __syncthreads();
    }

#pragma unroll
    for (int mt = 0; mt < 4; mt++) {
        int row0 = bm + warp_m * 64 + mt * 16 + g;
#pragma unroll
        for (int nt = 0; nt < 4; nt++) {
            int col = bn + warp_n * 32 + nt * 8 + 2 * tig;
            float bx = bias[col], by = bias[col + 1];
            float v00 = acc[mt][nt][0] + bx, v01 = acc[mt][nt][1] + by;
            float v10 = acc[mt][nt][2] + bx, v11 = acc[mt][nt][3] + by;
            if (relu) {
                v00 = fmaxf(v00, 0.f); v01 = fmaxf(v01, 0.f);
                v10 = fmaxf(v10, 0.f); v11 = fmaxf(v11, 0.f);
            }
            if (mode == 0) {
                *(float2*)&C[(size_t)row0 * N + col] = make_float2(v00, v01);
                *(float2*)&C[(size_t)(row0 + 8) * N + col] = make_float2(v10, v11);
            } else {
                float h00 = __bfloat162float(__float2bfloat16_rn(v00));
                float h01 = __bfloat162float(__float2bfloat16_rn(v01));
                float h10 = __bfloat162float(__float2bfloat16_rn(v10));
                float h11 = __bfloat162float(__float2bfloat16_rn(v11));
                *(uint32_t*)&Chi[(size_t)row0 * N + col] = pk2(h00, h01);
                *(uint32_t*)&Chi[(size_t)(row0 + 8) * N + col] = pk2(h10, h11);
                *(uint32_t*)&Clo[(size_t)row0 * N + col] = pk2(v00 - h00, v01 - h01);
                *(uint32_t*)&Clo[(size_t)(row0 + 8) * N + col] = pk2(v10 - h10, v11 - h11);
            }
        }
    }
}

// ---------------------------------------------------------------------------
// Tensor-core flash attention (R8 structure) + diagonal n-tile skip:
// an 8-col block starting at k0+8*nt is entirely above the causal diagonal
// for this warp iff k0+8*nt > wr0+15 (warp-uniform). Skipped blocks keep
// sacc=0, which the mask loop overwrites to -1e30 -> bit-identical output.
// ---------------------------------------------------------------------------
#define AP 72
#define ATT_SMEM ((2*128 + 4*64) * AP * 2)   // 73728 bytes

__global__ __launch_bounds__(256, 2) void attn_tc_kernel(
    const bf16* __restrict__ qkvhi, const bf16* __restrict__ qkvlo,
    bf16* __restrict__ thi, bf16* __restrict__ tlo) {
    extern __shared__ bf16 asmem[];
    const uint32_t sb = smem_u32(asmem);
    bf16* Qh = asmem;
    bf16* Ql = Qh + 128 * AP;
    bf16* Kh = Ql + 128 * AP;
    bf16* Kl = Kh + 64 * AP;
    bf16* Vh = Kl + 64 * AP;
    bf16* Vl = Vh + 64 * AP;
    const uint32_t vhb = sb + (uint32_t)(384 * AP) * 2;
    const uint32_t vlb = sb + (uint32_t)(448 * AP) * 2;

    const int tid = threadIdx.x;
    const int lane = tid & 31;
    const int wid = tid >> 5;
    const int g = lane >> 2;
    const int tig = lane & 3;

    const int qb = gridDim.x - 1 - blockIdx.x;
    const int bh = blockIdx.y;
    const int b = bh / HH;
    const int h = bh % HH;
    const int q0 = qb * 128;
    const size_t hoff = (size_t)h * DHH;

#pragma unroll
    for (int i = 0; i < 4; i++) {
        int idx = i * 256 + tid;
        int row = idx >> 3;
        int cb = (idx & 7) * 8;
        size_t go = (size_t)(b * SS + q0 + row) * TD + hoff + cb;
        *(uint4*)&Qh[row * AP + cb] = *(const uint4*)&qkvhi[go];
        *(uint4*)&Ql[row * AP + cb] = *(const uint4*)&qkvlo[go];
    }

    float oacc[8][4];
#pragma unroll
    for (int vn = 0; vn < 8; vn++)
#pragma unroll
        for (int e = 0; e < 4; e++) oacc[vn][e] = 0.f;
    float mrow[2] = {-1e30f, -1e30f};
    float lrow[2] = {0.f, 0.f};

    const int nkt = 2 * qb + 2;
    const int wr0 = q0 + wid * 16;
    const float scale = 0.125f;

    const int l7 = lane & 7;
    const int grp = lane >> 3;
    const uint32_t vrow_off = (uint32_t)((l7 + (grp & 1) * 8) * AP) * 2;
    const uint32_t vcol_off = (uint32_t)((grp >> 1) * 8) * 2;

    for (int kt = 0; kt < nkt; kt++) {
        const int k0 = kt * 64;
        __syncthreads();
#pragma unroll
        for (int i = 0; i < 2; i++) {
            int idx = i * 256 + tid;
            int row = idx >> 3;
            int cb = (idx & 7) * 8;
            size_t go = (size_t)(b * SS + k0 + row) * TD + hoff + cb;
            *(uint4*)&Kh[row * AP + cb] = *(const uint4*)&qkvhi[go + DD];
            *(uint4*)&Kl[row * AP + cb] = *(const uint4*)&qkvlo[go + DD];
            *(uint4*)&Vh[row * AP + cb] = *(const uint4*)&qkvhi[go + 2 * DD];
            *(uint4*)&Vl[row * AP + cb] = *(const uint4*)&qkvlo[go + 2 * DD];
        }
        __syncthreads();

        if (k0 <= wr0 + 15) {
            float sacc[8][4];
#pragma unroll
            for (int nt = 0; nt < 8; nt++)
#pragma unroll
                for (int e = 0; e < 4; e++) sacc[nt][e] = 0.f;

#pragma unroll
            for (int kc = 0; kc < 4; kc++) {
                uint32_t ah[4], al[4];
                int aoff = (wid * 16 + g) * AP + kc * 16 + 2 * tig;
                ah[0] = *(const uint32_t*)&Qh[aoff];
                ah[1] = *(const uint32_t*)&Qh[aoff + 8 * AP];
                ah[2] = *(const uint32_t*)&Qh[aoff + 8];
                ah[3] = *(const uint32_t*)&Qh[aoff + 8 * AP + 8];
                al[0] = *(const uint32_t*)&Ql[aoff];
                al[1] = *(const uint32_t*)&Ql[aoff + 8 * AP];
                al[2] = *(const uint32_t*)&Ql[aoff + 8];
                al[3] = *(const uint32_t*)&Ql[aoff + 8 * AP + 8];
#pragma unroll
                for (int nt = 0; nt < 8; nt++) {
                    if (k0 + nt * 8 > wr0 + 15) continue;   // fully-masked block
                    int boff = (nt * 8 + g) * AP + kc * 16 + 2 * tig;
                    uint32_t bh2[2], bl2[2];
                    bh2[0] = *(const uint32_t*)&Kh[boff];
                    bh2[1] = *(const uint32_t*)&Kh[boff + 8];
                    bl2[0] = *(const uint32_t*)&Kl[boff];
                    bl2[1] = *(const uint32_t*)&Kl[boff + 8];
                    mma16816(sacc[nt], ah, bh2);
                    mma16816(sacc[nt], ah, bl2);
                    mma16816(sacc[nt], al, bh2);
                }
            }

            const bool needmask = (k0 + 63) > wr0;
#pragma unroll
            for (int nt = 0; nt < 8; nt++)
#pragma unroll
                for (int e = 0; e < 4; e++) {
                    float sv = sacc[nt][e] * scale;
                    if (needmask) {
                        int row = wr0 + g + ((e >> 1) << 3);
                        int col = k0 + nt * 8 + 2 * tig + (e & 1);
                        if (col > row) sv = -1e30f;
                    }
                    sacc[nt][e] = sv;
                }

#pragma unroll
            for (int rr = 0; rr < 2; rr++) {
                float mx = -1e30f;
#pragma unroll
                for (int nt = 0; nt < 8; nt++)
                    mx = fmaxf(mx, fmaxf(sacc[nt][2 * rr], sacc[nt][2 * rr + 1]));
                mx = fmaxf(mx, __shfl_xor_sync(0xffffffffu, mx, 1));
                mx = fmaxf(mx, __shfl_xor_sync(0xffffffffu, mx, 2));
                float mnew = fmaxf(mrow[rr], mx);
                float alpha = __expf(mrow[rr] - mnew);
                float rs = 0.f;
#pragma unroll
                for (int nt = 0; nt < 8; nt++) {
                    float p0 = __expf(sacc[nt][2 * rr] - mnew);
                    float p1 = __expf(sacc[nt][2 * rr + 1] - mnew);
                    sacc[nt][2 * rr] = p0;
                    sacc[nt][2 * rr + 1] = p1;
                    rs += p0 + p1;
                }
                rs += __shfl_xor_sync(0xffffffffu, rs, 1);
                rs += __shfl_xor_sync(0xffffffffu, rs, 2);
                lrow[rr] = lrow[rr] * alpha + rs;
                mrow[rr] = mnew;
#pragma unroll
                for (int vn = 0; vn < 8; vn++) {
                    oacc[vn][2 * rr] *= alpha;
                    oacc[vn][2 * rr + 1] *= alpha;
                }
            }

#pragma unroll
            for (int kc2 = 0; kc2 < 4; kc2++) {
                float* t0 = sacc[2 * kc2];
                float* t1 = sacc[2 * kc2 + 1];
                float h00 = __bfloat162float(__float2bfloat16_rn(t0[0]));
                float h01 = __bfloat162float(__float2bfloat16_rn(t0[1]));
                float h02 = __bfloat162float(__float2bfloat16_rn(t0[2]));
                float h03 = __bfloat162float(__float2bfloat16_rn(t0[3]));
                float h10 = __bfloat162float(__float2bfloat16_rn(t1[0]));
                float h11 = __bfloat162float(__float2bfloat16_rn(t1[1]));
                float h12 = __bfloat162float(__float2bfloat16_rn(t1[2]));
                float h13 = __bfloat162float(__float2bfloat16_rn(t1[3]));
                uint32_t ph[4], pl[4];
                ph[0] = pk2(h00, h01); ph[1] = pk2(h02, h03);
                ph[2] = pk2(h10, h11); ph[3] = pk2(h12, h13);
                pl[0] = pk2(t0[0] - h00, t0[1] - h01);
                pl[1] = pk2(t0[2] - h02, t0[3] - h03);
                pl[2] = pk2(t1[0] - h10, t1[1] - h11);
                pl[3] = pk2(t1[2] - h12, t1[3] - h13);

                const uint32_t kbase = (uint32_t)(kc2 * 16 * AP) * 2 + vrow_off + vcol_off;
#pragma unroll
                for (int vnp = 0; vnp < 4; vnp++) {
                    uint32_t vaddr = kbase + (uint32_t)(vnp * 16) * 2;
                    uint32_t vh4[4], vl4[4];
                    ldm_x4t(vh4, vhb + vaddr);
                    ldm_x4t(vl4, vlb + vaddr);
                    uint32_t bh0[2] = {vh4[0], vh4[1]}, bh1[2] = {vh4[2], vh4[3]};
                    uint32_t bl0[2] = {vl4[0], vl4[1]}, bl1[2] = {vl4[2], vl4[3]};
                    mma16816(oacc[2 * vnp], ph, bh0);
                    mma16816(oacc[2 * vnp], pl, bh0);
                    mma16816(oacc[2 * vnp], ph, bl0);
                    mma16816(oacc[2 * vnp + 1], ph, bh1);
                    mma16816(oacc[2 * vnp + 1], pl, bh1);
                    mma16816(oacc[2 * vnp + 1], ph, bl1);
                }
            }
        }
    }

#pragma unroll
    for (int rr = 0; rr < 2; rr++) {
        float inv = 1.f / lrow[rr];
        int r = wr0 + g + rr * 8;
        size_t rb = (size_t)(b * SS + r) * DD + hoff;
#pragma unroll
        for (int vn = 0; vn < 8; vn++) {
            float o0 = oacc[vn][2 * rr] * inv;
            float o1 = oacc[vn][2 * rr + 1] * inv;
            float h0 = __bfloat162float(__float2bfloat16_rn(o0));
            float h1 = __bfloat162float(__float2bfloat16_rn(o1));
            int col = vn * 8 + 2 * tig;
            *(uint32_t*)&thi[rb + col] = pk2(h0, h1);
            *(uint32_t*)&tlo[rb + col] = pk2(o0 - h0, o1 - h1);
        }
    }
}

// ---------------------------------------------------------------------------
// Residual add + LayerNorm + split
// ---------------------------------------------------------------------------
__global__ __launch_bounds__(256) void add_ln_kernel(float* __restrict__ x,
                                                     const float* __restrict__ y,
                                                     const float* __restrict__ g,
                                                     const float* __restrict__ bb,
                                                     bf16* __restrict__ xhi,
                                                     bf16* __restrict__ xlo) {
    const int row = blockIdx.x;
    const int tid = threadIdx.x;
    float2 xv = *(const float2*)&x[(size_t)row * DD + tid * 2];
    float2 yv = *(const float2*)&y[(size_t)row * DD + tid * 2];
    float a0 = xv.x + yv.x;
    float a1 = xv.y + yv.y;

    float s = a0 + a1;
    float ss = a0 * a0 + a1 * a1;
#pragma unroll
    for (int off = 16; off >= 1; off >>= 1) {
        s += __shfl_xor_sync(0xffffffffu, s, off);
        ss += __shfl_xor_sync(0xffffffffu, ss, off);
    }
    __shared__ float sbuf[8], ssbuf[8];
    if ((tid & 31) == 0) { sbuf[tid >> 5] = s; ssbuf[tid >> 5] = ss; }
    __syncthreads();
    float ts = 0.f, tss = 0.f;
#pragma unroll
    for (int i = 0; i < 8; i++) { ts += sbuf[i]; tss += ssbuf[i]; }
    float mean = ts * (1.f / DD);
    float var = tss * (1.f / DD) - mean * mean;
    float rstd = rsqrtf(var + 1e-5f);

    int col = tid * 2;
    float2 go = *(const float2*)&g[col];
    float2 bo = *(const float2*)&bb[col];
    float o0 = (a0 - mean) * rstd * go.x + bo.x;
    float o1 = (a1 - mean) * rstd * go.y + bo.y;
    *(float2*)&x[(size_t)row * DD + col] = make_float2(o0, o1);
    float h0 = __bfloat162float(__float2bfloat16_rn(o0));
    float h1 = __bfloat162float(__float2bfloat16_rn(o1));
    *(uint32_t*)&xhi[(size_t)row * DD + col] = pk2(h0, h1);
    *(uint32_t*)&xlo[(size_t)row * DD + col] = pk2(o0 - h0, o1 - h1);
}

// ---------------------------------------------------------------------------
// Host driver
// ---------------------------------------------------------------------------
extern "C" void kernel_launch(void* const* d_in, const int* in_sizes, int n_in,
                              void* d_out, int out_size) {
    const int* source = (const int*)d_in[0];
    const float* emb = (const float*)d_in[1];
    const float* ln_g = (const float*)d_in[2];
    const float* ln_b = (const float*)d_in[3];
    const float* wq = (const float*)d_in[4];
    const float* bq = (const float*)d_in[5];
    const float* wk = (const float*)d_in[6];
    const float* bk = (const float*)d_in[7];
    const float* wv = (const float*)d_in[8];
    const float* bv = (const float*)d_in[9];
    const float* wo = (const float*)d_in[10];
    const float* bo = (const float*)d_in[11];
    const float* w1 = (const float*)d_in[12];
    const float* b1 = (const float*)d_in[13];
    const float* w2 = (const float*)d_in[14];
    const float* b2 = (const float*)d_in[15];

    float* x = (float*)d_out;

    float *tmp, *bqkv;
    bf16 *xhi, *xlo, *qkvhi, *qkvlo, *thi, *tlo, *hhi, *hlo;
    bf16 *wqkvhi, *wqkvlo, *wohi, *wolo, *w1hi, *w1lo, *w2hi, *w2lo;
    cudaGetSymbolAddress((void**)&tmp, g_tmp);
    cudaGetSymbolAddress((void**)&bqkv, g_bqkv);
    cudaGetSymbolAddress((void**)&xhi, g_xhi);
    cudaGetSymbolAddress((void**)&xlo, g_xlo);
    cudaGetSymbolAddress((void**)&qkvhi, g_qkvhi);
    cudaGetSymbolAddress((void**)&qkvlo, g_qkvlo);
    cudaGetSymbolAddress((void**)&thi, g_thi);
    cudaGetSymbolAddress((void**)&tlo, g_tlo);
    cudaGetSymbolAddress((void**)&hhi, g_hhi);
    cudaGetSymbolAddress((void**)&hlo, g_hlo);
    cudaGetSymbolAddress((void**)&wqkvhi, g_wqkvhi);
    cudaGetSymbolAddress((void**)&wqkvlo, g_wqkvlo);
    cudaGetSymbolAddress((void**)&wohi, g_wohi);
    cudaGetSymbolAddress((void**)&wolo, g_wolo);
    cudaGetSymbolAddress((void**)&w1hi, g_w1hi);
    cudaGetSymbolAddress((void**)&w1lo, g_w1lo);
    cudaGetSymbolAddress((void**)&w2hi, g_w2hi);
    cudaGetSymbolAddress((void**)&w2lo, g_w2lo);

    cudaFuncSetAttribute(attn_tc_kernel, cudaFuncAttributeMaxDynamicSharedMemorySize,
                         ATT_SMEM);
    cudaFuncSetAttribute(gemm_wm_kernel, cudaFuncAttributeMaxDynamicSharedMemorySize,
                         GSMEM);

    embed_kernel<<<NROWS, 128>>>(source, emb, x, xhi, xlo);
    {
        dim3 gD(DD / 32, DD / 32, LL);
        transpose_cvt_kernel<<<gD, 256>>>(wq, wqkvhi, wqkvlo, DD, DD,
                                          (size_t)DD * DD, (size_t)TD * DD);
        transpose_cvt_kernel<<<gD, 256>>>(wk, wqkvhi + (size_t)DD * DD,
                                          wqkvlo + (size_t)DD * DD, DD, DD,
                                          (size_t)DD * DD, (size_t)TD * DD);
        transpose_cvt_kernel<<<gD, 256>>>(wv, wqkvhi + (size_t)2 * DD * DD,
                                          wqkvlo + (size_t)2 * DD * DD, DD, DD,
                                          (size_t)DD * DD, (size_t)TD * DD);
        transpose_cvt_kernel<<<gD, 256>>>(wo, wohi, wolo, DD, DD,
                                          (size_t)DD * DD, (size_t)DD * DD);
        dim3 g1(FF / 32, DD / 32, LL);
        transpose_cvt_kernel<<<g1, 256>>>(w1, w1hi, w1lo, DD, FF,
                                          (size_t)DD * FF, (size_t)FF * DD);
        dim3 g2(DD / 32, FF / 32, LL);
        transpose_cvt_kernel<<<g2, 256>>>(w2, w2hi, w2lo, FF, DD,
                                          (size_t)FF * DD, (size_t)DD * FF);
        pack_bias_kernel<<<(LL * TD + 255) / 256, 256>>>(bq, bk, bv, bqkv);
    }

    dim3 gA(SS / 128, BB * HH);

    auto gemm = [&](const bf16* ah, const bf16* al, const bf16* bh, const bf16* bl,
                    const float* bias, float* C, bf16* Ch, bf16* Cl,
                    int M, int N, int K, int relu, int mode) {
        dim3 g(N / 128, M / 128);
        gemm_wm_kernel<<<g, 256, GSMEM>>>(ah, al, bh, bl, bias, C, Ch, Cl,
                                          M, N, K, relu, mode);
    };

    for (int l = 0; l < LL; l++) {
        const bf16* Wqkvh = wqkvhi + (size_t)l * TD * DD;
        const bf16* Wqkvl = wqkvlo + (size_t)l * TD * DD;
        const bf16* Woh = wohi + (size_t)l * DD * DD;
        const bf16* Wol = wolo + (size_t)l * DD * DD;
        const bf16* W1h = w1hi + (size_t)l * FF * DD;
        const bf16* W1l = w1lo + (size_t)l * FF * DD;
        const bf16* W2h = w2hi + (size_t)l * DD * FF;
        const bf16* W2l = w2lo + (size_t)l * DD * FF;
        const float* Bqkv = bqkv + (size_t)l * TD;
        const float* Bo = bo + (size_t)l * DD;
        const float* B1 = b1 + (size_t)l * FF;
        const float* B2 = b2 + (size_t)l * DD;

        gemm(xhi, xlo, Wqkvh, Wqkvl, Bqkv, nullptr, qkvhi, qkvlo,
             NROWS, TD, DD, 0, 1);

        attn_tc_kernel<<<gA, 256, ATT_SMEM>>>(qkvhi, qkvlo, thi, tlo);

        gemm(thi, tlo, Woh, Wol, Bo, tmp, nullptr, nullptr, NROWS, DD, DD, 0, 0);
        add_ln_kernel<<<NROWS, 256>>>(x, tmp, ln_g, ln_b, xhi, xlo);

        gemm(xhi, xlo, W1h, W1l, B1, nullptr, hhi, hlo, NROWS, FF, DD, 1, 1);
        gemm(hhi, hlo, W2h, W2l, B2, tmp, nullptr, nullptr, NROWS, DD, FF, 1, 0);
        add_ln_kernel<<<NROWS, 256>>>(x, tmp, ln_g, ln_b, xhi, xlo);
    }
}

// round 11
// speedup vs baseline: 1.1148x; 1.1145x over previous
#include <cuda_runtime.h>
#include <cuda_bf16.h>
#include <math.h>
#include <stdint.h>

#define BB 4
#define SS 2048
#define DD 512
#define HH 8
#define DHH 64
#define FF 2048
#define LL 6
#define NROWS (BB*SS)   // 8192
#define TD (3*DD)       // 1536 packed qkv width

typedef __nv_bfloat16 bf16;

// ---------------------------------------------------------------------------
// Scratch
// ---------------------------------------------------------------------------
__device__ float g_tmp[NROWS * DD];
__device__ bf16 g_xhi[NROWS * DD];
__device__ bf16 g_xlo[NROWS * DD];
__device__ bf16 g_qkvhi[NROWS * TD];
__device__ bf16 g_qkvlo[NROWS * TD];
__device__ bf16 g_thi[NROWS * DD];
__device__ bf16 g_tlo[NROWS * DD];
__device__ bf16 g_hhi[NROWS * FF];
__device__ bf16 g_hlo[NROWS * FF];
__device__ bf16 g_wqkvhi[LL * TD * DD];
__device__ bf16 g_wqkvlo[LL * TD * DD];
__device__ bf16 g_wohi[LL * DD * DD];
__device__ bf16 g_wolo[LL * DD * DD];
__device__ bf16 g_w1hi[LL * FF * DD];
__device__ bf16 g_w1lo[LL * FF * DD];
__device__ bf16 g_w2hi[LL * DD * FF];
__device__ bf16 g_w2lo[LL * DD * FF];
__device__ float g_bqkv[LL * TD];

// ---------------------------------------------------------------------------
// helpers
// ---------------------------------------------------------------------------
__device__ __forceinline__ uint32_t smem_u32(const void* p) {
    uint32_t a;
    asm("{ .reg .u64 t; cvta.to.shared.u64 t, %1; cvt.u32.u64 %0, t; }"
        : "=r"(a) : "l"(p));
    return a;
}

__device__ __forceinline__ void mma16816(float* c, const uint32_t* a, const uint32_t* b) {
    asm volatile(
        "mma.sync.aligned.m16n8k16.row.col.f32.bf16.bf16.f32 "
        "{%0,%1,%2,%3}, {%4,%5,%6,%7}, {%8,%9}, {%0,%1,%2,%3};"
        : "+f"(c[0]), "+f"(c[1]), "+f"(c[2]), "+f"(c[3])
        : "r"(a[0]), "r"(a[1]), "r"(a[2]), "r"(a[3]), "r"(b[0]), "r"(b[1]));
}

__device__ __forceinline__ void ldm_x4t(uint32_t* r, uint32_t addr) {
    asm volatile("ldmatrix.sync.aligned.m8n8.x4.trans.shared.b16 {%0,%1,%2,%3}, [%4];"
                 : "=r"(r[0]), "=r"(r[1]), "=r"(r[2]), "=r"(r[3]) : "r"(addr));
}

__device__ __forceinline__ void cpa16(uint32_t dst, const void* src) {
    asm volatile("cp.async.cg.shared.global [%0], [%1], 16;" :: "r"(dst), "l"(src));
}

__device__ __forceinline__ uint32_t pk2(float x0, float x1) {
    __nv_bfloat162 t = __floats2bfloat162_rn(x0, x1);
    return *(uint32_t*)&t;
}

// ---------------------------------------------------------------------------
// Embedding gather + split
// ---------------------------------------------------------------------------
__global__ __launch_bounds__(128) void embed_kernel(const int* __restrict__ src,
                                                    const float* __restrict__ emb,
                                                    float* __restrict__ x,
                                                    bf16* __restrict__ xhi,
                                                    bf16* __restrict__ xlo) {
    int row = blockIdx.x;
    int tok = src[row];
    float4 v = ((const float4*)(emb + (size_t)tok * DD))[threadIdx.x];
    ((float4*)(x + (size_t)row * DD))[threadIdx.x] = v;
    float h0 = __bfloat162float(__float2bfloat16_rn(v.x));
    float h1 = __bfloat162float(__float2bfloat16_rn(v.y));
    float h2 = __bfloat162float(__float2bfloat16_rn(v.z));
    float h3 = __bfloat162float(__float2bfloat16_rn(v.w));
    uint32_t* H = (uint32_t*)(xhi + (size_t)row * DD);
    uint32_t* L = (uint32_t*)(xlo + (size_t)row * DD);
    H[2 * threadIdx.x]     = pk2(h0, h1);
    H[2 * threadIdx.x + 1] = pk2(h2, h3);
    L[2 * threadIdx.x]     = pk2(v.x - h0, v.y - h1);
    L[2 * threadIdx.x + 1] = pk2(v.z - h2, v.w - h3);
}

// ---------------------------------------------------------------------------
// Batched transpose + split over layers
// ---------------------------------------------------------------------------
__global__ __launch_bounds__(256) void transpose_cvt_kernel(
    const float* __restrict__ W, bf16* __restrict__ WThi, bf16* __restrict__ WTlo,
    int K, int N, size_t src_ls, size_t dst_ls) {
    __shared__ float t[32][33];
    const float* Wl = W + (size_t)blockIdx.z * src_ls;
    bf16* Hl = WThi + (size_t)blockIdx.z * dst_ls;
    bf16* Ll = WTlo + (size_t)blockIdx.z * dst_ls;
    int n0 = blockIdx.x * 32, k0 = blockIdx.y * 32;
    int c = threadIdx.x & 31, r = threadIdx.x >> 5;
#pragma unroll
    for (int i = 0; i < 4; i++)
        t[r + i * 8][c] = Wl[(size_t)(k0 + r + i * 8) * N + n0 + c];
    __syncthreads();
#pragma unroll
    for (int i = 0; i < 4; i++) {
        float x = t[c][r + i * 8];
        bf16 h = __float2bfloat16_rn(x);
        bf16 l = __float2bfloat16_rn(x - __bfloat162float(h));
        size_t o = (size_t)(n0 + r + i * 8) * K + k0 + c;
        Hl[o] = h;
        Ll[o] = l;
    }
}

__global__ __launch_bounds__(256) void pack_bias_kernel(const float* __restrict__ bq,
                                                        const float* __restrict__ bk,
                                                        const float* __restrict__ bv,
                                                        float* __restrict__ dst) {
    int i = blockIdx.x * 256 + threadIdx.x;
    if (i >= LL * TD) return;
    int l = i / TD, r = i % TD;
    int sel = r / DD, c = r % DD;
    const float* s = sel == 0 ? bq : (sel == 1 ? bk : bv);
    dst[i] = s[l * DD + c];
}

// ---------------------------------------------------------------------------
// Warp-MMA bf16x3 GEMM — R8-proven two-sync double-buffered pipeline.
// ---------------------------------------------------------------------------
#define GP_B   80
#define GTILE_B (128 * GP_B)
#define GSTAGE_B (4 * GTILE_B)
#define GSMEM   (2 * GSTAGE_B)    // 81920

__global__ __launch_bounds__(256, 2) void gemm_wm_kernel(
    const bf16* __restrict__ Ahi, const bf16* __restrict__ Alo,
    const bf16* __restrict__ Bhi, const bf16* __restrict__ Blo,
    const float* __restrict__ bias, float* __restrict__ C,
    bf16* __restrict__ Chi, bf16* __restrict__ Clo,
    int M, int N, int K, int relu, int mode) {
    extern __shared__ char sm[];
    const uint32_t sbase = smem_u32(sm);

    const int tid = threadIdx.x;
    const int lane = tid & 31;
    const int wid = tid >> 5;
    const int warp_m = wid >> 2;
    const int warp_n = wid & 3;
    const int g = lane >> 2;
    const int tig = lane & 3;

    const int bm = blockIdx.y * 128;
    const int bn = blockIdx.x * 128;

    const bf16* srcs[4] = {
        Ahi + (size_t)bm * K, Alo + (size_t)bm * K,
        Bhi + (size_t)bn * K, Blo + (size_t)bn * K };

    float acc[4][4][4];
#pragma unroll
    for (int mt = 0; mt < 4; mt++)
#pragma unroll
        for (int nt = 0; nt < 4; nt++)
#pragma unroll
            for (int e = 0; e < 4; e++) acc[mt][nt][e] = 0.f;

    const int NIT = K >> 5;

    auto load_stage = [&](int s, int it) {
        const uint32_t stage = sbase + (uint32_t)s * GSTAGE_B;
#pragma unroll
        for (int t = 0; t < 4; t++) {
#pragma unroll
            for (int i = 0; i < 2; i++) {
                int idx = i * 256 + tid;
                int r = idx >> 2;
                int c8 = idx & 3;
                const void* src = (const char*)(srcs[t] + (size_t)r * K + it * 32) + c8 * 16;
                uint32_t dst = stage + (uint32_t)t * GTILE_B + (uint32_t)r * GP_B + c8 * 16;
                cpa16(dst, src);
            }
        }
        asm volatile("cp.async.commit_group;" ::: "memory");
    };

    load_stage(0, 0);

    for (int it = 0; it < NIT; it++) {
        const int buf = it & 1;
        if (it + 1 < NIT) {
            load_stage(buf ^ 1, it + 1);
            asm volatile("cp.async.wait_group 1;" ::: "memory");
        } else {
            asm volatile("cp.async.wait_group 0;" ::: "memory");
        }
        __syncthreads();

        const char* A0 = sm + buf * GSTAGE_B;
        const char* A1 = A0 + GTILE_B;
        const char* B0 = A0 + 2 * GTILE_B;
        const char* B1 = A0 + 3 * GTILE_B;

#pragma unroll
        for (int ks = 0; ks < 2; ks++) {
            const int kb = ks * 32 + tig * 4;
            uint32_t bh[4][2], bl[4][2];
#pragma unroll
            for (int nt = 0; nt < 4; nt++) {
                int off = (warp_n * 32 + nt * 8 + g) * GP_B + kb;
                bh[nt][0] = *(const uint32_t*)(B0 + off);
                bh[nt][1] = *(const uint32_t*)(B0 + off + 16);
                bl[nt][0] = *(const uint32_t*)(B1 + off);
                bl[nt][1] = *(const uint32_t*)(B1 + off + 16);
            }
#pragma unroll
            for (int mt = 0; mt < 4; mt++) {
                uint32_t ah[4], al[4];
                int off = (warp_m * 64 + mt * 16 + g) * GP_B + kb;
                ah[0] = *(const uint32_t*)(A0 + off);
                ah[1] = *(const uint32_t*)(A0 + off + 8 * GP_B);
                ah[2] = *(const uint32_t*)(A0 + off + 16);
                ah[3] = *(const uint32_t*)(A0 + off + 8 * GP_B + 16);
                al[0] = *(const uint32_t*)(A1 + off);
                al[1] = *(const uint32_t*)(A1 + off + 8 * GP_B);
                al[2] = *(const uint32_t*)(A1 + off + 16);
                al[3] = *(const uint32_t*)(A1 + off + 8 * GP_B + 16);
#pragma unroll
                for (int nt = 0; nt < 4; nt++) {
                    mma16816(acc[mt][nt], ah, bh[nt]);
                    mma16816(acc[mt][nt], ah, bl[nt]);
                    mma16816(acc[mt][nt], al, bh[nt]);
                }
            }
        }
        __syncthreads();
    }

#pragma unroll
    for (int mt = 0; mt < 4; mt++) {
        int row0 = bm + warp_m * 64 + mt * 16 + g;
#pragma unroll
        for (int nt = 0; nt < 4; nt++) {
            int col = bn + warp_n * 32 + nt * 8 + 2 * tig;
            float bx = bias[col], by = bias[col + 1];
            float v00 = acc[mt][nt][0] + bx, v01 = acc[mt][nt][1] + by;
            float v10 = acc[mt][nt][2] + bx, v11 = acc[mt][nt][3] + by;
            if (relu) {
                v00 = fmaxf(v00, 0.f); v01 = fmaxf(v01, 0.f);
                v10 = fmaxf(v10, 0.f); v11 = fmaxf(v11, 0.f);
            }
            if (mode == 0) {
                *(float2*)&C[(size_t)row0 * N + col] = make_float2(v00, v01);
                *(float2*)&C[(size_t)(row0 + 8) * N + col] = make_float2(v10, v11);
            } else {
                float h00 = __bfloat162float(__float2bfloat16_rn(v00));
                float h01 = __bfloat162float(__float2bfloat16_rn(v01));
                float h10 = __bfloat162float(__float2bfloat16_rn(v10));
                float h11 = __bfloat162float(__float2bfloat16_rn(v11));
                *(uint32_t*)&Chi[(size_t)row0 * N + col] = pk2(h00, h01);
                *(uint32_t*)&Chi[(size_t)(row0 + 8) * N + col] = pk2(h10, h11);
                *(uint32_t*)&Clo[(size_t)row0 * N + col] = pk2(v00 - h00, v01 - h01);
                *(uint32_t*)&Clo[(size_t)(row0 + 8) * N + col] = pk2(v10 - h10, v11 - h11);
            }
        }
    }
}

// ---------------------------------------------------------------------------
// Tensor-core flash attention — exact R8 compute; grid swapped to
// (bh, qtile) so ALL longest tiles (qb=15 across every bh) launch first
// (global longest-first packing instead of per-bh-stripe ordering).
// ---------------------------------------------------------------------------
#define AP 72
#define ATT_SMEM ((2*128 + 4*64) * AP * 2)   // 73728 bytes

__global__ __launch_bounds__(256, 2) void attn_tc_kernel(
    const bf16* __restrict__ qkvhi, const bf16* __restrict__ qkvlo,
    bf16* __restrict__ thi, bf16* __restrict__ tlo) {
    extern __shared__ bf16 asmem[];
    const uint32_t sb = smem_u32(asmem);
    bf16* Qh = asmem;
    bf16* Ql = Qh + 128 * AP;
    bf16* Kh = Ql + 128 * AP;
    bf16* Kl = Kh + 64 * AP;
    bf16* Vh = Kl + 64 * AP;
    bf16* Vl = Vh + 64 * AP;
    const uint32_t vhb = sb + (uint32_t)(384 * AP) * 2;
    const uint32_t vlb = sb + (uint32_t)(448 * AP) * 2;

    const int tid = threadIdx.x;
    const int lane = tid & 31;
    const int wid = tid >> 5;
    const int g = lane >> 2;
    const int tig = lane & 3;

    const int qb = gridDim.y - 1 - blockIdx.y;   // global longest-first
    const int bh = blockIdx.x;
    const int b = bh / HH;
    const int h = bh % HH;
    const int q0 = qb * 128;
    const size_t hoff = (size_t)h * DHH;

#pragma unroll
    for (int i = 0; i < 4; i++) {
        int idx = i * 256 + tid;
        int row = idx >> 3;
        int cb = (idx & 7) * 8;
        size_t go = (size_t)(b * SS + q0 + row) * TD + hoff + cb;
        *(uint4*)&Qh[row * AP + cb] = *(const uint4*)&qkvhi[go];
        *(uint4*)&Ql[row * AP + cb] = *(const uint4*)&qkvlo[go];
    }

    float oacc[8][4];
#pragma unroll
    for (int vn = 0; vn < 8; vn++)
#pragma unroll
        for (int e = 0; e < 4; e++) oacc[vn][e] = 0.f;
    float mrow[2] = {-1e30f, -1e30f};
    float lrow[2] = {0.f, 0.f};

    const int nkt = 2 * qb + 2;
    const int wr0 = q0 + wid * 16;
    const float scale = 0.125f;

    const int l7 = lane & 7;
    const int grp = lane >> 3;
    const uint32_t vrow_off = (uint32_t)((l7 + (grp & 1) * 8) * AP) * 2;
    const uint32_t vcol_off = (uint32_t)((grp >> 1) * 8) * 2;

    for (int kt = 0; kt < nkt; kt++) {
        const int k0 = kt * 64;
        __syncthreads();
#pragma unroll
        for (int i = 0; i < 2; i++) {
            int idx = i * 256 + tid;
            int row = idx >> 3;
            int cb = (idx & 7) * 8;
            size_t go = (size_t)(b * SS + k0 + row) * TD + hoff + cb;
            *(uint4*)&Kh[row * AP + cb] = *(const uint4*)&qkvhi[go + DD];
            *(uint4*)&Kl[row * AP + cb] = *(const uint4*)&qkvlo[go + DD];
            *(uint4*)&Vh[row * AP + cb] = *(const uint4*)&qkvhi[go + 2 * DD];
            *(uint4*)&Vl[row * AP + cb] = *(const uint4*)&qkvlo[go + 2 * DD];
        }
        __syncthreads();

        if (k0 <= wr0 + 15) {
            float sacc[8][4];
#pragma unroll
            for (int nt = 0; nt < 8; nt++)
#pragma unroll
                for (int e = 0; e < 4; e++) sacc[nt][e] = 0.f;

#pragma unroll
            for (int kc = 0; kc < 4; kc++) {
                uint32_t ah[4], al[4];
                int aoff = (wid * 16 + g) * AP + kc * 16 + 2 * tig;
                ah[0] = *(const uint32_t*)&Qh[aoff];
                ah[1] = *(const uint32_t*)&Qh[aoff + 8 * AP];
                ah[2] = *(const uint32_t*)&Qh[aoff + 8];
                ah[3] = *(const uint32_t*)&Qh[aoff + 8 * AP + 8];
                al[0] = *(const uint32_t*)&Ql[aoff];
                al[1] = *(const uint32_t*)&Ql[aoff + 8 * AP];
                al[2] = *(const uint32_t*)&Ql[aoff + 8];
                al[3] = *(const uint32_t*)&Ql[aoff + 8 * AP + 8];
#pragma unroll
                for (int nt = 0; nt < 8; nt++) {
                    int boff = (nt * 8 + g) * AP + kc * 16 + 2 * tig;
                    uint32_t bh2[2], bl2[2];
                    bh2[0] = *(const uint32_t*)&Kh[boff];
                    bh2[1] = *(const uint32_t*)&Kh[boff + 8];
                    bl2[0] = *(const uint32_t*)&Kl[boff];
                    bl2[1] = *(const uint32_t*)&Kl[boff + 8];
                    mma16816(sacc[nt], ah, bh2);
                    mma16816(sacc[nt], ah, bl2);
                    mma16816(sacc[nt], al, bh2);
                }
            }

            const bool needmask = (k0 + 63) > wr0;
#pragma unroll
            for (int nt = 0; nt < 8; nt++)
#pragma unroll
                for (int e = 0; e < 4; e++) {
                    float sv = sacc[nt][e] * scale;
                    if (needmask) {
                        int row = wr0 + g + ((e >> 1) << 3);
                        int col = k0 + nt * 8 + 2 * tig + (e & 1);
                        if (col > row) sv = -1e30f;
                    }
                    sacc[nt][e] = sv;
                }

#pragma unroll
            for (int rr = 0; rr < 2; rr++) {
                float mx = -1e30f;
#pragma unroll
                for (int nt = 0; nt < 8; nt++)
                    mx = fmaxf(mx, fmaxf(sacc[nt][2 * rr], sacc[nt][2 * rr + 1]));
                mx = fmaxf(mx, __shfl_xor_sync(0xffffffffu, mx, 1));
                mx = fmaxf(mx, __shfl_xor_sync(0xffffffffu, mx, 2));
                float mnew = fmaxf(mrow[rr], mx);
                float alpha = __expf(mrow[rr] - mnew);
                float rs = 0.f;
#pragma unroll
                for (int nt = 0; nt < 8; nt++) {
                    float p0 = __expf(sacc[nt][2 * rr] - mnew);
                    float p1 = __expf(sacc[nt][2 * rr + 1] - mnew);
                    sacc[nt][2 * rr] = p0;
                    sacc[nt][2 * rr + 1] = p1;
                    rs += p0 + p1;
                }
                rs += __shfl_xor_sync(0xffffffffu, rs, 1);
                rs += __shfl_xor_sync(0xffffffffu, rs, 2);
                lrow[rr] = lrow[rr] * alpha + rs;
                mrow[rr] = mnew;
#pragma unroll
                for (int vn = 0; vn < 8; vn++) {
                    oacc[vn][2 * rr] *= alpha;
                    oacc[vn][2 * rr + 1] *= alpha;
                }
            }

#pragma unroll
            for (int kc2 = 0; kc2 < 4; kc2++) {
                float* t0 = sacc[2 * kc2];
                float* t1 = sacc[2 * kc2 + 1];
                float h00 = __bfloat162float(__float2bfloat16_rn(t0[0]));
                float h01 = __bfloat162float(__float2bfloat16_rn(t0[1]));
                float h02 = __bfloat162float(__float2bfloat16_rn(t0[2]));
                float h03 = __bfloat162float(__float2bfloat16_rn(t0[3]));
                float h10 = __bfloat162float(__float2bfloat16_rn(t1[0]));
                float h11 = __bfloat162float(__float2bfloat16_rn(t1[1]));
                float h12 = __bfloat162float(__float2bfloat16_rn(t1[2]));
                float h13 = __bfloat162float(__float2bfloat16_rn(t1[3]));
                uint32_t ph[4], pl[4];
                ph[0] = pk2(h00, h01); ph[1] = pk2(h02, h03);
                ph[2] = pk2(h10, h11); ph[3] = pk2(h12, h13);
                pl[0] = pk2(t0[0] - h00, t0[1] - h01);
                pl[1] = pk2(t0[2] - h02, t0[3] - h03);
                pl[2] = pk2(t1[0] - h10, t1[1] - h11);
                pl[3] = pk2(t1[2] - h12, t1[3] - h13);

                const uint32_t kbase = (uint32_t)(kc2 * 16 * AP) * 2 + vrow_off + vcol_off;
#pragma unroll
                for (int vnp = 0; vnp < 4; vnp++) {
                    uint32_t vaddr = kbase + (uint32_t)(vnp * 16) * 2;
                    uint32_t vh4[4], vl4[4];
                    ldm_x4t(vh4, vhb + vaddr);
                    ldm_x4t(vl4, vlb + vaddr);
                    uint32_t bh0[2] = {vh4[0], vh4[1]}, bh1[2] = {vh4[2], vh4[3]};
                    uint32_t bl0[2] = {vl4[0], vl4[1]}, bl1[2] = {vl4[2], vl4[3]};
                    mma16816(oacc[2 * vnp], ph, bh0);
                    mma16816(oacc[2 * vnp], pl, bh0);
                    mma16816(oacc[2 * vnp], ph, bl0);
                    mma16816(oacc[2 * vnp + 1], ph, bh1);
                    mma16816(oacc[2 * vnp + 1], pl, bh1);
                    mma16816(oacc[2 * vnp + 1], ph, bl1);
                }
            }
        }
    }

#pragma unroll
    for (int rr = 0; rr < 2; rr++) {
        float inv = 1.f / lrow[rr];
        int r = wr0 + g + rr * 8;
        size_t rb = (size_t)(b * SS + r) * DD + hoff;
#pragma unroll
        for (int vn = 0; vn < 8; vn++) {
            float o0 = oacc[vn][2 * rr] * inv;
            float o1 = oacc[vn][2 * rr + 1] * inv;
            float h0 = __bfloat162float(__float2bfloat16_rn(o0));
            float h1 = __bfloat162float(__float2bfloat16_rn(o1));
            int col = vn * 8 + 2 * tig;
            *(uint32_t*)&thi[rb + col] = pk2(h0, h1);
            *(uint32_t*)&tlo[rb + col] = pk2(o0 - h0, o1 - h1);
        }
    }
}

// ---------------------------------------------------------------------------
// Residual add + LayerNorm + split
// ---------------------------------------------------------------------------
__global__ __launch_bounds__(256) void add_ln_kernel(float* __restrict__ x,
                                                     const float* __restrict__ y,
                                                     const float* __restrict__ g,
                                                     const float* __restrict__ bb,
                                                     bf16* __restrict__ xhi,
                                                     bf16* __restrict__ xlo) {
    const int row = blockIdx.x;
    const int tid = threadIdx.x;
    float2 xv = *(const float2*)&x[(size_t)row * DD + tid * 2];
    float2 yv = *(const float2*)&y[(size_t)row * DD + tid * 2];
    float a0 = xv.x + yv.x;
    float a1 = xv.y + yv.y;

    float s = a0 + a1;
    float ss = a0 * a0 + a1 * a1;
#pragma unroll
    for (int off = 16; off >= 1; off >>= 1) {
        s += __shfl_xor_sync(0xffffffffu, s, off);
        ss += __shfl_xor_sync(0xffffffffu, ss, off);
    }
    __shared__ float sbuf[8], ssbuf[8];
    if ((tid & 31) == 0) { sbuf[tid >> 5] = s; ssbuf[tid >> 5] = ss; }
    __syncthreads();
    float ts = 0.f, tss = 0.f;
#pragma unroll
    for (int i = 0; i < 8; i++) { ts += sbuf[i]; tss += ssbuf[i]; }
    float mean = ts * (1.f / DD);
    float var = tss * (1.f / DD) - mean * mean;
    float rstd = rsqrtf(var + 1e-5f);

    int col = tid * 2;
    float2 go = *(const float2*)&g[col];
    float2 bo = *(const float2*)&bb[col];
    float o0 = (a0 - mean) * rstd * go.x + bo.x;
    float o1 = (a1 - mean) * rstd * go.y + bo.y;
    *(float2*)&x[(size_t)row * DD + col] = make_float2(o0, o1);
    float h0 = __bfloat162float(__float2bfloat16_rn(o0));
    float h1 = __bfloat162float(__float2bfloat16_rn(o1));
    *(uint32_t*)&xhi[(size_t)row * DD + col] = pk2(h0, h1);
    *(uint32_t*)&xlo[(size_t)row * DD + col] = pk2(o0 - h0, o1 - h1);
}

// ---------------------------------------------------------------------------
// Host driver
// ---------------------------------------------------------------------------
extern "C" void kernel_launch(void* const* d_in, const int* in_sizes, int n_in,
                              void* d_out, int out_size) {
    const int* source = (const int*)d_in[0];
    const float* emb = (const float*)d_in[1];
    const float* ln_g = (const float*)d_in[2];
    const float* ln_b = (const float*)d_in[3];
    const float* wq = (const float*)d_in[4];
    const float* bq = (const float*)d_in[5];
    const float* wk = (const float*)d_in[6];
    const float* bk = (const float*)d_in[7];
    const float* wv = (const float*)d_in[8];
    const float* bv = (const float*)d_in[9];
    const float* wo = (const float*)d_in[10];
    const float* bo = (const float*)d_in[11];
    const float* w1 = (const float*)d_in[12];
    const float* b1 = (const float*)d_in[13];
    const float* w2 = (const float*)d_in[14];
    const float* b2 = (const float*)d_in[15];

    float* x = (float*)d_out;

    float *tmp, *bqkv;
    bf16 *xhi, *xlo, *qkvhi, *qkvlo, *thi, *tlo, *hhi, *hlo;
    bf16 *wqkvhi, *wqkvlo, *wohi, *wolo, *w1hi, *w1lo, *w2hi, *w2lo;
    cudaGetSymbolAddress((void**)&tmp, g_tmp);
    cudaGetSymbolAddress((void**)&bqkv, g_bqkv);
    cudaGetSymbolAddress((void**)&xhi, g_xhi);
    cudaGetSymbolAddress((void**)&xlo, g_xlo);
    cudaGetSymbolAddress((void**)&qkvhi, g_qkvhi);
    cudaGetSymbolAddress((void**)&qkvlo, g_qkvlo);
    cudaGetSymbolAddress((void**)&thi, g_thi);
    cudaGetSymbolAddress((void**)&tlo, g_tlo);
    cudaGetSymbolAddress((void**)&hhi, g_hhi);
    cudaGetSymbolAddress((void**)&hlo, g_hlo);
    cudaGetSymbolAddress((void**)&wqkvhi, g_wqkvhi);
    cudaGetSymbolAddress((void**)&wqkvlo, g_wqkvlo);
    cudaGetSymbolAddress((void**)&wohi, g_wohi);
    cudaGetSymbolAddress((void**)&wolo, g_wolo);
    cudaGetSymbolAddress((void**)&w1hi, g_w1hi);
    cudaGetSymbolAddress((void**)&w1lo, g_w1lo);
    cudaGetSymbolAddress((void**)&w2hi, g_w2hi);
    cudaGetSymbolAddress((void**)&w2lo, g_w2lo);

    cudaFuncSetAttribute(attn_tc_kernel, cudaFuncAttributeMaxDynamicSharedMemorySize,
                         ATT_SMEM);
    cudaFuncSetAttribute(gemm_wm_kernel, cudaFuncAttributeMaxDynamicSharedMemorySize,
                         GSMEM);

    embed_kernel<<<NROWS, 128>>>(source, emb, x, xhi, xlo);
    {
        dim3 gD(DD / 32, DD / 32, LL);
        transpose_cvt_kernel<<<gD, 256>>>(wq, wqkvhi, wqkvlo, DD, DD,
                                          (size_t)DD * DD, (size_t)TD * DD);
        transpose_cvt_kernel<<<gD, 256>>>(wk, wqkvhi + (size_t)DD * DD,
                                          wqkvlo + (size_t)DD * DD, DD, DD,
                                          (size_t)DD * DD, (size_t)TD * DD);
        transpose_cvt_kernel<<<gD, 256>>>(wv, wqkvhi + (size_t)2 * DD * DD,
                                          wqkvlo + (size_t)2 * DD * DD, DD, DD,
                                          (size_t)DD * DD, (size_t)TD * DD);
        transpose_cvt_kernel<<<gD, 256>>>(wo, wohi, wolo, DD, DD,
                                          (size_t)DD * DD, (size_t)DD * DD);
        dim3 g1(FF / 32, DD / 32, LL);
        transpose_cvt_kernel<<<g1, 256>>>(w1, w1hi, w1lo, DD, FF,
                                          (size_t)DD * FF, (size_t)FF * DD);
        dim3 g2(DD / 32, FF / 32, LL);
        transpose_cvt_kernel<<<g2, 256>>>(w2, w2hi, w2lo, FF, DD,
                                          (size_t)FF * DD, (size_t)DD * FF);
        pack_bias_kernel<<<(LL * TD + 255) / 256, 256>>>(bq, bk, bv, bqkv);
    }

    dim3 gA(BB * HH, SS / 128);   // x=bh, y=qtile (reversed in-kernel)

    auto gemm = [&](const bf16* ah, const bf16* al, const bf16* bh, const bf16* bl,
                    const float* bias, float* C, bf16* Ch, bf16* Cl,
                    int M, int N, int K, int relu, int mode) {
        dim3 g(N / 128, M / 128);
        gemm_wm_kernel<<<g, 256, GSMEM>>>(ah, al, bh, bl, bias, C, Ch, Cl,
                                          M, N, K, relu, mode);
    };

    for (int l = 0; l < LL; l++) {
        const bf16* Wqkvh = wqkvhi + (size_t)l * TD * DD;
        const bf16* Wqkvl = wqkvlo + (size_t)l * TD * DD;
        const bf16* Woh = wohi + (size_t)l * DD * DD;
        const bf16* Wol = wolo + (size_t)l * DD * DD;
        const bf16* W1h = w1hi + (size_t)l * FF * DD;
        const bf16* W1l = w1lo + (size_t)l * FF * DD;
        const bf16* W2h = w2hi + (size_t)l * DD * FF;
        const bf16* W2l = w2lo + (size_t)l * DD * FF;
        const float* Bqkv = bqkv + (size_t)l * TD;
        const float* Bo = bo + (size_t)l * DD;
        const float* B1 = b1 + (size_t)l * FF;
        const float* B2 = b2 + (size_t)l * DD;

        gemm(xhi, xlo, Wqkvh, Wqkvl, Bqkv, nullptr, qkvhi, qkvlo,
             NROWS, TD, DD, 0, 1);

        attn_tc_kernel<<<gA, 256, ATT_SMEM>>>(qkvhi, qkvlo, thi, tlo);

        gemm(thi, tlo, Woh, Wol, Bo, tmp, nullptr, nullptr, NROWS, DD, DD, 0, 0);
        add_ln_kernel<<<NROWS, 256>>>(x, tmp, ln_g, ln_b, xhi, xlo);

        gemm(xhi, xlo, W1h, W1l, B1, nullptr, hhi, hlo, NROWS, FF, DD, 1, 1);
        gemm(hhi, hlo, W2h, W2l, B2, tmp, nullptr, nullptr, NROWS, DD, FF, 1, 0);
        add_ln_kernel<<<NROWS, 256>>>(x, tmp, ln_g, ln_b, xhi, xlo);
    }
}

// round 12
// speedup vs baseline: 1.4350x; 1.2872x over previous
#include <cuda_runtime.h>
#include <cuda_fp16.h>
#include <math.h>
#include <stdint.h>

#define BB 4
#define SS 2048
#define DD 512
#define HH 8
#define DHH 64
#define FF 2048
#define LL 6
#define NROWS (BB*SS)   // 8192
#define TD (3*DD)       // 1536 packed qkv width

typedef __half f16;

// ---------------------------------------------------------------------------
// Scratch
// ---------------------------------------------------------------------------
__device__ float g_tmp[NROWS * DD];
__device__ f16 g_xhi[NROWS * DD];
__device__ f16 g_xlo[NROWS * DD];
__device__ f16 g_qkvhi[NROWS * TD];
__device__ f16 g_qkvlo[NROWS * TD];
__device__ f16 g_thi[NROWS * DD];
__device__ f16 g_tlo[NROWS * DD];
__device__ f16 g_hhi[NROWS * FF];
__device__ f16 g_hlo[NROWS * FF];
__device__ f16 g_wqkvhi[LL * TD * DD];
__device__ f16 g_wohi[LL * DD * DD];
__device__ f16 g_w1hi[LL * FF * DD];
__device__ f16 g_w2hi[LL * DD * FF];
__device__ float g_bqkv[LL * TD];

// ---------------------------------------------------------------------------
// helpers
// ---------------------------------------------------------------------------
__device__ __forceinline__ uint32_t smem_u32(const void* p) {
    uint32_t a;
    asm("{ .reg .u64 t; cvta.to.shared.u64 t, %1; cvt.u32.u64 %0, t; }"
        : "=r"(a) : "l"(p));
    return a;
}

__device__ __forceinline__ void mma16816(float* c, const uint32_t* a, const uint32_t* b) {
    asm volatile(
        "mma.sync.aligned.m16n8k16.row.col.f32.f16.f16.f32 "
        "{%0,%1,%2,%3}, {%4,%5,%6,%7}, {%8,%9}, {%0,%1,%2,%3};"
        : "+f"(c[0]), "+f"(c[1]), "+f"(c[2]), "+f"(c[3])
        : "r"(a[0]), "r"(a[1]), "r"(a[2]), "r"(a[3]), "r"(b[0]), "r"(b[1]));
}

__device__ __forceinline__ void ldm_x4t(uint32_t* r, uint32_t addr) {
    asm volatile("ldmatrix.sync.aligned.m8n8.x4.trans.shared.b16 {%0,%1,%2,%3}, [%4];"
                 : "=r"(r[0]), "=r"(r[1]), "=r"(r[2]), "=r"(r[3]) : "r"(addr));
}

__device__ __forceinline__ void cpa16(uint32_t dst, const void* src) {
    asm volatile("cp.async.cg.shared.global [%0], [%1], 16;" :: "r"(dst), "l"(src));
}

__device__ __forceinline__ uint32_t pk2(float x0, float x1) {
    __half2 t = __floats2half2_rn(x0, x1);
    return *(uint32_t*)&t;
}
__device__ __forceinline__ float hf(float v) {
    return __half2float(__float2half_rn(v));
}

// ---------------------------------------------------------------------------
// Embedding gather + fp16 split
// ---------------------------------------------------------------------------
__global__ __launch_bounds__(128) void embed_kernel(const int* __restrict__ src,
                                                    const float* __restrict__ emb,
                                                    float* __restrict__ x,
                                                    f16* __restrict__ xhi,
                                                    f16* __restrict__ xlo) {
    int row = blockIdx.x;
    int tok = src[row];
    float4 v = ((const float4*)(emb + (size_t)tok * DD))[threadIdx.x];
    ((float4*)(x + (size_t)row * DD))[threadIdx.x] = v;
    float h0 = hf(v.x), h1 = hf(v.y), h2 = hf(v.z), h3 = hf(v.w);
    uint32_t* H = (uint32_t*)(xhi + (size_t)row * DD);
    uint32_t* L = (uint32_t*)(xlo + (size_t)row * DD);
    H[2 * threadIdx.x]     = pk2(h0, h1);
    H[2 * threadIdx.x + 1] = pk2(h2, h3);
    L[2 * threadIdx.x]     = pk2(v.x - h0, v.y - h1);
    L[2 * threadIdx.x + 1] = pk2(v.z - h2, v.w - h3);
}

// ---------------------------------------------------------------------------
// Batched transpose + fp16 convert (hi only — weight residual dropped)
// ---------------------------------------------------------------------------
__global__ __launch_bounds__(256) void transpose_cvt_kernel(
    const float* __restrict__ W, f16* __restrict__ WThi,
    int K, int N, size_t src_ls, size_t dst_ls) {
    __shared__ float t[32][33];
    const float* Wl = W + (size_t)blockIdx.z * src_ls;
    f16* Hl = WThi + (size_t)blockIdx.z * dst_ls;
    int n0 = blockIdx.x * 32, k0 = blockIdx.y * 32;
    int c = threadIdx.x & 31, r = threadIdx.x >> 5;
#pragma unroll
    for (int i = 0; i < 4; i++)
        t[r + i * 8][c] = Wl[(size_t)(k0 + r + i * 8) * N + n0 + c];
    __syncthreads();
#pragma unroll
    for (int i = 0; i < 4; i++) {
        float x = t[c][r + i * 8];
        Hl[(size_t)(n0 + r + i * 8) * K + k0 + c] = __float2half_rn(x);
    }
}

__global__ __launch_bounds__(256) void pack_bias_kernel(const float* __restrict__ bq,
                                                        const float* __restrict__ bk,
                                                        const float* __restrict__ bv,
                                                        float* __restrict__ dst) {
    int i = blockIdx.x * 256 + threadIdx.x;
    if (i >= LL * TD) return;
    int l = i / TD, r = i % TD;
    int sel = r / DD, c = r % DD;
    const float* s = sel == 0 ? bq : (sel == 1 ? bk : bv);
    dst[i] = s[l * DD + c];
}

// ---------------------------------------------------------------------------
// Warp-MMA fp16 GEMM: D = (A_hi + A_lo) * B_hi  (2 MMAs per tile product).
// 3 operand tiles per stage (Ahi, Alo, Bhi). R8 two-sync pipeline.
// ---------------------------------------------------------------------------
#define GP_B   80
#define GTILE_B (128 * GP_B)
#define GSTAGE_B (3 * GTILE_B)
#define GSMEM   (2 * GSTAGE_B)    // 61440

__global__ __launch_bounds__(256, 2) void gemm_wm_kernel(
    const f16* __restrict__ Ahi, const f16* __restrict__ Alo,
    const f16* __restrict__ Bhi,
    const float* __restrict__ bias, float* __restrict__ C,
    f16* __restrict__ Chi, f16* __restrict__ Clo,
    int M, int N, int K, int relu, int mode) {
    extern __shared__ char sm[];
    const uint32_t sbase = smem_u32(sm);

    const int tid = threadIdx.x;
    const int lane = tid & 31;
    const int wid = tid >> 5;
    const int warp_m = wid >> 2;
    const int warp_n = wid & 3;
    const int g = lane >> 2;
    const int tig = lane & 3;

    const int bm = blockIdx.y * 128;
    const int bn = blockIdx.x * 128;

    const f16* srcs[3] = {
        Ahi + (size_t)bm * K, Alo + (size_t)bm * K, Bhi + (size_t)bn * K };

    float acc[4][4][4];
#pragma unroll
    for (int mt = 0; mt < 4; mt++)
#pragma unroll
        for (int nt = 0; nt < 4; nt++)
#pragma unroll
            for (int e = 0; e < 4; e++) acc[mt][nt][e] = 0.f;

    const int NIT = K >> 5;

    auto load_stage = [&](int s, int it) {
        const uint32_t stage = sbase + (uint32_t)s * GSTAGE_B;
#pragma unroll
        for (int t = 0; t < 3; t++) {
#pragma unroll
            for (int i = 0; i < 2; i++) {
                int idx = i * 256 + tid;
                int r = idx >> 2;
                int c8 = idx & 3;
                const void* src = (const char*)(srcs[t] + (size_t)r * K + it * 32) + c8 * 16;
                uint32_t dst = stage + (uint32_t)t * GTILE_B + (uint32_t)r * GP_B + c8 * 16;
                cpa16(dst, src);
            }
        }
        asm volatile("cp.async.commit_group;" ::: "memory");
    };

    load_stage(0, 0);

    for (int it = 0; it < NIT; it++) {
        const int buf = it & 1;
        if (it + 1 < NIT) {
            load_stage(buf ^ 1, it + 1);
            asm volatile("cp.async.wait_group 1;" ::: "memory");
        } else {
            asm volatile("cp.async.wait_group 0;" ::: "memory");
        }
        __syncthreads();

        const char* A0 = sm + buf * GSTAGE_B;
        const char* A1 = A0 + GTILE_B;
        const char* B0 = A0 + 2 * GTILE_B;

#pragma unroll
        for (int ks = 0; ks < 2; ks++) {
            const int kb = ks * 32 + tig * 4;
            uint32_t bh[4][2];
#pragma unroll
            for (int nt = 0; nt < 4; nt++) {
                int off = (warp_n * 32 + nt * 8 + g) * GP_B + kb;
                bh[nt][0] = *(const uint32_t*)(B0 + off);
                bh[nt][1] = *(const uint32_t*)(B0 + off + 16);
            }
#pragma unroll
            for (int mt = 0; mt < 4; mt++) {
                uint32_t ah[4], al[4];
                int off = (warp_m * 64 + mt * 16 + g) * GP_B + kb;
                ah[0] = *(const uint32_t*)(A0 + off);
                ah[1] = *(const uint32_t*)(A0 + off + 8 * GP_B);
                ah[2] = *(const uint32_t*)(A0 + off + 16);
                ah[3] = *(const uint32_t*)(A0 + off + 8 * GP_B + 16);
                al[0] = *(const uint32_t*)(A1 + off);
                al[1] = *(const uint32_t*)(A1 + off + 8 * GP_B);
                al[2] = *(const uint32_t*)(A1 + off + 16);
                al[3] = *(const uint32_t*)(A1 + off + 8 * GP_B + 16);
#pragma unroll
                for (int nt = 0; nt < 4; nt++) {
                    mma16816(acc[mt][nt], ah, bh[nt]);
                    mma16816(acc[mt][nt], al, bh[nt]);
                }
            }
        }
        __syncthreads();
    }

#pragma unroll
    for (int mt = 0; mt < 4; mt++) {
        int row0 = bm + warp_m * 64 + mt * 16 + g;
#pragma unroll
        for (int nt = 0; nt < 4; nt++) {
            int col = bn + warp_n * 32 + nt * 8 + 2 * tig;
            float bx = bias[col], by = bias[col + 1];
            float v00 = acc[mt][nt][0] + bx, v01 = acc[mt][nt][1] + by;
            float v10 = acc[mt][nt][2] + bx, v11 = acc[mt][nt][3] + by;
            if (relu) {
                v00 = fmaxf(v00, 0.f); v01 = fmaxf(v01, 0.f);
                v10 = fmaxf(v10, 0.f); v11 = fmaxf(v11, 0.f);
            }
            if (mode == 0) {
                *(float2*)&C[(size_t)row0 * N + col] = make_float2(v00, v01);
                *(float2*)&C[(size_t)(row0 + 8) * N + col] = make_float2(v10, v11);
            } else {
                float h00 = hf(v00), h01 = hf(v01), h10 = hf(v10), h11 = hf(v11);
                *(uint32_t*)&Chi[(size_t)row0 * N + col] = pk2(h00, h01);
                *(uint32_t*)&Chi[(size_t)(row0 + 8) * N + col] = pk2(h10, h11);
                *(uint32_t*)&Clo[(size_t)row0 * N + col] = pk2(v00 - h00, v01 - h01);
                *(uint32_t*)&Clo[(size_t)(row0 + 8) * N + col] = pk2(v10 - h10, v11 - h11);
            }
        }
    }
}

// ---------------------------------------------------------------------------
// Tensor-core flash attention — R8/R11 structure in fp16, 3-term hi/lo MMA.
// Grid (bh, qtile), qb reversed for global longest-first.
// ---------------------------------------------------------------------------
#define AP 72
#define ATT_SMEM ((2*128 + 4*64) * AP * 2)   // 73728 bytes

__global__ __launch_bounds__(256, 2) void attn_tc_kernel(
    const f16* __restrict__ qkvhi, const f16* __restrict__ qkvlo,
    f16* __restrict__ thi, f16* __restrict__ tlo) {
    extern __shared__ f16 asmem[];
    const uint32_t sb = smem_u32(asmem);
    f16* Qh = asmem;
    f16* Ql = Qh + 128 * AP;
    f16* Kh = Ql + 128 * AP;
    f16* Kl = Kh + 64 * AP;
    f16* Vh = Kl + 64 * AP;
    f16* Vl = Vh + 64 * AP;
    const uint32_t vhb = sb + (uint32_t)(384 * AP) * 2;
    const uint32_t vlb = sb + (uint32_t)(448 * AP) * 2;

    const int tid = threadIdx.x;
    const int lane = tid & 31;
    const int wid = tid >> 5;
    const int g = lane >> 2;
    const int tig = lane & 3;

    const int qb = gridDim.y - 1 - blockIdx.y;
    const int bh = blockIdx.x;
    const int b = bh / HH;
    const int h = bh % HH;
    const int q0 = qb * 128;
    const size_t hoff = (size_t)h * DHH;

#pragma unroll
    for (int i = 0; i < 4; i++) {
        int idx = i * 256 + tid;
        int row = idx >> 3;
        int cb = (idx & 7) * 8;
        size_t go = (size_t)(b * SS + q0 + row) * TD + hoff + cb;
        *(uint4*)&Qh[row * AP + cb] = *(const uint4*)&qkvhi[go];
        *(uint4*)&Ql[row * AP + cb] = *(const uint4*)&qkvlo[go];
    }

    float oacc[8][4];
#pragma unroll
    for (int vn = 0; vn < 8; vn++)
#pragma unroll
        for (int e = 0; e < 4; e++) oacc[vn][e] = 0.f;
    float mrow[2] = {-1e30f, -1e30f};
    float lrow[2] = {0.f, 0.f};

    const int nkt = 2 * qb + 2;
    const int wr0 = q0 + wid * 16;
    const float scale = 0.125f;

    const int l7 = lane & 7;
    const int grp = lane >> 3;
    const uint32_t vrow_off = (uint32_t)((l7 + (grp & 1) * 8) * AP) * 2;
    const uint32_t vcol_off = (uint32_t)((grp >> 1) * 8) * 2;

    for (int kt = 0; kt < nkt; kt++) {
        const int k0 = kt * 64;
        __syncthreads();
#pragma unroll
        for (int i = 0; i < 2; i++) {
            int idx = i * 256 + tid;
            int row = idx >> 3;
            int cb = (idx & 7) * 8;
            size_t go = (size_t)(b * SS + k0 + row) * TD + hoff + cb;
            *(uint4*)&Kh[row * AP + cb] = *(const uint4*)&qkvhi[go + DD];
            *(uint4*)&Kl[row * AP + cb] = *(const uint4*)&qkvlo[go + DD];
            *(uint4*)&Vh[row * AP + cb] = *(const uint4*)&qkvhi[go + 2 * DD];
            *(uint4*)&Vl[row * AP + cb] = *(const uint4*)&qkvlo[go + 2 * DD];
        }
        __syncthreads();

        if (k0 <= wr0 + 15) {
            float sacc[8][4];
#pragma unroll
            for (int nt = 0; nt < 8; nt++)
#pragma unroll
                for (int e = 0; e < 4; e++) sacc[nt][e] = 0.f;

#pragma unroll
            for (int kc = 0; kc < 4; kc++) {
                uint32_t ah[4], al[4];
                int aoff = (wid * 16 + g) * AP + kc * 16 + 2 * tig;
                ah[0] = *(const uint32_t*)&Qh[aoff];
                ah[1] = *(const uint32_t*)&Qh[aoff + 8 * AP];
                ah[2] = *(const uint32_t*)&Qh[aoff + 8];
                ah[3] = *(const uint32_t*)&Qh[aoff + 8 * AP + 8];
                al[0] = *(const uint32_t*)&Ql[aoff];
                al[1] = *(const uint32_t*)&Ql[aoff + 8 * AP];
                al[2] = *(const uint32_t*)&Ql[aoff + 8];
                al[3] = *(const uint32_t*)&Ql[aoff + 8 * AP + 8];
#pragma unroll
                for (int nt = 0; nt < 8; nt++) {
                    int boff = (nt * 8 + g) * AP + kc * 16 + 2 * tig;
                    uint32_t bh2[2], bl2[2];
                    bh2[0] = *(const uint32_t*)&Kh[boff];
                    bh2[1] = *(const uint32_t*)&Kh[boff + 8];
                    bl2[0] = *(const uint32_t*)&Kl[boff];
                    bl2[1] = *(const uint32_t*)&Kl[boff + 8];
                    mma16816(sacc[nt], ah, bh2);
                    mma16816(sacc[nt], ah, bl2);
                    mma16816(sacc[nt], al, bh2);
                }
            }

            const bool needmask = (k0 + 63) > wr0;
#pragma unroll
            for (int nt = 0; nt < 8; nt++)
#pragma unroll
                for (int e = 0; e < 4; e++) {
                    float sv = sacc[nt][e] * scale;
                    if (needmask) {
                        int row = wr0 + g + ((e >> 1) << 3);
                        int col = k0 + nt * 8 + 2 * tig + (e & 1);
                        if (col > row) sv = -1e30f;
                    }
                    sacc[nt][e] = sv;
                }

#pragma unroll
            for (int rr = 0; rr < 2; rr++) {
                float mx = -1e30f;
#pragma unroll
                for (int nt = 0; nt < 8; nt++)
                    mx = fmaxf(mx, fmaxf(sacc[nt][2 * rr], sacc[nt][2 * rr + 1]));
                mx = fmaxf(mx, __shfl_xor_sync(0xffffffffu, mx, 1));
                mx = fmaxf(mx, __shfl_xor_sync(0xffffffffu, mx, 2));
                float mnew = fmaxf(mrow[rr], mx);
                float alpha = __expf(mrow[rr] - mnew);
                float rs = 0.f;
#pragma unroll
                for (int nt = 0; nt < 8; nt++) {
                    float p0 = __expf(sacc[nt][2 * rr] - mnew);
                    float p1 = __expf(sacc[nt][2 * rr + 1] - mnew);
                    sacc[nt][2 * rr] = p0;
                    sacc[nt][2 * rr + 1] = p1;
                    rs += p0 + p1;
                }
                rs += __shfl_xor_sync(0xffffffffu, rs, 1);
                rs += __shfl_xor_sync(0xffffffffu, rs, 2);
                lrow[rr] = lrow[rr] * alpha + rs;
                mrow[rr] = mnew;
#pragma unroll
                for (int vn = 0; vn < 8; vn++) {
                    oacc[vn][2 * rr] *= alpha;
                    oacc[vn][2 * rr + 1] *= alpha;
                }
            }

#pragma unroll
            for (int kc2 = 0; kc2 < 4; kc2++) {
                float* t0 = sacc[2 * kc2];
                float* t1 = sacc[2 * kc2 + 1];
                float h00 = hf(t0[0]), h01 = hf(t0[1]), h02 = hf(t0[2]), h03 = hf(t0[3]);
                float h10 = hf(t1[0]), h11 = hf(t1[1]), h12 = hf(t1[2]), h13 = hf(t1[3]);
                uint32_t ph[4], pl[4];
                ph[0] = pk2(h00, h01); ph[1] = pk2(h02, h03);
                ph[2] = pk2(h10, h11); ph[3] = pk2(h12, h13);
                pl[0] = pk2(t0[0] - h00, t0[1] - h01);
                pl[1] = pk2(t0[2] - h02, t0[3] - h03);
                pl[2] = pk2(t1[0] - h10, t1[1] - h11);
                pl[3] = pk2(t1[2] - h12, t1[3] - h13);

                const uint32_t kbase = (uint32_t)(kc2 * 16 * AP) * 2 + vrow_off + vcol_off;
#pragma unroll
                for (int vnp = 0; vnp < 4; vnp++) {
                    uint32_t vaddr = kbase + (uint32_t)(vnp * 16) * 2;
                    uint32_t vh4[4], vl4[4];
                    ldm_x4t(vh4, vhb + vaddr);
                    ldm_x4t(vl4, vlb + vaddr);
                    uint32_t bh0[2] = {vh4[0], vh4[1]}, bh1[2] = {vh4[2], vh4[3]};
                    uint32_t bl0[2] = {vl4[0], vl4[1]}, bl1[2] = {vl4[2], vl4[3]};
                    mma16816(oacc[2 * vnp], ph, bh0);
                    mma16816(oacc[2 * vnp], pl, bh0);
                    mma16816(oacc[2 * vnp], ph, bl0);
                    mma16816(oacc[2 * vnp + 1], ph, bh1);
                    mma16816(oacc[2 * vnp + 1], pl, bh1);
                    mma16816(oacc[2 * vnp + 1], ph, bl1);
                }
            }
        }
    }

#pragma unroll
    for (int rr = 0; rr < 2; rr++) {
        float inv = 1.f / lrow[rr];
        int r = wr0 + g + rr * 8;
        size_t rb = (size_t)(b * SS + r) * DD + hoff;
#pragma unroll
        for (int vn = 0; vn < 8; vn++) {
            float o0 = oacc[vn][2 * rr] * inv;
            float o1 = oacc[vn][2 * rr + 1] * inv;
            float h0 = hf(o0), h1 = hf(o1);
            int col = vn * 8 + 2 * tig;
            *(uint32_t*)&thi[rb + col] = pk2(h0, h1);
            *(uint32_t*)&tlo[rb + col] = pk2(o0 - h0, o1 - h1);
        }
    }
}

// ---------------------------------------------------------------------------
// Residual add + LayerNorm + fp16 split
// ---------------------------------------------------------------------------
__global__ __launch_bounds__(256) void add_ln_kernel(float* __restrict__ x,
                                                     const float* __restrict__ y,
                                                     const float* __restrict__ g,
                                                     const float* __restrict__ bb,
                                                     f16* __restrict__ xhi,
                                                     f16* __restrict__ xlo) {
    const int row = blockIdx.x;
    const int tid = threadIdx.x;
    float2 xv = *(const float2*)&x[(size_t)row * DD + tid * 2];
    float2 yv = *(const float2*)&y[(size_t)row * DD + tid * 2];
    float a0 = xv.x + yv.x;
    float a1 = xv.y + yv.y;

    float s = a0 + a1;
    float ss = a0 * a0 + a1 * a1;
#pragma unroll
    for (int off = 16; off >= 1; off >>= 1) {
        s += __shfl_xor_sync(0xffffffffu, s, off);
        ss += __shfl_xor_sync(0xffffffffu, ss, off);
    }
    __shared__ float sbuf[8], ssbuf[8];
    if ((tid & 31) == 0) { sbuf[tid >> 5] = s; ssbuf[tid >> 5] = ss; }
    __syncthreads();
    float ts = 0.f, tss = 0.f;
#pragma unroll
    for (int i = 0; i < 8; i++) { ts += sbuf[i]; tss += ssbuf[i]; }
    float mean = ts * (1.f / DD);
    float var = tss * (1.f / DD) - mean * mean;
    float rstd = rsqrtf(var + 1e-5f);

    int col = tid * 2;
    float2 go = *(const float2*)&g[col];
    float2 bo = *(const float2*)&bb[col];
    float o0 = (a0 - mean) * rstd * go.x + bo.x;
    float o1 = (a1 - mean) * rstd * go.y + bo.y;
    *(float2*)&x[(size_t)row * DD + col] = make_float2(o0, o1);
    float h0 = hf(o0), h1 = hf(o1);
    *(uint32_t*)&xhi[(size_t)row * DD + col] = pk2(h0, h1);
    *(uint32_t*)&xlo[(size_t)row * DD + col] = pk2(o0 - h0, o1 - h1);
}

// ---------------------------------------------------------------------------
// Host driver
// ---------------------------------------------------------------------------
extern "C" void kernel_launch(void* const* d_in, const int* in_sizes, int n_in,
                              void* d_out, int out_size) {
    const int* source = (const int*)d_in[0];
    const float* emb = (const float*)d_in[1];
    const float* ln_g = (const float*)d_in[2];
    const float* ln_b = (const float*)d_in[3];
    const float* wq = (const float*)d_in[4];
    const float* bq = (const float*)d_in[5];
    const float* wk = (const float*)d_in[6];
    const float* bk = (const float*)d_in[7];
    const float* wv = (const float*)d_in[8];
    const float* bv = (const float*)d_in[9];
    const float* wo = (const float*)d_in[10];
    const float* bo = (const float*)d_in[11];
    const float* w1 = (const float*)d_in[12];
    const float* b1 = (const float*)d_in[13];
    const float* w2 = (const float*)d_in[14];
    const float* b2 = (const float*)d_in[15];

    float* x = (float*)d_out;

    float *tmp, *bqkv;
    f16 *xhi, *xlo, *qkvhi, *qkvlo, *thi, *tlo, *hhi, *hlo;
    f16 *wqkvhi, *wohi, *w1hi, *w2hi;
    cudaGetSymbolAddress((void**)&tmp, g_tmp);
    cudaGetSymbolAddress((void**)&bqkv, g_bqkv);
    cudaGetSymbolAddress((void**)&xhi, g_xhi);
    cudaGetSymbolAddress((void**)&xlo, g_xlo);
    cudaGetSymbolAddress((void**)&qkvhi, g_qkvhi);
    cudaGetSymbolAddress((void**)&qkvlo, g_qkvlo);
    cudaGetSymbolAddress((void**)&thi, g_thi);
    cudaGetSymbolAddress((void**)&tlo, g_tlo);
    cudaGetSymbolAddress((void**)&hhi, g_hhi);
    cudaGetSymbolAddress((void**)&hlo, g_hlo);
    cudaGetSymbolAddress((void**)&wqkvhi, g_wqkvhi);
    cudaGetSymbolAddress((void**)&wohi, g_wohi);
    cudaGetSymbolAddress((void**)&w1hi, g_w1hi);
    cudaGetSymbolAddress((void**)&w2hi, g_w2hi);

    cudaFuncSetAttribute(attn_tc_kernel, cudaFuncAttributeMaxDynamicSharedMemorySize,
                         ATT_SMEM);
    cudaFuncSetAttribute(gemm_wm_kernel, cudaFuncAttributeMaxDynamicSharedMemorySize,
                         GSMEM);

    embed_kernel<<<NROWS, 128>>>(source, emb, x, xhi, xlo);
    {
        dim3 gD(DD / 32, DD / 32, LL);
        transpose_cvt_kernel<<<gD, 256>>>(wq, wqkvhi, DD, DD,
                                          (size_t)DD * DD, (size_t)TD * DD);
        transpose_cvt_kernel<<<gD, 256>>>(wk, wqkvhi + (size_t)DD * DD, DD, DD,
                                          (size_t)DD * DD, (size_t)TD * DD);
        transpose_cvt_kernel<<<gD, 256>>>(wv, wqkvhi + (size_t)2 * DD * DD, DD, DD,
                                          (size_t)DD * DD, (size_t)TD * DD);
        transpose_cvt_kernel<<<gD, 256>>>(wo, wohi, DD, DD,
                                          (size_t)DD * DD, (size_t)DD * DD);
        dim3 g1(FF / 32, DD / 32, LL);
        transpose_cvt_kernel<<<g1, 256>>>(w1, w1hi, DD, FF,
                                          (size_t)DD * FF, (size_t)FF * DD);
        dim3 g2(DD / 32, FF / 32, LL);
        transpose_cvt_kernel<<<g2, 256>>>(w2, w2hi, FF, DD,
                                          (size_t)FF * DD, (size_t)DD * FF);
        pack_bias_kernel<<<(LL * TD + 255) / 256, 256>>>(bq, bk, bv, bqkv);
    }

    dim3 gA(BB * HH, SS / 128);   // x=bh, y=qtile (reversed in-kernel)

    auto gemm = [&](const f16* ah, const f16* al, const f16* bhw,
                    const float* bias, float* C, f16* Ch, f16* Cl,
                    int M, int N, int K, int relu, int mode) {
        dim3 g(N / 128, M / 128);
        gemm_wm_kernel<<<g, 256, GSMEM>>>(ah, al, bhw, bias, C, Ch, Cl,
                                          M, N, K, relu, mode);
    };

    for (int l = 0; l < LL; l++) {
        const f16* Wqkvh = wqkvhi + (size_t)l * TD * DD;
        const f16* Woh = wohi + (size_t)l * DD * DD;
        const f16* W1h = w1hi + (size_t)l * FF * DD;
        const f16* W2h = w2hi + (size_t)l * DD * FF;
        const float* Bqkv = bqkv + (size_t)l * TD;
        const float* Bo = bo + (size_t)l * DD;
        const float* B1 = b1 + (size_t)l * FF;
        const float* B2 = b2 + (size_t)l * DD;

        gemm(xhi, xlo, Wqkvh, Bqkv, nullptr, qkvhi, qkvlo, NROWS, TD, DD, 0, 1);

        attn_tc_kernel<<<gA, 256, ATT_SMEM>>>(qkvhi, qkvlo, thi, tlo);

        gemm(thi, tlo, Woh, Bo, tmp, nullptr, nullptr, NROWS, DD, DD, 0, 0);
        add_ln_kernel<<<NROWS, 256>>>(x, tmp, ln_g, ln_b, xhi, xlo);

        gemm(xhi, xlo, W1h, B1, nullptr, hhi, hlo, NROWS, FF, DD, 1, 1);
        gemm(hhi, hlo, W2h, B2, tmp, nullptr, nullptr, NROWS, DD, FF, 1, 0);
        add_ln_kernel<<<NROWS, 256>>>(x, tmp, ln_g, ln_b, xhi, xlo);
    }
}

// round 13
// speedup vs baseline: 1.5497x; 1.0800x over previous
#include <cuda_runtime.h>
#include <cuda_fp16.h>
#include <math.h>
#include <stdint.h>

#define BB 4
#define SS 2048
#define DD 512
#define HH 8
#define DHH 64
#define FF 2048
#define LL 6
#define NROWS (BB*SS)   // 8192
#define TD (3*DD)       // 1536 packed qkv width

typedef __half f16;

// ---------------------------------------------------------------------------
// Scratch
// ---------------------------------------------------------------------------
__device__ float g_tmp[NROWS * DD];
__device__ f16 g_xhi[NROWS * DD];
__device__ f16 g_xlo[NROWS * DD];
__device__ f16 g_qkvhi[NROWS * TD];
__device__ f16 g_qkvlo[NROWS * TD];
__device__ f16 g_thi[NROWS * DD];
__device__ f16 g_tlo[NROWS * DD];
__device__ f16 g_hhi[NROWS * FF];
__device__ f16 g_hlo[NROWS * FF];
__device__ f16 g_wqkvhi[LL * TD * DD];
__device__ f16 g_wohi[LL * DD * DD];
__device__ f16 g_w1hi[LL * FF * DD];
__device__ f16 g_w2hi[LL * DD * FF];
__device__ float g_bqkv[LL * TD];

// ---------------------------------------------------------------------------
// helpers
// ---------------------------------------------------------------------------
__device__ __forceinline__ uint32_t smem_u32(const void* p) {
    uint32_t a;
    asm("{ .reg .u64 t; cvta.to.shared.u64 t, %1; cvt.u32.u64 %0, t; }"
        : "=r"(a) : "l"(p));
    return a;
}

__device__ __forceinline__ void mma16816(float* c, const uint32_t* a, const uint32_t* b) {
    asm volatile(
        "mma.sync.aligned.m16n8k16.row.col.f32.f16.f16.f32 "
        "{%0,%1,%2,%3}, {%4,%5,%6,%7}, {%8,%9}, {%0,%1,%2,%3};"
        : "+f"(c[0]), "+f"(c[1]), "+f"(c[2]), "+f"(c[3])
        : "r"(a[0]), "r"(a[1]), "r"(a[2]), "r"(a[3]), "r"(b[0]), "r"(b[1]));
}

__device__ __forceinline__ void ldm_x4t(uint32_t* r, uint32_t addr) {
    asm volatile("ldmatrix.sync.aligned.m8n8.x4.trans.shared.b16 {%0,%1,%2,%3}, [%4];"
                 : "=r"(r[0]), "=r"(r[1]), "=r"(r[2]), "=r"(r[3]) : "r"(addr));
}

__device__ __forceinline__ void cpa16(uint32_t dst, const void* src) {
    asm volatile("cp.async.cg.shared.global [%0], [%1], 16;" :: "r"(dst), "l"(src));
}

__device__ __forceinline__ uint32_t pk2(float x0, float x1) {
    __half2 t = __floats2half2_rn(x0, x1);
    return *(uint32_t*)&t;
}
__device__ __forceinline__ float hf(float v) {
    return __half2float(__float2half_rn(v));
}

// ---------------------------------------------------------------------------
// Embedding gather + fp16 split
// ---------------------------------------------------------------------------
__global__ __launch_bounds__(128) void embed_kernel(const int* __restrict__ src,
                                                    const float* __restrict__ emb,
                                                    float* __restrict__ x,
                                                    f16* __restrict__ xhi,
                                                    f16* __restrict__ xlo) {
    int row = blockIdx.x;
    int tok = src[row];
    float4 v = ((const float4*)(emb + (size_t)tok * DD))[threadIdx.x];
    ((float4*)(x + (size_t)row * DD))[threadIdx.x] = v;
    float h0 = hf(v.x), h1 = hf(v.y), h2 = hf(v.z), h3 = hf(v.w);
    uint32_t* H = (uint32_t*)(xhi + (size_t)row * DD);
    uint32_t* L = (uint32_t*)(xlo + (size_t)row * DD);
    H[2 * threadIdx.x]     = pk2(h0, h1);
    H[2 * threadIdx.x + 1] = pk2(h2, h3);
    L[2 * threadIdx.x]     = pk2(v.x - h0, v.y - h1);
    L[2 * threadIdx.x + 1] = pk2(v.z - h2, v.w - h3);
}

// ---------------------------------------------------------------------------
// Batched transpose + fp16 convert (hi only)
// ---------------------------------------------------------------------------
__global__ __launch_bounds__(256) void transpose_cvt_kernel(
    const float* __restrict__ W, f16* __restrict__ WThi,
    int K, int N, size_t src_ls, size_t dst_ls) {
    __shared__ float t[32][33];
    const float* Wl = W + (size_t)blockIdx.z * src_ls;
    f16* Hl = WThi + (size_t)blockIdx.z * dst_ls;
    int n0 = blockIdx.x * 32, k0 = blockIdx.y * 32;
    int c = threadIdx.x & 31, r = threadIdx.x >> 5;
#pragma unroll
    for (int i = 0; i < 4; i++)
        t[r + i * 8][c] = Wl[(size_t)(k0 + r + i * 8) * N + n0 + c];
    __syncthreads();
#pragma unroll
    for (int i = 0; i < 4; i++) {
        float x = t[c][r + i * 8];
        Hl[(size_t)(n0 + r + i * 8) * K + k0 + c] = __float2half_rn(x);
    }
}

__global__ __launch_bounds__(256) void pack_bias_kernel(const float* __restrict__ bq,
                                                        const float* __restrict__ bk,
                                                        const float* __restrict__ bv,
                                                        float* __restrict__ dst) {
    int i = blockIdx.x * 256 + threadIdx.x;
    if (i >= LL * TD) return;
    int l = i / TD, r = i % TD;
    int sel = r / DD, c = r % DD;
    const float* s = sel == 0 ? bq : (sel == 1 ? bk : bv);
    dst[i] = s[l * DD + c];
}

// ---------------------------------------------------------------------------
// Warp-MMA fp16 GEMM: D = (A_hi + A_lo) * B_hi  (2 MMAs). R12-proven.
// ---------------------------------------------------------------------------
#define GP_B   80
#define GTILE_B (128 * GP_B)
#define GSTAGE_B (3 * GTILE_B)
#define GSMEM   (2 * GSTAGE_B)    // 61440

__global__ __launch_bounds__(256, 2) void gemm_wm_kernel(
    const f16* __restrict__ Ahi, const f16* __restrict__ Alo,
    const f16* __restrict__ Bhi,
    const float* __restrict__ bias, float* __restrict__ C,
    f16* __restrict__ Chi, f16* __restrict__ Clo,
    int M, int N, int K, int relu, int mode) {
    extern __shared__ char sm[];
    const uint32_t sbase = smem_u32(sm);

    const int tid = threadIdx.x;
    const int lane = tid & 31;
    const int wid = tid >> 5;
    const int warp_m = wid >> 2;
    const int warp_n = wid & 3;
    const int g = lane >> 2;
    const int tig = lane & 3;

    const int bm = blockIdx.y * 128;
    const int bn = blockIdx.x * 128;

    const f16* srcs[3] = {
        Ahi + (size_t)bm * K, Alo + (size_t)bm * K, Bhi + (size_t)bn * K };

    float acc[4][4][4];
#pragma unroll
    for (int mt = 0; mt < 4; mt++)
#pragma unroll
        for (int nt = 0; nt < 4; nt++)
#pragma unroll
            for (int e = 0; e < 4; e++) acc[mt][nt][e] = 0.f;

    const int NIT = K >> 5;

    auto load_stage = [&](int s, int it) {
        const uint32_t stage = sbase + (uint32_t)s * GSTAGE_B;
#pragma unroll
        for (int t = 0; t < 3; t++) {
#pragma unroll
            for (int i = 0; i < 2; i++) {
                int idx = i * 256 + tid;
                int r = idx >> 2;
                int c8 = idx & 3;
                const void* src = (const char*)(srcs[t] + (size_t)r * K + it * 32) + c8 * 16;
                uint32_t dst = stage + (uint32_t)t * GTILE_B + (uint32_t)r * GP_B + c8 * 16;
                cpa16(dst, src);
            }
        }
        asm volatile("cp.async.commit_group;" ::: "memory");
    };

    load_stage(0, 0);

    for (int it = 0; it < NIT; it++) {
        const int buf = it & 1;
        if (it + 1 < NIT) {
            load_stage(buf ^ 1, it + 1);
            asm volatile("cp.async.wait_group 1;" ::: "memory");
        } else {
            asm volatile("cp.async.wait_group 0;" ::: "memory");
        }
        __syncthreads();

        const char* A0 = sm + buf * GSTAGE_B;
        const char* A1 = A0 + GTILE_B;
        const char* B0 = A0 + 2 * GTILE_B;

#pragma unroll
        for (int ks = 0; ks < 2; ks++) {
            const int kb = ks * 32 + tig * 4;
            uint32_t bh[4][2];
#pragma unroll
            for (int nt = 0; nt < 4; nt++) {
                int off = (warp_n * 32 + nt * 8 + g) * GP_B + kb;
                bh[nt][0] = *(const uint32_t*)(B0 + off);
                bh[nt][1] = *(const uint32_t*)(B0 + off + 16);
            }
#pragma unroll
            for (int mt = 0; mt < 4; mt++) {
                uint32_t ah[4], al[4];
                int off = (warp_m * 64 + mt * 16 + g) * GP_B + kb;
                ah[0] = *(const uint32_t*)(A0 + off);
                ah[1] = *(const uint32_t*)(A0 + off + 8 * GP_B);
                ah[2] = *(const uint32_t*)(A0 + off + 16);
                ah[3] = *(const uint32_t*)(A0 + off + 8 * GP_B + 16);
                al[0] = *(const uint32_t*)(A1 + off);
                al[1] = *(const uint32_t*)(A1 + off + 8 * GP_B);
                al[2] = *(const uint32_t*)(A1 + off + 16);
                al[3] = *(const uint32_t*)(A1 + off + 8 * GP_B + 16);
#pragma unroll
                for (int nt = 0; nt < 4; nt++) {
                    mma16816(acc[mt][nt], ah, bh[nt]);
                    mma16816(acc[mt][nt], al, bh[nt]);
                }
            }
        }
        __syncthreads();
    }

#pragma unroll
    for (int mt = 0; mt < 4; mt++) {
        int row0 = bm + warp_m * 64 + mt * 16 + g;
#pragma unroll
        for (int nt = 0; nt < 4; nt++) {
            int col = bn + warp_n * 32 + nt * 8 + 2 * tig;
            float bx = bias[col], by = bias[col + 1];
            float v00 = acc[mt][nt][0] + bx, v01 = acc[mt][nt][1] + by;
            float v10 = acc[mt][nt][2] + bx, v11 = acc[mt][nt][3] + by;
            if (relu) {
                v00 = fmaxf(v00, 0.f); v01 = fmaxf(v01, 0.f);
                v10 = fmaxf(v10, 0.f); v11 = fmaxf(v11, 0.f);
            }
            if (mode == 0) {
                *(float2*)&C[(size_t)row0 * N + col] = make_float2(v00, v01);
                *(float2*)&C[(size_t)(row0 + 8) * N + col] = make_float2(v10, v11);
            } else {
                float h00 = hf(v00), h01 = hf(v01), h10 = hf(v10), h11 = hf(v11);
                *(uint32_t*)&Chi[(size_t)row0 * N + col] = pk2(h00, h01);
                *(uint32_t*)&Chi[(size_t)(row0 + 8) * N + col] = pk2(h10, h11);
                *(uint32_t*)&Clo[(size_t)row0 * N + col] = pk2(v00 - h00, v01 - h01);
                *(uint32_t*)&Clo[(size_t)(row0 + 8) * N + col] = pk2(v10 - h10, v11 - h11);
            }
        }
    }
}

// ---------------------------------------------------------------------------
// Tensor-core flash attention — 2-term fp16:
//   S = (Q_hi+Q_lo)·K_hi,  O = (P_hi+P_lo)·V_hi.
// K_lo / V_lo tiles eliminated (smem 55,296B, halved KV loads).
// Grid (bh, qtile), qb reversed = global longest-first (R11 win).
// ---------------------------------------------------------------------------
#define AP 72
#define ATT_SMEM ((2*128 + 2*64) * AP * 2)   // 55296 bytes

__global__ __launch_bounds__(256, 2) void attn_tc_kernel(
    const f16* __restrict__ qkvhi, const f16* __restrict__ qkvlo,
    f16* __restrict__ thi, f16* __restrict__ tlo) {
    extern __shared__ f16 asmem[];
    const uint32_t sb = smem_u32(asmem);
    f16* Qh = asmem;
    f16* Ql = Qh + 128 * AP;
    f16* Kh = Ql + 128 * AP;
    f16* Vh = Kh + 64 * AP;
    const uint32_t vhb = sb + (uint32_t)(320 * AP) * 2;

    const int tid = threadIdx.x;
    const int lane = tid & 31;
    const int wid = tid >> 5;
    const int g = lane >> 2;
    const int tig = lane & 3;

    const int qb = gridDim.y - 1 - blockIdx.y;
    const int bh = blockIdx.x;
    const int b = bh / HH;
    const int h = bh % HH;
    const int q0 = qb * 128;
    const size_t hoff = (size_t)h * DHH;

#pragma unroll
    for (int i = 0; i < 4; i++) {
        int idx = i * 256 + tid;
        int row = idx >> 3;
        int cb = (idx & 7) * 8;
        size_t go = (size_t)(b * SS + q0 + row) * TD + hoff + cb;
        *(uint4*)&Qh[row * AP + cb] = *(const uint4*)&qkvhi[go];
        *(uint4*)&Ql[row * AP + cb] = *(const uint4*)&qkvlo[go];
    }

    float oacc[8][4];
#pragma unroll
    for (int vn = 0; vn < 8; vn++)
#pragma unroll
        for (int e = 0; e < 4; e++) oacc[vn][e] = 0.f;
    float mrow[2] = {-1e30f, -1e30f};
    float lrow[2] = {0.f, 0.f};

    const int nkt = 2 * qb + 2;
    const int wr0 = q0 + wid * 16;
    const float scale = 0.125f;

    const int l7 = lane & 7;
    const int grp = lane >> 3;
    const uint32_t vrow_off = (uint32_t)((l7 + (grp & 1) * 8) * AP) * 2;
    const uint32_t vcol_off = (uint32_t)((grp >> 1) * 8) * 2;

    for (int kt = 0; kt < nkt; kt++) {
        const int k0 = kt * 64;
        __syncthreads();
#pragma unroll
        for (int i = 0; i < 2; i++) {
            int idx = i * 256 + tid;
            int row = idx >> 3;
            int cb = (idx & 7) * 8;
            size_t go = (size_t)(b * SS + k0 + row) * TD + hoff + cb;
            *(uint4*)&Kh[row * AP + cb] = *(const uint4*)&qkvhi[go + DD];
            *(uint4*)&Vh[row * AP + cb] = *(const uint4*)&qkvhi[go + 2 * DD];
        }
        __syncthreads();

        if (k0 <= wr0 + 15) {
            float sacc[8][4];
#pragma unroll
            for (int nt = 0; nt < 8; nt++)
#pragma unroll
                for (int e = 0; e < 4; e++) sacc[nt][e] = 0.f;

#pragma unroll
            for (int kc = 0; kc < 4; kc++) {
                uint32_t ah[4], al[4];
                int aoff = (wid * 16 + g) * AP + kc * 16 + 2 * tig;
                ah[0] = *(const uint32_t*)&Qh[aoff];
                ah[1] = *(const uint32_t*)&Qh[aoff + 8 * AP];
                ah[2] = *(const uint32_t*)&Qh[aoff + 8];
                ah[3] = *(const uint32_t*)&Qh[aoff + 8 * AP + 8];
                al[0] = *(const uint32_t*)&Ql[aoff];
                al[1] = *(const uint32_t*)&Ql[aoff + 8 * AP];
                al[2] = *(const uint32_t*)&Ql[aoff + 8];
                al[3] = *(const uint32_t*)&Ql[aoff + 8 * AP + 8];
#pragma unroll
                for (int nt = 0; nt < 8; nt++) {
                    int boff = (nt * 8 + g) * AP + kc * 16 + 2 * tig;
                    uint32_t bh2[2];
                    bh2[0] = *(const uint32_t*)&Kh[boff];
                    bh2[1] = *(const uint32_t*)&Kh[boff + 8];
                    mma16816(sacc[nt], ah, bh2);
                    mma16816(sacc[nt], al, bh2);
                }
            }

            const bool needmask = (k0 + 63) > wr0;
#pragma unroll
            for (int nt = 0; nt < 8; nt++)
#pragma unroll
                for (int e = 0; e < 4; e++) {
                    float sv = sacc[nt][e] * scale;
                    if (needmask) {
                        int row = wr0 + g + ((e >> 1) << 3);
                        int col = k0 + nt * 8 + 2 * tig + (e & 1);
                        if (col > row) sv = -1e30f;
                    }
                    sacc[nt][e] = sv;
                }

#pragma unroll
            for (int rr = 0; rr < 2; rr++) {
                float mx = -1e30f;
#pragma unroll
                for (int nt = 0; nt < 8; nt++)
                    mx = fmaxf(mx, fmaxf(sacc[nt][2 * rr], sacc[nt][2 * rr + 1]));
                mx = fmaxf(mx, __shfl_xor_sync(0xffffffffu, mx, 1));
                mx = fmaxf(mx, __shfl_xor_sync(0xffffffffu, mx, 2));
                float mnew = fmaxf(mrow[rr], mx);
                float alpha = __expf(mrow[rr] - mnew);
                float rs = 0.f;
#pragma unroll
                for (int nt = 0; nt < 8; nt++) {
                    float p0 = __expf(sacc[nt][2 * rr] - mnew);
                    float p1 = __expf(sacc[nt][2 * rr + 1] - mnew);
                    sacc[nt][2 * rr] = p0;
                    sacc[nt][2 * rr + 1] = p1;
                    rs += p0 + p1;
                }
                rs += __shfl_xor_sync(0xffffffffu, rs, 1);
                rs += __shfl_xor_sync(0xffffffffu, rs, 2);
                lrow[rr] = lrow[rr] * alpha + rs;
                mrow[rr] = mnew;
#pragma unroll
                for (int vn = 0; vn < 8; vn++) {
                    oacc[vn][2 * rr] *= alpha;
                    oacc[vn][2 * rr + 1] *= alpha;
                }
            }

#pragma unroll
            for (int kc2 = 0; kc2 < 4; kc2++) {
                float* t0 = sacc[2 * kc2];
                float* t1 = sacc[2 * kc2 + 1];
                float h00 = hf(t0[0]), h01 = hf(t0[1]), h02 = hf(t0[2]), h03 = hf(t0[3]);
                float h10 = hf(t1[0]), h11 = hf(t1[1]), h12 = hf(t1[2]), h13 = hf(t1[3]);
                uint32_t ph[4], pl[4];
                ph[0] = pk2(h00, h01); ph[1] = pk2(h02, h03);
                ph[2] = pk2(h10, h11); ph[3] = pk2(h12, h13);
                pl[0] = pk2(t0[0] - h00, t0[1] - h01);
                pl[1] = pk2(t0[2] - h02, t0[3] - h03);
                pl[2] = pk2(t1[0] - h10, t1[1] - h11);
                pl[3] = pk2(t1[2] - h12, t1[3] - h13);

                const uint32_t kbase = (uint32_t)(kc2 * 16 * AP) * 2 + vrow_off + vcol_off;
#pragma unroll
                for (int vnp = 0; vnp < 4; vnp++) {
                    uint32_t vaddr = kbase + (uint32_t)(vnp * 16) * 2;
                    uint32_t vh4[4];
                    ldm_x4t(vh4, vhb + vaddr);
                    uint32_t bh0[2] = {vh4[0], vh4[1]}, bh1[2] = {vh4[2], vh4[3]};
                    mma16816(oacc[2 * vnp], ph, bh0);
                    mma16816(oacc[2 * vnp], pl, bh0);
                    mma16816(oacc[2 * vnp + 1], ph, bh1);
                    mma16816(oacc[2 * vnp + 1], pl, bh1);
                }
            }
        }
    }

#pragma unroll
    for (int rr = 0; rr < 2; rr++) {
        float inv = 1.f / lrow[rr];
        int r = wr0 + g + rr * 8;
        size_t rb = (size_t)(b * SS + r) * DD + hoff;
#pragma unroll
        for (int vn = 0; vn < 8; vn++) {
            float o0 = oacc[vn][2 * rr] * inv;
            float o1 = oacc[vn][2 * rr + 1] * inv;
            float h0 = hf(o0), h1 = hf(o1);
            int col = vn * 8 + 2 * tig;
            *(uint32_t*)&thi[rb + col] = pk2(h0, h1);
            *(uint32_t*)&tlo[rb + col] = pk2(o0 - h0, o1 - h1);
        }
    }
}

// ---------------------------------------------------------------------------
// Residual add + LayerNorm + fp16 split
// ---------------------------------------------------------------------------
__global__ __launch_bounds__(256) void add_ln_kernel(float* __restrict__ x,
                                                     const float* __restrict__ y,
                                                     const float* __restrict__ g,
                                                     const float* __restrict__ bb,
                                                     f16* __restrict__ xhi,
                                                     f16* __restrict__ xlo) {
    const int row = blockIdx.x;
    const int tid = threadIdx.x;
    float2 xv = *(const float2*)&x[(size_t)row * DD + tid * 2];
    float2 yv = *(const float2*)&y[(size_t)row * DD + tid * 2];
    float a0 = xv.x + yv.x;
    float a1 = xv.y + yv.y;

    float s = a0 + a1;
    float ss = a0 * a0 + a1 * a1;
#pragma unroll
    for (int off = 16; off >= 1; off >>= 1) {
        s += __shfl_xor_sync(0xffffffffu, s, off);
        ss += __shfl_xor_sync(0xffffffffu, ss, off);
    }
    __shared__ float sbuf[8], ssbuf[8];
    if ((tid & 31) == 0) { sbuf[tid >> 5] = s; ssbuf[tid >> 5] = ss; }
    __syncthreads();
    float ts = 0.f, tss = 0.f;
#pragma unroll
    for (int i = 0; i < 8; i++) { ts += sbuf[i]; tss += ssbuf[i]; }
    float mean = ts * (1.f / DD);
    float var = tss * (1.f / DD) - mean * mean;
    float rstd = rsqrtf(var + 1e-5f);

    int col = tid * 2;
    float2 go = *(const float2*)&g[col];
    float2 bo = *(const float2*)&bb[col];
    float o0 = (a0 - mean) * rstd * go.x + bo.x;
    float o1 = (a1 - mean) * rstd * go.y + bo.y;
    *(float2*)&x[(size_t)row * DD + col] = make_float2(o0, o1);
    float h0 = hf(o0), h1 = hf(o1);
    *(uint32_t*)&xhi[(size_t)row * DD + col] = pk2(h0, h1);
    *(uint32_t*)&xlo[(size_t)row * DD + col] = pk2(o0 - h0, o1 - h1);
}

// ---------------------------------------------------------------------------
// Host driver
// ---------------------------------------------------------------------------
extern "C" void kernel_launch(void* const* d_in, const int* in_sizes, int n_in,
                              void* d_out, int out_size) {
    const int* source = (const int*)d_in[0];
    const float* emb = (const float*)d_in[1];
    const float* ln_g = (const float*)d_in[2];
    const float* ln_b = (const float*)d_in[3];
    const float* wq = (const float*)d_in[4];
    const float* bq = (const float*)d_in[5];
    const float* wk = (const float*)d_in[6];
    const float* bk = (const float*)d_in[7];
    const float* wv = (const float*)d_in[8];
    const float* bv = (const float*)d_in[9];
    const float* wo = (const float*)d_in[10];
    const float* bo = (const float*)d_in[11];
    const float* w1 = (const float*)d_in[12];
    const float* b1 = (const float*)d_in[13];
    const float* w2 = (const float*)d_in[14];
    const float* b2 = (const float*)d_in[15];

    float* x = (float*)d_out;

    float *tmp, *bqkv;
    f16 *xhi, *xlo, *qkvhi, *qkvlo, *thi, *tlo, *hhi, *hlo;
    f16 *wqkvhi, *wohi, *w1hi, *w2hi;
    cudaGetSymbolAddress((void**)&tmp, g_tmp);
    cudaGetSymbolAddress((void**)&bqkv, g_bqkv);
    cudaGetSymbolAddress((void**)&xhi, g_xhi);
    cudaGetSymbolAddress((void**)&xlo, g_xlo);
    cudaGetSymbolAddress((void**)&qkvhi, g_qkvhi);
    cudaGetSymbolAddress((void**)&qkvlo, g_qkvlo);
    cudaGetSymbolAddress((void**)&thi, g_thi);
    cudaGetSymbolAddress((void**)&tlo, g_tlo);
    cudaGetSymbolAddress((void**)&hhi, g_hhi);
    cudaGetSymbolAddress((void**)&hlo, g_hlo);
    cudaGetSymbolAddress((void**)&wqkvhi, g_wqkvhi);
    cudaGetSymbolAddress((void**)&wohi, g_wohi);
    cudaGetSymbolAddress((void**)&w1hi, g_w1hi);
    cudaGetSymbolAddress((void**)&w2hi, g_w2hi);

    cudaFuncSetAttribute(attn_tc_kernel, cudaFuncAttributeMaxDynamicSharedMemorySize,
                         ATT_SMEM);
    cudaFuncSetAttribute(gemm_wm_kernel, cudaFuncAttributeMaxDynamicSharedMemorySize,
                         GSMEM);

    embed_kernel<<<NROWS, 128>>>(source, emb, x, xhi, xlo);
    {
        dim3 gD(DD / 32, DD / 32, LL);
        transpose_cvt_kernel<<<gD, 256>>>(wq, wqkvhi, DD, DD,
                                          (size_t)DD * DD, (size_t)TD * DD);
        transpose_cvt_kernel<<<gD, 256>>>(wk, wqkvhi + (size_t)DD * DD, DD, DD,
                                          (size_t)DD * DD, (size_t)TD * DD);
        transpose_cvt_kernel<<<gD, 256>>>(wv, wqkvhi + (size_t)2 * DD * DD, DD, DD,
                                          (size_t)DD * DD, (size_t)TD * DD);
        transpose_cvt_kernel<<<gD, 256>>>(wo, wohi, DD, DD,
                                          (size_t)DD * DD, (size_t)DD * DD);
        dim3 g1(FF / 32, DD / 32, LL);
        transpose_cvt_kernel<<<g1, 256>>>(w1, w1hi, DD, FF,
                                          (size_t)DD * FF, (size_t)FF * DD);
        dim3 g2(DD / 32, FF / 32, LL);
        transpose_cvt_kernel<<<g2, 256>>>(w2, w2hi, FF, DD,
                                          (size_t)FF * DD, (size_t)DD * FF);
        pack_bias_kernel<<<(LL * TD + 255) / 256, 256>>>(bq, bk, bv, bqkv);
    }

    dim3 gA(BB * HH, SS / 128);

    auto gemm = [&](const f16* ah, const f16* al, const f16* bhw,
                    const float* bias, float* C, f16* Ch, f16* Cl,
                    int M, int N, int K, int relu, int mode) {
        dim3 g(N / 128, M / 128);
        gemm_wm_kernel<<<g, 256, GSMEM>>>(ah, al, bhw, bias, C, Ch, Cl,
                                          M, N, K, relu, mode);
    };

    for (int l = 0; l < LL; l++) {
        const f16* Wqkvh = wqkvhi + (size_t)l * TD * DD;
        const f16* Woh = wohi + (size_t)l * DD * DD;
        const f16* W1h = w1hi + (size_t)l * FF * DD;
        const f16* W2h = w2hi + (size_t)l * DD * FF;
        const float* Bqkv = bqkv + (size_t)l * TD;
        const float* Bo = bo + (size_t)l * DD;
        const float* B1 = b1 + (size_t)l * FF;
        const float* B2 = b2 + (size_t)l * DD;

        gemm(xhi, xlo, Wqkvh, Bqkv, nullptr, qkvhi, qkvlo, NROWS, TD, DD, 0, 1);

        attn_tc_kernel<<<gA, 256, ATT_SMEM>>>(qkvhi, qkvlo, thi, tlo);

        gemm(thi, tlo, Woh, Bo, tmp, nullptr, nullptr, NROWS, DD, DD, 0, 0);
        add_ln_kernel<<<NROWS, 256>>>(x, tmp, ln_g, ln_b, xhi, xlo);

        gemm(xhi, xlo, W1h, B1, nullptr, hhi, hlo, NROWS, FF, DD, 1, 1);
        gemm(hhi, hlo, W2h, B2, tmp, nullptr, nullptr, NROWS, DD, FF, 1, 0);
        add_ln_kernel<<<NROWS, 256>>>(x, tmp, ln_g, ln_b, xhi, xlo);
    }
}

// round 14
// speedup vs baseline: 2.0282x; 1.3088x over previous
#include <cuda_runtime.h>
#include <cuda_fp16.h>
#include <math.h>
#include <stdint.h>

#define BB 4
#define SS 2048
#define DD 512
#define HH 8
#define DHH 64
#define FF 2048
#define LL 6
#define NROWS (BB*SS)   // 8192
#define TD (3*DD)       // 1536 packed qkv width

typedef __half f16;

// ---------------------------------------------------------------------------
// Scratch
// ---------------------------------------------------------------------------
__device__ float g_tmp[NROWS * DD];
__device__ f16 g_xhi[NROWS * DD];
__device__ f16 g_qkvhi[NROWS * TD];
__device__ f16 g_qkvlo[NROWS * TD];
__device__ f16 g_thi[NROWS * DD];
__device__ f16 g_hhi[NROWS * FF];
__device__ f16 g_wqkvhi[LL * TD * DD];
__device__ f16 g_wohi[LL * DD * DD];
__device__ f16 g_w1hi[LL * FF * DD];
__device__ f16 g_w2hi[LL * DD * FF];
__device__ float g_bqkv[LL * TD];

// ---------------------------------------------------------------------------
// helpers
// ---------------------------------------------------------------------------
__device__ __forceinline__ uint32_t smem_u32(const void* p) {
    uint32_t a;
    asm("{ .reg .u64 t; cvta.to.shared.u64 t, %1; cvt.u32.u64 %0, t; }"
        : "=r"(a) : "l"(p));
    return a;
}

__device__ __forceinline__ void mma16816(float* c, const uint32_t* a, const uint32_t* b) {
    asm volatile(
        "mma.sync.aligned.m16n8k16.row.col.f32.f16.f16.f32 "
        "{%0,%1,%2,%3}, {%4,%5,%6,%7}, {%8,%9}, {%0,%1,%2,%3};"
        : "+f"(c[0]), "+f"(c[1]), "+f"(c[2]), "+f"(c[3])
        : "r"(a[0]), "r"(a[1]), "r"(a[2]), "r"(a[3]), "r"(b[0]), "r"(b[1]));
}

__device__ __forceinline__ void ldm_x4t(uint32_t* r, uint32_t addr) {
    asm volatile("ldmatrix.sync.aligned.m8n8.x4.trans.shared.b16 {%0,%1,%2,%3}, [%4];"
                 : "=r"(r[0]), "=r"(r[1]), "=r"(r[2]), "=r"(r[3]) : "r"(addr));
}

__device__ __forceinline__ void cpa16(uint32_t dst, const void* src) {
    asm volatile("cp.async.cg.shared.global [%0], [%1], 16;" :: "r"(dst), "l"(src));
}

__device__ __forceinline__ uint32_t pk2(float x0, float x1) {
    __half2 t = __floats2half2_rn(x0, x1);
    return *(uint32_t*)&t;
}
__device__ __forceinline__ float hf(float v) {
    return __half2float(__float2half_rn(v));
}

// ---------------------------------------------------------------------------
// Embedding gather + fp16 hi
// ---------------------------------------------------------------------------
__global__ __launch_bounds__(128) void embed_kernel(const int* __restrict__ src,
                                                    const float* __restrict__ emb,
                                                    float* __restrict__ x,
                                                    f16* __restrict__ xhi) {
    int row = blockIdx.x;
    int tok = src[row];
    float4 v = ((const float4*)(emb + (size_t)tok * DD))[threadIdx.x];
    ((float4*)(x + (size_t)row * DD))[threadIdx.x] = v;
    uint32_t* H = (uint32_t*)(xhi + (size_t)row * DD);
    H[2 * threadIdx.x]     = pk2(v.x, v.y);
    H[2 * threadIdx.x + 1] = pk2(v.z, v.w);
}

// ---------------------------------------------------------------------------
// Batched transpose + fp16 convert (hi only)
// ---------------------------------------------------------------------------
__global__ __launch_bounds__(256) void transpose_cvt_kernel(
    const float* __restrict__ W, f16* __restrict__ WThi,
    int K, int N, size_t src_ls, size_t dst_ls) {
    __shared__ float t[32][33];
    const float* Wl = W + (size_t)blockIdx.z * src_ls;
    f16* Hl = WThi + (size_t)blockIdx.z * dst_ls;
    int n0 = blockIdx.x * 32, k0 = blockIdx.y * 32;
    int c = threadIdx.x & 31, r = threadIdx.x >> 5;
#pragma unroll
    for (int i = 0; i < 4; i++)
        t[r + i * 8][c] = Wl[(size_t)(k0 + r + i * 8) * N + n0 + c];
    __syncthreads();
#pragma unroll
    for (int i = 0; i < 4; i++) {
        float x = t[c][r + i * 8];
        Hl[(size_t)(n0 + r + i * 8) * K + k0 + c] = __float2half_rn(x);
    }
}

__global__ __launch_bounds__(256) void pack_bias_kernel(const float* __restrict__ bq,
                                                        const float* __restrict__ bk,
                                                        const float* __restrict__ bv,
                                                        float* __restrict__ dst) {
    int i = blockIdx.x * 256 + threadIdx.x;
    if (i >= LL * TD) return;
    int l = i / TD, r = i % TD;
    int sel = r / DD, c = r % DD;
    const float* s = sel == 0 ? bq : (sel == 1 ? bk : bv);
    dst[i] = s[l * DD + c];
}

// ---------------------------------------------------------------------------
// Warp-MMA fp16 GEMM: D = A_hi * B_hi  (1 MMA per tile product).
// 2 operand tiles per stage. R8 two-sync pipeline.
// mode 0: fp32 C; mode 1: split (Chi,Clo); mode 2: Chi only.
// ---------------------------------------------------------------------------
#define GP_B   80
#define GTILE_B (128 * GP_B)
#define GSTAGE_B (2 * GTILE_B)
#define GSMEM   (2 * GSTAGE_B)    // 40960

__global__ __launch_bounds__(256, 2) void gemm_wm_kernel(
    const f16* __restrict__ Ahi, const f16* __restrict__ Bhi,
    const float* __restrict__ bias, float* __restrict__ C,
    f16* __restrict__ Chi, f16* __restrict__ Clo,
    int M, int N, int K, int relu, int mode) {
    extern __shared__ char sm[];
    const uint32_t sbase = smem_u32(sm);

    const int tid = threadIdx.x;
    const int lane = tid & 31;
    const int wid = tid >> 5;
    const int warp_m = wid >> 2;
    const int warp_n = wid & 3;
    const int g = lane >> 2;
    const int tig = lane & 3;

    const int bm = blockIdx.y * 128;
    const int bn = blockIdx.x * 128;

    const f16* srcs[2] = { Ahi + (size_t)bm * K, Bhi + (size_t)bn * K };

    float acc[4][4][4];
#pragma unroll
    for (int mt = 0; mt < 4; mt++)
#pragma unroll
        for (int nt = 0; nt < 4; nt++)
#pragma unroll
            for (int e = 0; e < 4; e++) acc[mt][nt][e] = 0.f;

    const int NIT = K >> 5;

    auto load_stage = [&](int s, int it) {
        const uint32_t stage = sbase + (uint32_t)s * GSTAGE_B;
#pragma unroll
        for (int t = 0; t < 2; t++) {
#pragma unroll
            for (int i = 0; i < 2; i++) {
                int idx = i * 256 + tid;
                int r = idx >> 2;
                int c8 = idx & 3;
                const void* src = (const char*)(srcs[t] + (size_t)r * K + it * 32) + c8 * 16;
                uint32_t dst = stage + (uint32_t)t * GTILE_B + (uint32_t)r * GP_B + c8 * 16;
                cpa16(dst, src);
            }
        }
        asm volatile("cp.async.commit_group;" ::: "memory");
    };

    load_stage(0, 0);

    for (int it = 0; it < NIT; it++) {
        const int buf = it & 1;
        if (it + 1 < NIT) {
            load_stage(buf ^ 1, it + 1);
            asm volatile("cp.async.wait_group 1;" ::: "memory");
        } else {
            asm volatile("cp.async.wait_group 0;" ::: "memory");
        }
        __syncthreads();

        const char* A0 = sm + buf * GSTAGE_B;
        const char* B0 = A0 + GTILE_B;

#pragma unroll
        for (int ks = 0; ks < 2; ks++) {
            const int kb = ks * 32 + tig * 4;
            uint32_t bh[4][2];
#pragma unroll
            for (int nt = 0; nt < 4; nt++) {
                int off = (warp_n * 32 + nt * 8 + g) * GP_B + kb;
                bh[nt][0] = *(const uint32_t*)(B0 + off);
                bh[nt][1] = *(const uint32_t*)(B0 + off + 16);
            }
#pragma unroll
            for (int mt = 0; mt < 4; mt++) {
                uint32_t ah[4];
                int off = (warp_m * 64 + mt * 16 + g) * GP_B + kb;
                ah[0] = *(const uint32_t*)(A0 + off);
                ah[1] = *(const uint32_t*)(A0 + off + 8 * GP_B);
                ah[2] = *(const uint32_t*)(A0 + off + 16);
                ah[3] = *(const uint32_t*)(A0 + off + 8 * GP_B + 16);
#pragma unroll
                for (int nt = 0; nt < 4; nt++)
                    mma16816(acc[mt][nt], ah, bh[nt]);
            }
        }
        __syncthreads();
    }

#pragma unroll
    for (int mt = 0; mt < 4; mt++) {
        int row0 = bm + warp_m * 64 + mt * 16 + g;
#pragma unroll
        for (int nt = 0; nt < 4; nt++) {
            int col = bn + warp_n * 32 + nt * 8 + 2 * tig;
            float bx = bias[col], by = bias[col + 1];
            float v00 = acc[mt][nt][0] + bx, v01 = acc[mt][nt][1] + by;
            float v10 = acc[mt][nt][2] + bx, v11 = acc[mt][nt][3] + by;
            if (relu) {
                v00 = fmaxf(v00, 0.f); v01 = fmaxf(v01, 0.f);
                v10 = fmaxf(v10, 0.f); v11 = fmaxf(v11, 0.f);
            }
            if (mode == 0) {
                *(float2*)&C[(size_t)row0 * N + col] = make_float2(v00, v01);
                *(float2*)&C[(size_t)(row0 + 8) * N + col] = make_float2(v10, v11);
            } else if (mode == 2) {
                *(uint32_t*)&Chi[(size_t)row0 * N + col] = pk2(v00, v01);
                *(uint32_t*)&Chi[(size_t)(row0 + 8) * N + col] = pk2(v10, v11);
            } else {
                float h00 = hf(v00), h01 = hf(v01), h10 = hf(v10), h11 = hf(v11);
                *(uint32_t*)&Chi[(size_t)row0 * N + col] = pk2(h00, h01);
                *(uint32_t*)&Chi[(size_t)(row0 + 8) * N + col] = pk2(h10, h11);
                *(uint32_t*)&Clo[(size_t)row0 * N + col] = pk2(v00 - h00, v01 - h01);
                *(uint32_t*)&Clo[(size_t)(row0 + 8) * N + col] = pk2(v10 - h10, v11 - h11);
            }
        }
    }
}

// ---------------------------------------------------------------------------
// Tensor-core flash attention — R13-proven 2-term fp16:
//   S = (Q_hi+Q_lo)·K_hi,  O = (P_hi+P_lo)·V_hi.
// Epilogue writes thi only (proj GEMM is now 1-term).
// ---------------------------------------------------------------------------
#define AP 72
#define ATT_SMEM ((2*128 + 2*64) * AP * 2)   // 55296 bytes

__global__ __launch_bounds__(256, 2) void attn_tc_kernel(
    const f16* __restrict__ qkvhi, const f16* __restrict__ qkvlo,
    f16* __restrict__ thi) {
    extern __shared__ f16 asmem[];
    const uint32_t sb = smem_u32(asmem);
    f16* Qh = asmem;
    f16* Ql = Qh + 128 * AP;
    f16* Kh = Ql + 128 * AP;
    f16* Vh = Kh + 64 * AP;
    const uint32_t vhb = sb + (uint32_t)(320 * AP) * 2;

    const int tid = threadIdx.x;
    const int lane = tid & 31;
    const int wid = tid >> 5;
    const int g = lane >> 2;
    const int tig = lane & 3;

    const int qb = gridDim.y - 1 - blockIdx.y;
    const int bh = blockIdx.x;
    const int b = bh / HH;
    const int h = bh % HH;
    const int q0 = qb * 128;
    const size_t hoff = (size_t)h * DHH;

#pragma unroll
    for (int i = 0; i < 4; i++) {
        int idx = i * 256 + tid;
        int row = idx >> 3;
        int cb = (idx & 7) * 8;
        size_t go = (size_t)(b * SS + q0 + row) * TD + hoff + cb;
        *(uint4*)&Qh[row * AP + cb] = *(const uint4*)&qkvhi[go];
        *(uint4*)&Ql[row * AP + cb] = *(const uint4*)&qkvlo[go];
    }

    float oacc[8][4];
#pragma unroll
    for (int vn = 0; vn < 8; vn++)
#pragma unroll
        for (int e = 0; e < 4; e++) oacc[vn][e] = 0.f;
    float mrow[2] = {-1e30f, -1e30f};
    float lrow[2] = {0.f, 0.f};

    const int nkt = 2 * qb + 2;
    const int wr0 = q0 + wid * 16;
    const float scale = 0.125f;

    const int l7 = lane & 7;
    const int grp = lane >> 3;
    const uint32_t vrow_off = (uint32_t)((l7 + (grp & 1) * 8) * AP) * 2;
    const uint32_t vcol_off = (uint32_t)((grp >> 1) * 8) * 2;

    for (int kt = 0; kt < nkt; kt++) {
        const int k0 = kt * 64;
        __syncthreads();
#pragma unroll
        for (int i = 0; i < 2; i++) {
            int idx = i * 256 + tid;
            int row = idx >> 3;
            int cb = (idx & 7) * 8;
            size_t go = (size_t)(b * SS + k0 + row) * TD + hoff + cb;
            *(uint4*)&Kh[row * AP + cb] = *(const uint4*)&qkvhi[go + DD];
            *(uint4*)&Vh[row * AP + cb] = *(const uint4*)&qkvhi[go + 2 * DD];
        }
        __syncthreads();

        if (k0 <= wr0 + 15) {
            float sacc[8][4];
#pragma unroll
            for (int nt = 0; nt < 8; nt++)
#pragma unroll
                for (int e = 0; e < 4; e++) sacc[nt][e] = 0.f;

#pragma unroll
            for (int kc = 0; kc < 4; kc++) {
                uint32_t ah[4], al[4];
                int aoff = (wid * 16 + g) * AP + kc * 16 + 2 * tig;
                ah[0] = *(const uint32_t*)&Qh[aoff];
                ah[1] = *(const uint32_t*)&Qh[aoff + 8 * AP];
                ah[2] = *(const uint32_t*)&Qh[aoff + 8];
                ah[3] = *(const uint32_t*)&Qh[aoff + 8 * AP + 8];
                al[0] = *(const uint32_t*)&Ql[aoff];
                al[1] = *(const uint32_t*)&Ql[aoff + 8 * AP];
                al[2] = *(const uint32_t*)&Ql[aoff + 8];
                al[3] = *(const uint32_t*)&Ql[aoff + 8 * AP + 8];
#pragma unroll
                for (int nt = 0; nt < 8; nt++) {
                    int boff = (nt * 8 + g) * AP + kc * 16 + 2 * tig;
                    uint32_t bh2[2];
                    bh2[0] = *(const uint32_t*)&Kh[boff];
                    bh2[1] = *(const uint32_t*)&Kh[boff + 8];
                    mma16816(sacc[nt], ah, bh2);
                    mma16816(sacc[nt], al, bh2);
                }
            }

            const bool needmask = (k0 + 63) > wr0;
#pragma unroll
            for (int nt = 0; nt < 8; nt++)
#pragma unroll
                for (int e = 0; e < 4; e++) {
                    float sv = sacc[nt][e] * scale;
                    if (needmask) {
                        int row = wr0 + g + ((e >> 1) << 3);
                        int col = k0 + nt * 8 + 2 * tig + (e & 1);
                        if (col > row) sv = -1e30f;
                    }
                    sacc[nt][e] = sv;
                }

#pragma unroll
            for (int rr = 0; rr < 2; rr++) {
                float mx = -1e30f;
#pragma unroll
                for (int nt = 0; nt < 8; nt++)
                    mx = fmaxf(mx, fmaxf(sacc[nt][2 * rr], sacc[nt][2 * rr + 1]));
                mx = fmaxf(mx, __shfl_xor_sync(0xffffffffu, mx, 1));
                mx = fmaxf(mx, __shfl_xor_sync(0xffffffffu, mx, 2));
                float mnew = fmaxf(mrow[rr], mx);
                float alpha = __expf(mrow[rr] - mnew);
                float rs = 0.f;
#pragma unroll
                for (int nt = 0; nt < 8; nt++) {
                    float p0 = __expf(sacc[nt][2 * rr] - mnew);
                    float p1 = __expf(sacc[nt][2 * rr + 1] - mnew);
                    sacc[nt][2 * rr] = p0;
                    sacc[nt][2 * rr + 1] = p1;
                    rs += p0 + p1;
                }
                rs += __shfl_xor_sync(0xffffffffu, rs, 1);
                rs += __shfl_xor_sync(0xffffffffu, rs, 2);
                lrow[rr] = lrow[rr] * alpha + rs;
                mrow[rr] = mnew;
#pragma unroll
                for (int vn = 0; vn < 8; vn++) {
                    oacc[vn][2 * rr] *= alpha;
                    oacc[vn][2 * rr + 1] *= alpha;
                }
            }

#pragma unroll
            for (int kc2 = 0; kc2 < 4; kc2++) {
                float* t0 = sacc[2 * kc2];
                float* t1 = sacc[2 * kc2 + 1];
                float h00 = hf(t0[0]), h01 = hf(t0[1]), h02 = hf(t0[2]), h03 = hf(t0[3]);
                float h10 = hf(t1[0]), h11 = hf(t1[1]), h12 = hf(t1[2]), h13 = hf(t1[3]);
                uint32_t ph[4], pl[4];
                ph[0] = pk2(h00, h01); ph[1] = pk2(h02, h03);
                ph[2] = pk2(h10, h11); ph[3] = pk2(h12, h13);
                pl[0] = pk2(t0[0] - h00, t0[1] - h01);
                pl[1] = pk2(t0[2] - h02, t0[3] - h03);
                pl[2] = pk2(t1[0] - h10, t1[1] - h11);
                pl[3] = pk2(t1[2] - h12, t1[3] - h13);

                const uint32_t kbase = (uint32_t)(kc2 * 16 * AP) * 2 + vrow_off + vcol_off;
#pragma unroll
                for (int vnp = 0; vnp < 4; vnp++) {
                    uint32_t vaddr = kbase + (uint32_t)(vnp * 16) * 2;
                    uint32_t vh4[4];
                    ldm_x4t(vh4, vhb + vaddr);
                    uint32_t bh0[2] = {vh4[0], vh4[1]}, bh1[2] = {vh4[2], vh4[3]};
                    mma16816(oacc[2 * vnp], ph, bh0);
                    mma16816(oacc[2 * vnp], pl, bh0);
                    mma16816(oacc[2 * vnp + 1], ph, bh1);
                    mma16816(oacc[2 * vnp + 1], pl, bh1);
                }
            }
        }
    }

#pragma unroll
    for (int rr = 0; rr < 2; rr++) {
        float inv = 1.f / lrow[rr];
        int r = wr0 + g + rr * 8;
        size_t rb = (size_t)(b * SS + r) * DD + hoff;
#pragma unroll
        for (int vn = 0; vn < 8; vn++) {
            float o0 = oacc[vn][2 * rr] * inv;
            float o1 = oacc[vn][2 * rr + 1] * inv;
            int col = vn * 8 + 2 * tig;
            *(uint32_t*)&thi[rb + col] = pk2(o0, o1);
        }
    }
}

// ---------------------------------------------------------------------------
// Residual add + LayerNorm + fp16 hi out
// ---------------------------------------------------------------------------
__global__ __launch_bounds__(256) void add_ln_kernel(float* __restrict__ x,
                                                     const float* __restrict__ y,
                                                     const float* __restrict__ g,
                                                     const float* __restrict__ bb,
                                                     f16* __restrict__ xhi) {
    const int row = blockIdx.x;
    const int tid = threadIdx.x;
    float2 xv = *(const float2*)&x[(size_t)row * DD + tid * 2];
    float2 yv = *(const float2*)&y[(size_t)row * DD + tid * 2];
    float a0 = xv.x + yv.x;
    float a1 = xv.y + yv.y;

    float s = a0 + a1;
    float ss = a0 * a0 + a1 * a1;
#pragma unroll
    for (int off = 16; off >= 1; off >>= 1) {
        s += __shfl_xor_sync(0xffffffffu, s, off);
        ss += __shfl_xor_sync(0xffffffffu, ss, off);
    }
    __shared__ float sbuf[8], ssbuf[8];
    if ((tid & 31) == 0) { sbuf[tid >> 5] = s; ssbuf[tid >> 5] = ss; }
    __syncthreads();
    float ts = 0.f, tss = 0.f;
#pragma unroll
    for (int i = 0; i < 8; i++) { ts += sbuf[i]; tss += ssbuf[i]; }
    float mean = ts * (1.f / DD);
    float var = tss * (1.f / DD) - mean * mean;
    float rstd = rsqrtf(var + 1e-5f);

    int col = tid * 2;
    float2 go = *(const float2*)&g[col];
    float2 bo = *(const float2*)&bb[col];
    float o0 = (a0 - mean) * rstd * go.x + bo.x;
    float o1 = (a1 - mean) * rstd * go.y + bo.y;
    *(float2*)&x[(size_t)row * DD + col] = make_float2(o0, o1);
    *(uint32_t*)&xhi[(size_t)row * DD + col] = pk2(o0, o1);
}

// ---------------------------------------------------------------------------
// Host driver
// ---------------------------------------------------------------------------
extern "C" void kernel_launch(void* const* d_in, const int* in_sizes, int n_in,
                              void* d_out, int out_size) {
    const int* source = (const int*)d_in[0];
    const float* emb = (const float*)d_in[1];
    const float* ln_g = (const float*)d_in[2];
    const float* ln_b = (const float*)d_in[3];
    const float* wq = (const float*)d_in[4];
    const float* bq = (const float*)d_in[5];
    const float* wk = (const float*)d_in[6];
    const float* bk = (const float*)d_in[7];
    const float* wv = (const float*)d_in[8];
    const float* bv = (const float*)d_in[9];
    const float* wo = (const float*)d_in[10];
    const float* bo = (const float*)d_in[11];
    const float* w1 = (const float*)d_in[12];
    const float* b1 = (const float*)d_in[13];
    const float* w2 = (const float*)d_in[14];
    const float* b2 = (const float*)d_in[15];

    float* x = (float*)d_out;

    float *tmp, *bqkv;
    f16 *xhi, *qkvhi, *qkvlo, *thi, *hhi;
    f16 *wqkvhi, *wohi, *w1hi, *w2hi;
    cudaGetSymbolAddress((void**)&tmp, g_tmp);
    cudaGetSymbolAddress((void**)&bqkv, g_bqkv);
    cudaGetSymbolAddress((void**)&xhi, g_xhi);
    cudaGetSymbolAddress((void**)&qkvhi, g_qkvhi);
    cudaGetSymbolAddress((void**)&qkvlo, g_qkvlo);
    cudaGetSymbolAddress((void**)&thi, g_thi);
    cudaGetSymbolAddress((void**)&hhi, g_hhi);
    cudaGetSymbolAddress((void**)&wqkvhi, g_wqkvhi);
    cudaGetSymbolAddress((void**)&wohi, g_wohi);
    cudaGetSymbolAddress((void**)&w1hi, g_w1hi);
    cudaGetSymbolAddress((void**)&w2hi, g_w2hi);

    cudaFuncSetAttribute(attn_tc_kernel, cudaFuncAttributeMaxDynamicSharedMemorySize,
                         ATT_SMEM);
    cudaFuncSetAttribute(gemm_wm_kernel, cudaFuncAttributeMaxDynamicSharedMemorySize,
                         GSMEM);

    embed_kernel<<<NROWS, 128>>>(source, emb, x, xhi);
    {
        dim3 gD(DD / 32, DD / 32, LL);
        transpose_cvt_kernel<<<gD, 256>>>(wq, wqkvhi, DD, DD,
                                          (size_t)DD * DD, (size_t)TD * DD);
        transpose_cvt_kernel<<<gD, 256>>>(wk, wqkvhi + (size_t)DD * DD, DD, DD,
                                          (size_t)DD * DD, (size_t)TD * DD);
        transpose_cvt_kernel<<<gD, 256>>>(wv, wqkvhi + (size_t)2 * DD * DD, DD, DD,
                                          (size_t)DD * DD, (size_t)TD * DD);
        transpose_cvt_kernel<<<gD, 256>>>(wo, wohi, DD, DD,
                                          (size_t)DD * DD, (size_t)DD * DD);
        dim3 g1(FF / 32, DD / 32, LL);
        transpose_cvt_kernel<<<g1, 256>>>(w1, w1hi, DD, FF,
                                          (size_t)DD * FF, (size_t)FF * DD);
        dim3 g2(DD / 32, FF / 32, LL);
        transpose_cvt_kernel<<<g2, 256>>>(w2, w2hi, FF, DD,
                                          (size_t)FF * DD, (size_t)DD * FF);
        pack_bias_kernel<<<(LL * TD + 255) / 256, 256>>>(bq, bk, bv, bqkv);
    }

    dim3 gA(BB * HH, SS / 128);

    auto gemm = [&](const f16* ah, const f16* bhw,
                    const float* bias, float* C, f16* Ch, f16* Cl,
                    int M, int N, int K, int relu, int mode) {
        dim3 g(N / 128, M / 128);
        gemm_wm_kernel<<<g, 256, GSMEM>>>(ah, bhw, bias, C, Ch, Cl,
                                          M, N, K, relu, mode);
    };

    for (int l = 0; l < LL; l++) {
        const f16* Wqkvh = wqkvhi + (size_t)l * TD * DD;
        const f16* Woh = wohi + (size_t)l * DD * DD;
        const f16* W1h = w1hi + (size_t)l * FF * DD;
        const f16* W2h = w2hi + (size_t)l * DD * FF;
        const float* Bqkv = bqkv + (size_t)l * TD;
        const float* Bo = bo + (size_t)l * DD;
        const float* B1 = b1 + (size_t)l * FF;
        const float* B2 = b2 + (size_t)l * DD;

        // QKV: split epilogue (attention Q uses hi+lo)
        gemm(xhi, Wqkvh, Bqkv, nullptr, qkvhi, qkvlo, NROWS, TD, DD, 0, 1);

        attn_tc_kernel<<<gA, 256, ATT_SMEM>>>(qkvhi, qkvlo, thi);

        gemm(thi, Woh, Bo, tmp, nullptr, nullptr, NROWS, DD, DD, 0, 0);
        add_ln_kernel<<<NROWS, 256>>>(x, tmp, ln_g, ln_b, xhi);

        gemm(xhi, W1h, B1, nullptr, hhi, nullptr, NROWS, FF, DD, 1, 2);
        gemm(hhi, W2h, B2, tmp, nullptr, nullptr, NROWS, DD, FF, 1, 0);
        add_ln_kernel<<<NROWS, 256>>>(x, tmp, ln_g, ln_b, xhi);
    }
}

// round 15
// speedup vs baseline: 2.3124x; 1.1401x over previous
#include <cuda_runtime.h>
#include <cuda_fp16.h>
#include <math.h>
#include <stdint.h>

#define BB 4
#define SS 2048
#define DD 512
#define HH 8
#define DHH 64
#define FF 2048
#define LL 6
#define NROWS (BB*SS)   // 8192
#define TD (3*DD)       // 1536 packed qkv width

typedef __half f16;

// ---------------------------------------------------------------------------
// Scratch
// ---------------------------------------------------------------------------
__device__ float g_tmp[NROWS * DD];
__device__ f16 g_xhi[NROWS * DD];
__device__ f16 g_qkvhi[NROWS * TD];
__device__ f16 g_thi[NROWS * DD];
__device__ f16 g_hhi[NROWS * FF];
__device__ f16 g_wqkvhi[LL * TD * DD];
__device__ f16 g_wohi[LL * DD * DD];
__device__ f16 g_w1hi[LL * FF * DD];
__device__ f16 g_w2hi[LL * DD * FF];
__device__ float g_bqkv[LL * TD];

// ---------------------------------------------------------------------------
// helpers
// ---------------------------------------------------------------------------
__device__ __forceinline__ uint32_t smem_u32(const void* p) {
    uint32_t a;
    asm("{ .reg .u64 t; cvta.to.shared.u64 t, %1; cvt.u32.u64 %0, t; }"
        : "=r"(a) : "l"(p));
    return a;
}

__device__ __forceinline__ void mma16816(float* c, const uint32_t* a, const uint32_t* b) {
    asm volatile(
        "mma.sync.aligned.m16n8k16.row.col.f32.f16.f16.f32 "
        "{%0,%1,%2,%3}, {%4,%5,%6,%7}, {%8,%9}, {%0,%1,%2,%3};"
        : "+f"(c[0]), "+f"(c[1]), "+f"(c[2]), "+f"(c[3])
        : "r"(a[0]), "r"(a[1]), "r"(a[2]), "r"(a[3]), "r"(b[0]), "r"(b[1]));
}

__device__ __forceinline__ void ldm_x4t(uint32_t* r, uint32_t addr) {
    asm volatile("ldmatrix.sync.aligned.m8n8.x4.trans.shared.b16 {%0,%1,%2,%3}, [%4];"
                 : "=r"(r[0]), "=r"(r[1]), "=r"(r[2]), "=r"(r[3]) : "r"(addr));
}

__device__ __forceinline__ void cpa16(uint32_t dst, const void* src) {
    asm volatile("cp.async.cg.shared.global [%0], [%1], 16;" :: "r"(dst), "l"(src));
}

__device__ __forceinline__ uint32_t pk2(float x0, float x1) {
    __half2 t = __floats2half2_rn(x0, x1);
    return *(uint32_t*)&t;
}
__device__ __forceinline__ float hf(float v) {
    return __half2float(__float2half_rn(v));
}

// ---------------------------------------------------------------------------
// Embedding gather + fp16 hi
// ---------------------------------------------------------------------------
__global__ __launch_bounds__(128) void embed_kernel(const int* __restrict__ src,
                                                    const float* __restrict__ emb,
                                                    float* __restrict__ x,
                                                    f16* __restrict__ xhi) {
    int row = blockIdx.x;
    int tok = src[row];
    float4 v = ((const float4*)(emb + (size_t)tok * DD))[threadIdx.x];
    ((float4*)(x + (size_t)row * DD))[threadIdx.x] = v;
    uint32_t* H = (uint32_t*)(xhi + (size_t)row * DD);
    H[2 * threadIdx.x]     = pk2(v.x, v.y);
    H[2 * threadIdx.x + 1] = pk2(v.z, v.w);
}

// ---------------------------------------------------------------------------
// Batched transpose + fp16 convert (hi only)
// ---------------------------------------------------------------------------
__global__ __launch_bounds__(256) void transpose_cvt_kernel(
    const float* __restrict__ W, f16* __restrict__ WThi,
    int K, int N, size_t src_ls, size_t dst_ls) {
    __shared__ float t[32][33];
    const float* Wl = W + (size_t)blockIdx.z * src_ls;
    f16* Hl = WThi + (size_t)blockIdx.z * dst_ls;
    int n0 = blockIdx.x * 32, k0 = blockIdx.y * 32;
    int c = threadIdx.x & 31, r = threadIdx.x >> 5;
#pragma unroll
    for (int i = 0; i < 4; i++)
        t[r + i * 8][c] = Wl[(size_t)(k0 + r + i * 8) * N + n0 + c];
    __syncthreads();
#pragma unroll
    for (int i = 0; i < 4; i++) {
        float x = t[c][r + i * 8];
        Hl[(size_t)(n0 + r + i * 8) * K + k0 + c] = __float2half_rn(x);
    }
}

__global__ __launch_bounds__(256) void pack_bias_kernel(const float* __restrict__ bq,
                                                        const float* __restrict__ bk,
                                                        const float* __restrict__ bv,
                                                        float* __restrict__ dst) {
    int i = blockIdx.x * 256 + threadIdx.x;
    if (i >= LL * TD) return;
    int l = i / TD, r = i % TD;
    int sel = r / DD, c = r % DD;
    const float* s = sel == 0 ? bq : (sel == 1 ? bk : bv);
    dst[i] = s[l * DD + c];
}

// ---------------------------------------------------------------------------
// Warp-MMA fp16 GEMM: D = A_hi * B_hi (1 MMA). R14-proven.
// mode 0: fp32 C; mode 2: Chi only.
// ---------------------------------------------------------------------------
#define GP_B   80
#define GTILE_B (128 * GP_B)
#define GSTAGE_B (2 * GTILE_B)
#define GSMEM   (2 * GSTAGE_B)    // 40960

__global__ __launch_bounds__(256, 2) void gemm_wm_kernel(
    const f16* __restrict__ Ahi, const f16* __restrict__ Bhi,
    const float* __restrict__ bias, float* __restrict__ C,
    f16* __restrict__ Chi,
    int M, int N, int K, int relu, int mode) {
    extern __shared__ char sm[];
    const uint32_t sbase = smem_u32(sm);

    const int tid = threadIdx.x;
    const int lane = tid & 31;
    const int wid = tid >> 5;
    const int warp_m = wid >> 2;
    const int warp_n = wid & 3;
    const int g = lane >> 2;
    const int tig = lane & 3;

    const int bm = blockIdx.y * 128;
    const int bn = blockIdx.x * 128;

    const f16* srcs[2] = { Ahi + (size_t)bm * K, Bhi + (size_t)bn * K };

    float acc[4][4][4];
#pragma unroll
    for (int mt = 0; mt < 4; mt++)
#pragma unroll
        for (int nt = 0; nt < 4; nt++)
#pragma unroll
            for (int e = 0; e < 4; e++) acc[mt][nt][e] = 0.f;

    const int NIT = K >> 5;

    auto load_stage = [&](int s, int it) {
        const uint32_t stage = sbase + (uint32_t)s * GSTAGE_B;
#pragma unroll
        for (int t = 0; t < 2; t++) {
#pragma unroll
            for (int i = 0; i < 2; i++) {
                int idx = i * 256 + tid;
                int r = idx >> 2;
                int c8 = idx & 3;
                const void* src = (const char*)(srcs[t] + (size_t)r * K + it * 32) + c8 * 16;
                uint32_t dst = stage + (uint32_t)t * GTILE_B + (uint32_t)r * GP_B + c8 * 16;
                cpa16(dst, src);
            }
        }
        asm volatile("cp.async.commit_group;" ::: "memory");
    };

    load_stage(0, 0);

    for (int it = 0; it < NIT; it++) {
        const int buf = it & 1;
        if (it + 1 < NIT) {
            load_stage(buf ^ 1, it + 1);
            asm volatile("cp.async.wait_group 1;" ::: "memory");
        } else {
            asm volatile("cp.async.wait_group 0;" ::: "memory");
        }
        __syncthreads();

        const char* A0 = sm + buf * GSTAGE_B;
        const char* B0 = A0 + GTILE_B;

#pragma unroll
        for (int ks = 0; ks < 2; ks++) {
            const int kb = ks * 32 + tig * 4;
            uint32_t bh[4][2];
#pragma unroll
            for (int nt = 0; nt < 4; nt++) {
                int off = (warp_n * 32 + nt * 8 + g) * GP_B + kb;
                bh[nt][0] = *(const uint32_t*)(B0 + off);
                bh[nt][1] = *(const uint32_t*)(B0 + off + 16);
            }
#pragma unroll
            for (int mt = 0; mt < 4; mt++) {
                uint32_t ah[4];
                int off = (warp_m * 64 + mt * 16 + g) * GP_B + kb;
                ah[0] = *(const uint32_t*)(A0 + off);
                ah[1] = *(const uint32_t*)(A0 + off + 8 * GP_B);
                ah[2] = *(const uint32_t*)(A0 + off + 16);
                ah[3] = *(const uint32_t*)(A0 + off + 8 * GP_B + 16);
#pragma unroll
                for (int nt = 0; nt < 4; nt++)
                    mma16816(acc[mt][nt], ah, bh[nt]);
            }
        }
        __syncthreads();
    }

#pragma unroll
    for (int mt = 0; mt < 4; mt++) {
        int row0 = bm + warp_m * 64 + mt * 16 + g;
#pragma unroll
        for (int nt = 0; nt < 4; nt++) {
            int col = bn + warp_n * 32 + nt * 8 + 2 * tig;
            float bx = bias[col], by = bias[col + 1];
            float v00 = acc[mt][nt][0] + bx, v01 = acc[mt][nt][1] + by;
            float v10 = acc[mt][nt][2] + bx, v11 = acc[mt][nt][3] + by;
            if (relu) {
                v00 = fmaxf(v00, 0.f); v01 = fmaxf(v01, 0.f);
                v10 = fmaxf(v10, 0.f); v11 = fmaxf(v11, 0.f);
            }
            if (mode == 0) {
                *(float2*)&C[(size_t)row0 * N + col] = make_float2(v00, v01);
                *(float2*)&C[(size_t)(row0 + 8) * N + col] = make_float2(v10, v11);
            } else {
                *(uint32_t*)&Chi[(size_t)row0 * N + col] = pk2(v00, v01);
                *(uint32_t*)&Chi[(size_t)(row0 + 8) * N + col] = pk2(v10, v11);
            }
        }
    }
}

// ---------------------------------------------------------------------------
// Tensor-core flash attention — 1-term fp16: S = Q_hi·K_hi, O = P_hi·V_hi.
// smem 36,864 B. Grid (bh, qtile), qb reversed (global longest-first).
// ---------------------------------------------------------------------------
#define AP 72
#define ATT_SMEM ((128 + 2*64) * AP * 2)   // 36864 bytes

__global__ __launch_bounds__(256, 2) void attn_tc_kernel(
    const f16* __restrict__ qkvhi, f16* __restrict__ thi) {
    extern __shared__ f16 asmem[];
    const uint32_t sb = smem_u32(asmem);
    f16* Qh = asmem;
    f16* Kh = Qh + 128 * AP;
    f16* Vh = Kh + 64 * AP;
    const uint32_t vhb = sb + (uint32_t)(192 * AP) * 2;

    const int tid = threadIdx.x;
    const int lane = tid & 31;
    const int wid = tid >> 5;
    const int g = lane >> 2;
    const int tig = lane & 3;

    const int qb = gridDim.y - 1 - blockIdx.y;
    const int bh = blockIdx.x;
    const int b = bh / HH;
    const int h = bh % HH;
    const int q0 = qb * 128;
    const size_t hoff = (size_t)h * DHH;

#pragma unroll
    for (int i = 0; i < 4; i++) {
        int idx = i * 256 + tid;
        int row = idx >> 3;
        int cb = (idx & 7) * 8;
        size_t go = (size_t)(b * SS + q0 + row) * TD + hoff + cb;
        *(uint4*)&Qh[row * AP + cb] = *(const uint4*)&qkvhi[go];
    }

    float oacc[8][4];
#pragma unroll
    for (int vn = 0; vn < 8; vn++)
#pragma unroll
        for (int e = 0; e < 4; e++) oacc[vn][e] = 0.f;
    float mrow[2] = {-1e30f, -1e30f};
    float lrow[2] = {0.f, 0.f};

    const int nkt = 2 * qb + 2;
    const int wr0 = q0 + wid * 16;
    const float scale = 0.125f;

    const int l7 = lane & 7;
    const int grp = lane >> 3;
    const uint32_t vrow_off = (uint32_t)((l7 + (grp & 1) * 8) * AP) * 2;
    const uint32_t vcol_off = (uint32_t)((grp >> 1) * 8) * 2;

    for (int kt = 0; kt < nkt; kt++) {
        const int k0 = kt * 64;
        __syncthreads();
#pragma unroll
        for (int i = 0; i < 2; i++) {
            int idx = i * 256 + tid;
            int row = idx >> 3;
            int cb = (idx & 7) * 8;
            size_t go = (size_t)(b * SS + k0 + row) * TD + hoff + cb;
            *(uint4*)&Kh[row * AP + cb] = *(const uint4*)&qkvhi[go + DD];
            *(uint4*)&Vh[row * AP + cb] = *(const uint4*)&qkvhi[go + 2 * DD];
        }
        __syncthreads();

        if (k0 <= wr0 + 15) {
            float sacc[8][4];
#pragma unroll
            for (int nt = 0; nt < 8; nt++)
#pragma unroll
                for (int e = 0; e < 4; e++) sacc[nt][e] = 0.f;

#pragma unroll
            for (int kc = 0; kc < 4; kc++) {
                uint32_t ah[4];
                int aoff = (wid * 16 + g) * AP + kc * 16 + 2 * tig;
                ah[0] = *(const uint32_t*)&Qh[aoff];
                ah[1] = *(const uint32_t*)&Qh[aoff + 8 * AP];
                ah[2] = *(const uint32_t*)&Qh[aoff + 8];
                ah[3] = *(const uint32_t*)&Qh[aoff + 8 * AP + 8];
#pragma unroll
                for (int nt = 0; nt < 8; nt++) {
                    int boff = (nt * 8 + g) * AP + kc * 16 + 2 * tig;
                    uint32_t bh2[2];
                    bh2[0] = *(const uint32_t*)&Kh[boff];
                    bh2[1] = *(const uint32_t*)&Kh[boff + 8];
                    mma16816(sacc[nt], ah, bh2);
                }
            }

            const bool needmask = (k0 + 63) > wr0;
#pragma unroll
            for (int nt = 0; nt < 8; nt++)
#pragma unroll
                for (int e = 0; e < 4; e++) {
                    float sv = sacc[nt][e] * scale;
                    if (needmask) {
                        int row = wr0 + g + ((e >> 1) << 3);
                        int col = k0 + nt * 8 + 2 * tig + (e & 1);
                        if (col > row) sv = -1e30f;
                    }
                    sacc[nt][e] = sv;
                }

#pragma unroll
            for (int rr = 0; rr < 2; rr++) {
                float mx = -1e30f;
#pragma unroll
                for (int nt = 0; nt < 8; nt++)
                    mx = fmaxf(mx, fmaxf(sacc[nt][2 * rr], sacc[nt][2 * rr + 1]));
                mx = fmaxf(mx, __shfl_xor_sync(0xffffffffu, mx, 1));
                mx = fmaxf(mx, __shfl_xor_sync(0xffffffffu, mx, 2));
                float mnew = fmaxf(mrow[rr], mx);
                float alpha = __expf(mrow[rr] - mnew);
                float rs = 0.f;
#pragma unroll
                for (int nt = 0; nt < 8; nt++) {
                    float p0 = __expf(sacc[nt][2 * rr] - mnew);
                    float p1 = __expf(sacc[nt][2 * rr + 1] - mnew);
                    sacc[nt][2 * rr] = p0;
                    sacc[nt][2 * rr + 1] = p1;
                    rs += p0 + p1;
                }
                rs += __shfl_xor_sync(0xffffffffu, rs, 1);
                rs += __shfl_xor_sync(0xffffffffu, rs, 2);
                lrow[rr] = lrow[rr] * alpha + rs;
                mrow[rr] = mnew;
#pragma unroll
                for (int vn = 0; vn < 8; vn++) {
                    oacc[vn][2 * rr] *= alpha;
                    oacc[vn][2 * rr + 1] *= alpha;
                }
            }

#pragma unroll
            for (int kc2 = 0; kc2 < 4; kc2++) {
                float* t0 = sacc[2 * kc2];
                float* t1 = sacc[2 * kc2 + 1];
                uint32_t ph[4];
                ph[0] = pk2(t0[0], t0[1]); ph[1] = pk2(t0[2], t0[3]);
                ph[2] = pk2(t1[0], t1[1]); ph[3] = pk2(t1[2], t1[3]);

                const uint32_t kbase = (uint32_t)(kc2 * 16 * AP) * 2 + vrow_off + vcol_off;
#pragma unroll
                for (int vnp = 0; vnp < 4; vnp++) {
                    uint32_t vaddr = kbase + (uint32_t)(vnp * 16) * 2;
                    uint32_t vh4[4];
                    ldm_x4t(vh4, vhb + vaddr);
                    uint32_t bh0[2] = {vh4[0], vh4[1]}, bh1[2] = {vh4[2], vh4[3]};
                    mma16816(oacc[2 * vnp], ph, bh0);
                    mma16816(oacc[2 * vnp + 1], ph, bh1);
                }
            }
        }
    }

#pragma unroll
    for (int rr = 0; rr < 2; rr++) {
        float inv = 1.f / lrow[rr];
        int r = wr0 + g + rr * 8;
        size_t rb = (size_t)(b * SS + r) * DD + hoff;
#pragma unroll
        for (int vn = 0; vn < 8; vn++) {
            float o0 = oacc[vn][2 * rr] * inv;
            float o1 = oacc[vn][2 * rr + 1] * inv;
            int col = vn * 8 + 2 * tig;
            *(uint32_t*)&thi[rb + col] = pk2(o0, o1);
        }
    }
}

// ---------------------------------------------------------------------------
// Residual add + LayerNorm + fp16 hi out
// ---------------------------------------------------------------------------
__global__ __launch_bounds__(256) void add_ln_kernel(float* __restrict__ x,
                                                     const float* __restrict__ y,
                                                     const float* __restrict__ g,
                                                     const float* __restrict__ bb,
                                                     f16* __restrict__ xhi) {
    const int row = blockIdx.x;
    const int tid = threadIdx.x;
    float2 xv = *(const float2*)&x[(size_t)row * DD + tid * 2];
    float2 yv = *(const float2*)&y[(size_t)row * DD + tid * 2];
    float a0 = xv.x + yv.x;
    float a1 = xv.y + yv.y;

    float s = a0 + a1;
    float ss = a0 * a0 + a1 * a1;
#pragma unroll
    for (int off = 16; off >= 1; off >>= 1) {
        s += __shfl_xor_sync(0xffffffffu, s, off);
        ss += __shfl_xor_sync(0xffffffffu, ss, off);
    }
    __shared__ float sbuf[8], ssbuf[8];
    if ((tid & 31) == 0) { sbuf[tid >> 5] = s; ssbuf[tid >> 5] = ss; }
    __syncthreads();
    float ts = 0.f, tss = 0.f;
#pragma unroll
    for (int i = 0; i < 8; i++) { ts += sbuf[i]; tss += ssbuf[i]; }
    float mean = ts * (1.f / DD);
    float var = tss * (1.f / DD) - mean * mean;
    float rstd = rsqrtf(var + 1e-5f);

    int col = tid * 2;
    float2 go = *(const float2*)&g[col];
    float2 bo = *(const float2*)&bb[col];
    float o0 = (a0 - mean) * rstd * go.x + bo.x;
    float o1 = (a1 - mean) * rstd * go.y + bo.y;
    *(float2*)&x[(size_t)row * DD + col] = make_float2(o0, o1);
    *(uint32_t*)&xhi[(size_t)row * DD + col] = pk2(o0, o1);
}

// ---------------------------------------------------------------------------
// Host driver
// ---------------------------------------------------------------------------
extern "C" void kernel_launch(void* const* d_in, const int* in_sizes, int n_in,
                              void* d_out, int out_size) {
    const int* source = (const int*)d_in[0];
    const float* emb = (const float*)d_in[1];
    const float* ln_g = (const float*)d_in[2];
    const float* ln_b = (const float*)d_in[3];
    const float* wq = (const float*)d_in[4];
    const float* bq = (const float*)d_in[5];
    const float* wk = (const float*)d_in[6];
    const float* bk = (const float*)d_in[7];
    const float* wv = (const float*)d_in[8];
    const float* bv = (const float*)d_in[9];
    const float* wo = (const float*)d_in[10];
    const float* bo = (const float*)d_in[11];
    const float* w1 = (const float*)d_in[12];
    const float* b1 = (const float*)d_in[13];
    const float* w2 = (const float*)d_in[14];
    const float* b2 = (const float*)d_in[15];

    float* x = (float*)d_out;

    float *tmp, *bqkv;
    f16 *xhi, *qkvhi, *thi, *hhi;
    f16 *wqkvhi, *wohi, *w1hi, *w2hi;
    cudaGetSymbolAddress((void**)&tmp, g_tmp);
    cudaGetSymbolAddress((void**)&bqkv, g_bqkv);
    cudaGetSymbolAddress((void**)&xhi, g_xhi);
    cudaGetSymbolAddress((void**)&qkvhi, g_qkvhi);
    cudaGetSymbolAddress((void**)&thi, g_thi);
    cudaGetSymbolAddress((void**)&hhi, g_hhi);
    cudaGetSymbolAddress((void**)&wqkvhi, g_wqkvhi);
    cudaGetSymbolAddress((void**)&wohi, g_wohi);
    cudaGetSymbolAddress((void**)&w1hi, g_w1hi);
    cudaGetSymbolAddress((void**)&w2hi, g_w2hi);

    cudaFuncSetAttribute(attn_tc_kernel, cudaFuncAttributeMaxDynamicSharedMemorySize,
                         ATT_SMEM);
    cudaFuncSetAttribute(gemm_wm_kernel, cudaFuncAttributeMaxDynamicSharedMemorySize,
                         GSMEM);

    embed_kernel<<<NROWS, 128>>>(source, emb, x, xhi);
    {
        dim3 gD(DD / 32, DD / 32, LL);
        transpose_cvt_kernel<<<gD, 256>>>(wq, wqkvhi, DD, DD,
                                          (size_t)DD * DD, (size_t)TD * DD);
        transpose_cvt_kernel<<<gD, 256>>>(wk, wqkvhi + (size_t)DD * DD, DD, DD,
                                          (size_t)DD * DD, (size_t)TD * DD);
        transpose_cvt_kernel<<<gD, 256>>>(wv, wqkvhi + (size_t)2 * DD * DD, DD, DD,
                                          (size_t)DD * DD, (size_t)TD * DD);
        transpose_cvt_kernel<<<gD, 256>>>(wo, wohi, DD, DD,
                                          (size_t)DD * DD, (size_t)DD * DD);
        dim3 g1(FF / 32, DD / 32, LL);
        transpose_cvt_kernel<<<g1, 256>>>(w1, w1hi, DD, FF,
                                          (size_t)DD * FF, (size_t)FF * DD);
        dim3 g2(DD / 32, FF / 32, LL);
        transpose_cvt_kernel<<<g2, 256>>>(w2, w2hi, FF, DD,
                                          (size_t)FF * DD, (size_t)DD * FF);
        pack_bias_kernel<<<(LL * TD + 255) / 256, 256>>>(bq, bk, bv, bqkv);
    }

    dim3 gA(BB * HH, SS / 128);

    auto gemm = [&](const f16* ah, const f16* bhw,
                    const float* bias, float* C, f16* Ch,
                    int M, int N, int K, int relu, int mode) {
        dim3 g(N / 128, M / 128);
        gemm_wm_kernel<<<g, 256, GSMEM>>>(ah, bhw, bias, C, Ch,
                                          M, N, K, relu, mode);
    };

    for (int l = 0; l < LL; l++) {
        const f16* Wqkvh = wqkvhi + (size_t)l * TD * DD;
        const f16* Woh = wohi + (size_t)l * DD * DD;
        const f16* W1h = w1hi + (size_t)l * FF * DD;
        const f16* W2h = w2hi + (size_t)l * DD * FF;
        const float* Bqkv = bqkv + (size_t)l * TD;
        const float* Bo = bo + (size_t)l * DD;
        const float* B1 = b1 + (size_t)l * FF;
        const float* B2 = b2 + (size_t)l * DD;

        gemm(xhi, Wqkvh, Bqkv, nullptr, qkvhi, NROWS, TD, DD, 0, 2);

        attn_tc_kernel<<<gA, 256, ATT_SMEM>>>(qkvhi, thi);

        gemm(thi, Woh, Bo, tmp, nullptr, NROWS, DD, DD, 0, 0);
        add_ln_kernel<<<NROWS, 256>>>(x, tmp, ln_g, ln_b, xhi);

        gemm(xhi, W1h, B1, nullptr, hhi, NROWS, FF, DD, 1, 2);
        gemm(hhi, W2h, B2, tmp, nullptr, NROWS, DD, FF, 1, 0);
        add_ln_kernel<<<NROWS, 256>>>(x, tmp, ln_g, ln_b, xhi);
    }
}